// round 1
// baseline (speedup 1.0000x reference)
#include <cuda_runtime.h>
#include <math.h>

#define B_  4
#define G_  1024
#define D_  512
#define H_  8
#define DH  64

// ---- scratch (device globals: allocation-free rule) ----
__device__ float g_Q[B_*H_*G_*DH];     // 8 MB  (B,H,G,dh)
__device__ float g_K[B_*H_*G_*DH];     // 8 MB
__device__ float g_V[B_*H_*G_*DH];     // 8 MB
__device__ float g_O[B_*G_*D_];        // 8 MB  (B,G,D) attention output
__device__ int   g_bkt[B_*G_*G_];      // 16.8 MB packed buckets + mask bit

// ================= bucket precompute =================
// bucket = clip(floor(log(n)/log2),0,31)*sign + 31 ; n = clip(|d|,1e-6,128)
// |d| >= 128 clamps to exactly 128: fp32 jax math gives exactly 7.0 -> li=7.
__device__ __forceinline__ int rpb(float d) {
    float ad = fabsf(d);
    int li;
    if (ad >= 128.0f) {
        li = 7;
    } else {
        float n = fmaxf(ad, 1e-6f);
        li = (int)floorf(__fdiv_rn(logf(n), 0.69314718055994530942f));
        li = max(0, min(li, 31));
    }
    return d > 0.0f ? 31 + li : (d < 0.0f ? 31 - li : 31);
}

__global__ void bucket_kernel(const float* __restrict__ coords,
                              const int*   __restrict__ mask) {
    int idx = blockIdx.x * blockDim.x + threadIdx.x;   // < 4M
    int k = idx & (G_-1);
    int q = (idx >> 10) & (G_-1);
    int b = idx >> 20;
    float2 cq = ((const float2*)coords)[b*G_ + q];
    float2 ck = ((const float2*)coords)[b*G_ + k];
    int v = rpb(cq.x - ck.x) | (rpb(cq.y - ck.y) << 8);
    if (mask[b*G_ + k] == 0) v |= (int)0x80000000;
    g_bkt[idx] = v;
}

// ================= GEMM: Y = X @ W^T + b (NT, fp32) =================
// M=4096, N=K=512 fixed. ymode: 0 -> plain row-major Yp; 1/2/3 -> scatter to
// g_Q/g_K/g_V in (B,H,G,dh) layout. xmode: 1 -> read X from g_O.
#define BM 64
#define BN 64
#define BKK 16
__global__ __launch_bounds__(256) void gemm_nt(
    const float* __restrict__ Xp, const float* __restrict__ W,
    const float* __restrict__ bias, float* __restrict__ Yp,
    int xmode, int ymode)
{
    const float* X = xmode ? (const float*)g_O : Xp;
    __shared__ __align__(16) float Xs[BKK][BM+4];
    __shared__ __align__(16) float Ws[BKK][BN+4];
    int tid  = threadIdx.x;
    int brow = blockIdx.y * BM;
    int bcol = blockIdx.x * BN;
    int tx = tid & 15, ty = tid >> 4;
    int lr = tid >> 2;            // 0..63
    int lc = (tid & 3) << 2;      // 0,4,8,12
    float acc[4][4] = {};
    const float* xg = X + (brow + lr) * D_ + lc;
    const float* wg = W + (bcol + lr) * D_ + lc;

    for (int k0 = 0; k0 < D_; k0 += BKK) {
        float4 xv = *(const float4*)(xg + k0);
        float4 wv = *(const float4*)(wg + k0);
        Xs[lc+0][lr]=xv.x; Xs[lc+1][lr]=xv.y; Xs[lc+2][lr]=xv.z; Xs[lc+3][lr]=xv.w;
        Ws[lc+0][lr]=wv.x; Ws[lc+1][lr]=wv.y; Ws[lc+2][lr]=wv.z; Ws[lc+3][lr]=wv.w;
        __syncthreads();
        #pragma unroll
        for (int kk = 0; kk < BKK; kk++) {
            float4 a  = *(const float4*)&Xs[kk][ty << 2];
            float4 w4 = *(const float4*)&Ws[kk][tx << 2];
            float av[4] = {a.x, a.y, a.z, a.w};
            float bv4[4] = {w4.x, w4.y, w4.z, w4.w};
            #pragma unroll
            for (int i = 0; i < 4; i++)
                #pragma unroll
                for (int j = 0; j < 4; j++)
                    acc[i][j] = fmaf(av[i], bv4[j], acc[i][j]);
        }
        __syncthreads();
    }

    #pragma unroll
    for (int i = 0; i < 4; i++) {
        int r = brow + (ty << 2) + i;
        #pragma unroll
        for (int j = 0; j < 4; j++) {
            int c = bcol + (tx << 2) + j;
            float v = acc[i][j] + bias[c];
            if (ymode == 0) {
                Yp[r * D_ + c] = v;
            } else {
                int bb = r >> 10, g = r & 1023;
                int hh = c >> 6,  dd = c & 63;
                int oi = (((bb * H_ + hh) << 10) + g) * DH + dd;
                float* dst = (ymode == 1) ? g_Q : (ymode == 2) ? g_K : g_V;
                dst[oi] = v;
            }
        }
    }
}

// ================= flash attention =================
// grid (G/64, B*H), 128 threads: 64 queries x 2 half-threads (32 dims each)
#define QT 64
#define KT 64
__global__ __launch_bounds__(128) void attn_kernel(
    const float* __restrict__ rpe_x, const float* __restrict__ rpe_y)
{
    __shared__ __align__(16) float Ks[KT][DH];
    __shared__ __align__(16) float Vs[KT][DH];
    __shared__ float rxs[63], rys[63];

    int bh = blockIdx.y;
    int b  = bh >> 3, h = bh & 7;
    int q0 = blockIdx.x * QT;
    int tid  = threadIdx.x;
    int q    = q0 + (tid >> 1);
    int half = tid & 1;

    if (tid < 63) { rxs[tid] = rpe_x[tid * H_ + h]; rys[tid] = rpe_y[tid * H_ + h]; }

    const float* qrow = &g_Q[((bh << 10) + q) * DH + (half << 5)];
    float4 qv[8];
    #pragma unroll
    for (int i = 0; i < 8; i++) qv[i] = ((const float4*)qrow)[i];

    float4 av[8] = {};
    float m = -3.4e38f, l = 0.0f;

    const float* kbase = &g_K[(size_t)(bh << 10) * DH];
    const float* vbase = &g_V[(size_t)(bh << 10) * DH];
    const int4*  brow4 = (const int4*)&g_bkt[(size_t)((b << 10) + q) << 10];

    for (int kt = 0; kt < G_; kt += KT) {
        __syncthreads();
        #pragma unroll
        for (int p = 0; p < 8; p++) {
            int e = tid + (p << 7);           // 0..1023 float4 slots
            int row = e >> 4, col = (e & 15) << 2;
            *(float4*)&Ks[row][col] = *(const float4*)&kbase[(kt + row) * DH + col];
            *(float4*)&Vs[row][col] = *(const float4*)&vbase[(kt + row) * DH + col];
        }
        __syncthreads();

        #pragma unroll 1
        for (int j4 = 0; j4 < KT; j4 += 4) {
            int4 pk4 = brow4[(kt + j4) >> 2];
            int pks[4] = {pk4.x, pk4.y, pk4.z, pk4.w};
            #pragma unroll
            for (int jj = 0; jj < 4; jj++) {
                int j  = j4 + jj;
                int pk = pks[jj];
                const float4* kr = (const float4*)&Ks[j][half << 5];
                float s0=0.f, s1=0.f, s2=0.f, s3=0.f;
                #pragma unroll
                for (int i = 0; i < 8; i++) {
                    float4 kv = kr[i];
                    s0 = fmaf(qv[i].x, kv.x, s0);
                    s1 = fmaf(qv[i].y, kv.y, s1);
                    s2 = fmaf(qv[i].z, kv.z, s2);
                    s3 = fmaf(qv[i].w, kv.w, s3);
                }
                float part = (s0 + s1) + (s2 + s3);
                part += __shfl_xor_sync(0xffffffffu, part, 1);

                float p;
                if (pk >= 0) {
                    float s = fmaf(part, 0.125f, rxs[pk & 63] + rys[(pk >> 8) & 63]);
                    if (s > m) {                    // rare (~ln(G) times/row)
                        float corr = __expf(m - s);
                        m = s;
                        l *= corr;
                        #pragma unroll
                        for (int i = 0; i < 8; i++) {
                            av[i].x *= corr; av[i].y *= corr;
                            av[i].z *= corr; av[i].w *= corr;
                        }
                    }
                    p = __expf(s - m);
                    l += p;
                } else {
                    p = 0.0f;                       // masked key
                }
                const float4* vr = (const float4*)&Vs[j][half << 5];
                #pragma unroll
                for (int i = 0; i < 8; i++) {
                    float4 vv = vr[i];
                    av[i].x = fmaf(p, vv.x, av[i].x);
                    av[i].y = fmaf(p, vv.y, av[i].y);
                    av[i].z = fmaf(p, vv.z, av[i].z);
                    av[i].w = fmaf(p, vv.w, av[i].w);
                }
            }
        }
    }

    float inv = 1.0f / l;
    float* orow = &g_O[((b << 10) + q) * D_ + h * DH + (half << 5)];
    #pragma unroll
    for (int i = 0; i < 8; i++) {
        float4 o;
        o.x = av[i].x * inv; o.y = av[i].y * inv;
        o.z = av[i].z * inv; o.w = av[i].w * inv;
        ((float4*)orow)[i] = o;
    }
}

// ================= launch =================
extern "C" void kernel_launch(void* const* d_in, const int* in_sizes, int n_in,
                              void* d_out, int out_size) {
    const float* query  = (const float*)d_in[0];
    const float* key    = (const float*)d_in[1];
    const float* value  = (const float*)d_in[2];
    const float* coords = (const float*)d_in[3];
    const int*   mask   = (const int*)  d_in[4];
    const float* Wq = (const float*)d_in[5];
    const float* bq = (const float*)d_in[6];
    const float* Wk = (const float*)d_in[7];
    const float* bk = (const float*)d_in[8];
    const float* Wv = (const float*)d_in[9];
    const float* bv = (const float*)d_in[10];
    const float* Wo = (const float*)d_in[11];
    const float* bo = (const float*)d_in[12];
    const float* rpe_x = (const float*)d_in[13];
    const float* rpe_y = (const float*)d_in[14];
    float* out = (float*)d_out;

    bucket_kernel<<<(B_*G_*G_) / 256, 256>>>(coords, mask);

    dim3 gg(D_ / BN, (B_ * G_) / BM);          // (8, 64)
    gemm_nt<<<gg, 256>>>(query, Wq, bq, nullptr, 0, 1);
    gemm_nt<<<gg, 256>>>(key,   Wk, bk, nullptr, 0, 2);
    gemm_nt<<<gg, 256>>>(value, Wv, bv, nullptr, 0, 3);

    attn_kernel<<<dim3(G_ / QT, B_ * H_), 128>>>(rpe_x, rpe_y);

    gemm_nt<<<gg, 256>>>(nullptr, Wo, bo, out, 1, 0);
}

// round 2
// speedup vs baseline: 1.5062x; 1.5062x over previous
#include <cuda_runtime.h>
#include <math.h>

#define B_  4
#define G_  1024
#define D_  512
#define H_  8
#define DH  64

// ---- scratch (device globals: allocation-free rule) ----
__device__ float g_Q[B_*H_*G_*DH];     // 8 MB  (B,H,G,dh)
__device__ float g_K[B_*H_*G_*DH];     // 8 MB
__device__ float g_V[B_*H_*G_*DH];     // 8 MB
__device__ float g_O[B_*G_*D_];        // 8 MB  (B,G,D) attention output
__device__ int   g_bkt[B_*G_*G_];      // 16.8 MB packed buckets + mask bit

// ================= bucket precompute =================
__device__ __forceinline__ int rpb(float d) {
    float ad = fabsf(d);
    int li;
    if (ad >= 128.0f) {
        li = 7;
    } else {
        float n = fmaxf(ad, 1e-6f);
        li = (int)floorf(__fdiv_rn(logf(n), 0.69314718055994530942f));
        li = max(0, min(li, 31));
    }
    return d > 0.0f ? 31 + li : (d < 0.0f ? 31 - li : 31);
}

__global__ void bucket_kernel(const float* __restrict__ coords,
                              const int*   __restrict__ mask) {
    int idx = blockIdx.x * blockDim.x + threadIdx.x;   // < 4M
    int k = idx & (G_-1);
    int q = (idx >> 10) & (G_-1);
    int b = idx >> 20;
    float2 cq = ((const float2*)coords)[b*G_ + q];
    float2 ck = ((const float2*)coords)[b*G_ + k];
    int v = rpb(cq.x - ck.x) | (rpb(cq.y - ck.y) << 8);
    if (mask[b*G_ + k] == 0) v |= (int)0x80000000;
    g_bkt[idx] = v;
}

// ================= GEMM core macro-ish pieces =================
#define BM 64
#define BN 64
#define BKK 16

// fused QKV projection: blockIdx.z selects (X, W, bias, destination)
__global__ __launch_bounds__(256) void qkv_gemm(
    const float* __restrict__ Xq, const float* __restrict__ Xk, const float* __restrict__ Xv,
    const float* __restrict__ Wq, const float* __restrict__ Wk, const float* __restrict__ Wv,
    const float* __restrict__ bq, const float* __restrict__ bk, const float* __restrict__ bv)
{
    int z = blockIdx.z;
    const float* X    = (z == 0) ? Xq : (z == 1) ? Xk : Xv;
    const float* W    = (z == 0) ? Wq : (z == 1) ? Wk : Wv;
    const float* bias = (z == 0) ? bq : (z == 1) ? bk : bv;
    float* dst        = (z == 0) ? g_Q : (z == 1) ? g_K : g_V;

    __shared__ __align__(16) float Xs[BKK][BM+4];
    __shared__ __align__(16) float Ws[BKK][BN+4];
    int tid  = threadIdx.x;
    int brow = blockIdx.y * BM;
    int bcol = blockIdx.x * BN;
    int tx = tid & 15, ty = tid >> 4;
    int lr = tid >> 2;
    int lc = (tid & 3) << 2;
    float acc[4][4] = {};
    const float* xg = X + (brow + lr) * D_ + lc;
    const float* wg = W + (bcol + lr) * D_ + lc;

    for (int k0 = 0; k0 < D_; k0 += BKK) {
        float4 xv = *(const float4*)(xg + k0);
        float4 wv = *(const float4*)(wg + k0);
        Xs[lc+0][lr]=xv.x; Xs[lc+1][lr]=xv.y; Xs[lc+2][lr]=xv.z; Xs[lc+3][lr]=xv.w;
        Ws[lc+0][lr]=wv.x; Ws[lc+1][lr]=wv.y; Ws[lc+2][lr]=wv.z; Ws[lc+3][lr]=wv.w;
        __syncthreads();
        #pragma unroll
        for (int kk = 0; kk < BKK; kk++) {
            float4 a  = *(const float4*)&Xs[kk][ty << 2];
            float4 w4 = *(const float4*)&Ws[kk][tx << 2];
            float av[4] = {a.x, a.y, a.z, a.w};
            float bv4[4] = {w4.x, w4.y, w4.z, w4.w};
            #pragma unroll
            for (int i = 0; i < 4; i++)
                #pragma unroll
                for (int j = 0; j < 4; j++)
                    acc[i][j] = fmaf(av[i], bv4[j], acc[i][j]);
        }
        __syncthreads();
    }

    #pragma unroll
    for (int i = 0; i < 4; i++) {
        int r = brow + (ty << 2) + i;
        #pragma unroll
        for (int j = 0; j < 4; j++) {
            int c = bcol + (tx << 2) + j;
            float v = acc[i][j] + bias[c];
            int bb = r >> 10, g = r & 1023;
            int hh = c >> 6,  dd = c & 63;
            dst[(((bb * H_ + hh) << 10) + g) * DH + dd] = v;
        }
    }
}

// output projection: out = g_O @ Wo^T + bo
__global__ __launch_bounds__(256) void out_gemm(
    const float* __restrict__ W, const float* __restrict__ bias,
    float* __restrict__ Yp)
{
    const float* X = (const float*)g_O;
    __shared__ __align__(16) float Xs[BKK][BM+4];
    __shared__ __align__(16) float Ws[BKK][BN+4];
    int tid  = threadIdx.x;
    int brow = blockIdx.y * BM;
    int bcol = blockIdx.x * BN;
    int tx = tid & 15, ty = tid >> 4;
    int lr = tid >> 2;
    int lc = (tid & 3) << 2;
    float acc[4][4] = {};
    const float* xg = X + (brow + lr) * D_ + lc;
    const float* wg = W + (bcol + lr) * D_ + lc;

    for (int k0 = 0; k0 < D_; k0 += BKK) {
        float4 xv = *(const float4*)(xg + k0);
        float4 wv = *(const float4*)(wg + k0);
        Xs[lc+0][lr]=xv.x; Xs[lc+1][lr]=xv.y; Xs[lc+2][lr]=xv.z; Xs[lc+3][lr]=xv.w;
        Ws[lc+0][lr]=wv.x; Ws[lc+1][lr]=wv.y; Ws[lc+2][lr]=wv.z; Ws[lc+3][lr]=wv.w;
        __syncthreads();
        #pragma unroll
        for (int kk = 0; kk < BKK; kk++) {
            float4 a  = *(const float4*)&Xs[kk][ty << 2];
            float4 w4 = *(const float4*)&Ws[kk][tx << 2];
            float av[4] = {a.x, a.y, a.z, a.w};
            float bv4[4] = {w4.x, w4.y, w4.z, w4.w};
            #pragma unroll
            for (int i = 0; i < 4; i++)
                #pragma unroll
                for (int j = 0; j < 4; j++)
                    acc[i][j] = fmaf(av[i], bv4[j], acc[i][j]);
        }
        __syncthreads();
    }

    #pragma unroll
    for (int i = 0; i < 4; i++) {
        int r = brow + (ty << 2) + i;
        #pragma unroll
        for (int j = 0; j < 4; j++) {
            int c = bcol + (tx << 2) + j;
            Yp[r * D_ + c] = acc[i][j] + bias[c];
        }
    }
}

// ================= flash attention (register-tiled FA2) =================
// grid (16, 32): 64q x 64k tiles, 256 threads, each owns 4x4 score + 4x4 out
#define KT 64
#define PITCH 68
#define ATTN_SMEM ((4*64*PITCH + 128) * 4)

__global__ __launch_bounds__(256, 3) void attn_kernel(
    const float* __restrict__ rpe_x, const float* __restrict__ rpe_y)
{
    extern __shared__ float sm[];
    float (*Qt)[PITCH] = (float(*)[PITCH])sm;                    // [d][q]
    float (*Kt)[PITCH] = (float(*)[PITCH])(sm + 64*PITCH);       // [d][k]
    float (*Vs)[PITCH] = (float(*)[PITCH])(sm + 2*64*PITCH);     // [k][d]
    float (*Ps)[PITCH] = (float(*)[PITCH])(sm + 3*64*PITCH);     // [q][k]
    float* rxs = sm + 4*64*PITCH;
    float* rys = rxs + 64;

    int bh = blockIdx.y;
    int b  = bh >> 3, h = bh & 7;
    int q0 = blockIdx.x * 64;
    int tid = threadIdx.x;
    int tx = tid & 15, ty = tid >> 4;        // thread owns q rows 4ty.., k/d cols 4tx..

    if (tid < 63) { rxs[tid] = rpe_x[tid * H_ + h]; rys[tid] = rpe_y[tid * H_ + h]; }

    // load Q tile transposed: Qt[d][q]
    const float* qbase = &g_Q[((size_t)(bh << 10) + q0) * DH];
    #pragma unroll
    for (int p = 0; p < 4; p++) {
        int s = tid + (p << 8);
        int row = s >> 4, c4 = (s & 15) << 2;
        float4 v = *(const float4*)&qbase[row * DH + c4];
        Qt[c4+0][row] = v.x; Qt[c4+1][row] = v.y;
        Qt[c4+2][row] = v.z; Qt[c4+3][row] = v.w;
    }

    float o[4][4] = {};
    float m[4] = {-1e30f, -1e30f, -1e30f, -1e30f};
    float l[4] = {};

    const float* kbase = &g_K[(size_t)(bh << 10) * DH];
    const float* vbase = &g_V[(size_t)(bh << 10) * DH];
    int brow0 = ((b << 10) + q0 + (ty << 2)) << 10;   // g_bkt row base for this thread's q rows

    for (int kt = 0; kt < G_; kt += KT) {
        __syncthreads();
        #pragma unroll
        for (int p = 0; p < 4; p++) {
            int s = tid + (p << 8);
            int row = s >> 4, c4 = (s & 15) << 2;
            float4 kv = *(const float4*)&kbase[(kt + row) * DH + c4];
            Kt[c4+0][row] = kv.x; Kt[c4+1][row] = kv.y;
            Kt[c4+2][row] = kv.z; Kt[c4+3][row] = kv.w;
            *(float4*)&Vs[row][c4] = *(const float4*)&vbase[(kt + row) * DH + c4];
        }
        __syncthreads();

        // ---- S = Q @ K^T (4x4 per thread) ----
        float S[4][4] = {};
        #pragma unroll 8
        for (int d = 0; d < DH; d++) {
            float4 a  = *(const float4*)&Qt[d][ty << 2];
            float4 bb = *(const float4*)&Kt[d][tx << 2];
            float av[4] = {a.x, a.y, a.z, a.w};
            float bv[4] = {bb.x, bb.y, bb.z, bb.w};
            #pragma unroll
            for (int i = 0; i < 4; i++)
                #pragma unroll
                for (int j = 0; j < 4; j++)
                    S[i][j] = fmaf(av[i], bv[j], S[i][j]);
        }

        // ---- bias + online softmax per q row ----
        #pragma unroll
        for (int i = 0; i < 4; i++) {
            int4 pk4 = *(const int4*)&g_bkt[brow0 + (i << 10) + kt + (tx << 2)];
            int pka[4] = {pk4.x, pk4.y, pk4.z, pk4.w};
            float sv[4];
            #pragma unroll
            for (int j = 0; j < 4; j++) {
                int pk = pka[j];
                sv[j] = (pk >= 0)
                    ? fmaf(S[i][j], 0.125f, rxs[pk & 63] + rys[(pk >> 8) & 63])
                    : -1e30f;
            }
            float rm = fmaxf(fmaxf(sv[0], sv[1]), fmaxf(sv[2], sv[3]));
            rm = fmaxf(rm, __shfl_xor_sync(0xffffffffu, rm, 1));
            rm = fmaxf(rm, __shfl_xor_sync(0xffffffffu, rm, 2));
            rm = fmaxf(rm, __shfl_xor_sync(0xffffffffu, rm, 4));
            rm = fmaxf(rm, __shfl_xor_sync(0xffffffffu, rm, 8));
            float mn = fmaxf(m[i], rm);
            float scale = __expf(m[i] - mn);
            m[i] = mn;
            float rs = 0.0f;
            #pragma unroll
            for (int j = 0; j < 4; j++) {
                float pv = __expf(sv[j] - mn);
                S[i][j] = pv;
                rs += pv;
            }
            l[i] = l[i] * scale + rs;
            #pragma unroll
            for (int j = 0; j < 4; j++) o[i][j] *= scale;
            *(float4*)&Ps[(ty << 2) + i][tx << 2] =
                make_float4(S[i][0], S[i][1], S[i][2], S[i][3]);
        }
        __syncwarp();

        // ---- O += P @ V (4x4 per thread) ----
        #pragma unroll 8
        for (int k = 0; k < KT; k++) {
            float4 v4 = *(const float4*)&Vs[k][tx << 2];
            float vv[4] = {v4.x, v4.y, v4.z, v4.w};
            float p0 = Ps[(ty << 2) + 0][k];
            float p1 = Ps[(ty << 2) + 1][k];
            float p2 = Ps[(ty << 2) + 2][k];
            float p3 = Ps[(ty << 2) + 3][k];
            #pragma unroll
            for (int j = 0; j < 4; j++) {
                o[0][j] = fmaf(p0, vv[j], o[0][j]);
                o[1][j] = fmaf(p1, vv[j], o[1][j]);
                o[2][j] = fmaf(p2, vv[j], o[2][j]);
                o[3][j] = fmaf(p3, vv[j], o[3][j]);
            }
        }
    }

    // ---- finalize: reduce l across the 16-lane row group, normalize, store ----
    #pragma unroll
    for (int i = 0; i < 4; i++) {
        float li = l[i];
        li += __shfl_xor_sync(0xffffffffu, li, 1);
        li += __shfl_xor_sync(0xffffffffu, li, 2);
        li += __shfl_xor_sync(0xffffffffu, li, 4);
        li += __shfl_xor_sync(0xffffffffu, li, 8);
        float inv = 1.0f / li;
        float4 ov = make_float4(o[i][0] * inv, o[i][1] * inv,
                                o[i][2] * inv, o[i][3] * inv);
        int q = q0 + (ty << 2) + i;
        *(float4*)&g_O[((b << 10) + q) * D_ + h * DH + (tx << 2)] = ov;
    }
}

// ================= launch =================
extern "C" void kernel_launch(void* const* d_in, const int* in_sizes, int n_in,
                              void* d_out, int out_size) {
    const float* query  = (const float*)d_in[0];
    const float* key    = (const float*)d_in[1];
    const float* value  = (const float*)d_in[2];
    const float* coords = (const float*)d_in[3];
    const int*   mask   = (const int*)  d_in[4];
    const float* Wq = (const float*)d_in[5];
    const float* bq = (const float*)d_in[6];
    const float* Wk = (const float*)d_in[7];
    const float* bk = (const float*)d_in[8];
    const float* Wv = (const float*)d_in[9];
    const float* bv = (const float*)d_in[10];
    const float* Wo = (const float*)d_in[11];
    const float* bo = (const float*)d_in[12];
    const float* rpe_x = (const float*)d_in[13];
    const float* rpe_y = (const float*)d_in[14];
    float* out = (float*)d_out;

    cudaFuncSetAttribute(attn_kernel,
                         cudaFuncAttributeMaxDynamicSharedMemorySize, ATTN_SMEM);

    bucket_kernel<<<(B_*G_*G_) / 256, 256>>>(coords, mask);

    dim3 gq(D_ / BN, (B_ * G_) / BM, 3);       // (8, 64, 3)
    qkv_gemm<<<gq, 256>>>(query, key, value, Wq, Wk, Wv, bq, bk, bv);

    attn_kernel<<<dim3(G_ / 64, B_ * H_), 256, ATTN_SMEM>>>(rpe_x, rpe_y);

    dim3 gg(D_ / BN, (B_ * G_) / BM);          // (8, 64)
    out_gemm<<<gg, 256>>>(Wo, bo, out);
}

// round 4
// speedup vs baseline: 1.9076x; 1.2665x over previous
#include <cuda_runtime.h>
#include <cuda_bf16.h>
#include <math.h>

#define B_  4
#define G_  1024
#define D_  512
#define H_  8
#define DH  64
#define MK  (4096*512)
#define WK  (512*512)

// ---- scratch (device globals: allocation-free rule) ----
__device__ float g_Q[B_*H_*G_*DH];
__device__ float g_K[B_*H_*G_*DH];
__device__ float g_V[B_*H_*G_*DH];
__device__ int   g_bkt[B_*G_*G_];
// bf16 hi/lo split operands: A slabs 0..2 = query/key/value, 3 = attn output
__device__ __align__(16) __nv_bfloat16 g_Ah[4*MK];
__device__ __align__(16) __nv_bfloat16 g_Al[4*MK];
__device__ __align__(16) __nv_bfloat16 g_Wh[4*WK];
__device__ __align__(16) __nv_bfloat16 g_Wl[4*WK];

__device__ __forceinline__ unsigned smem_u32(const void* p) {
    unsigned r;
    asm("{ .reg .u64 t; cvta.to.shared.u64 t, %1; cvt.u32.u64 %0, t; }"
        : "=r"(r) : "l"(p));
    return r;
}

// ================= bucket precompute =================
__device__ __forceinline__ int rpb(float d) {
    float ad = fabsf(d);
    int li;
    if (ad >= 128.0f) {
        li = 7;
    } else {
        float n = fmaxf(ad, 1e-6f);
        li = (int)floorf(__fdiv_rn(logf(n), 0.69314718055994530942f));
        li = max(0, min(li, 31));
    }
    return d > 0.0f ? 31 + li : (d < 0.0f ? 31 - li : 31);
}

__global__ void bucket_kernel(const float* __restrict__ coords,
                              const int*   __restrict__ mask) {
    int idx = blockIdx.x * blockDim.x + threadIdx.x;
    int k = idx & (G_-1);
    int q = (idx >> 10) & (G_-1);
    int b = idx >> 20;
    float2 cq = ((const float2*)coords)[b*G_ + q];
    float2 ck = ((const float2*)coords)[b*G_ + k];
    int v = rpb(cq.x - ck.x) | (rpb(cq.y - ck.y) << 8);
    if (mask[b*G_ + k] == 0) v |= (int)0x80000000;
    g_bkt[idx] = v;
}

// ================= fp32 -> bf16 hi/lo converts =================
__global__ void convert_x(const float* __restrict__ q,
                          const float* __restrict__ k,
                          const float* __restrict__ v) {
    int i = blockIdx.x * blockDim.x + threadIdx.x;
    int e = i << 2;
    int z = e / MK;
    int r = e - z * MK;
    const float* src = (z == 0) ? q : (z == 1) ? k : v;
    float4 x = *(const float4*)(src + r);
    float f[4] = {x.x, x.y, x.z, x.w};
    __nv_bfloat16 hi[4], lo[4];
    #pragma unroll
    for (int j = 0; j < 4; j++) {
        hi[j] = __float2bfloat16_rn(f[j]);
        lo[j] = __float2bfloat16_rn(f[j] - __bfloat162float(hi[j]));
    }
    *(uint2*)(g_Ah + e) = *(uint2*)hi;
    *(uint2*)(g_Al + e) = *(uint2*)lo;
}

__global__ void convert_w(const float* __restrict__ wq, const float* __restrict__ wk,
                          const float* __restrict__ wv, const float* __restrict__ wo) {
    int i = blockIdx.x * blockDim.x + threadIdx.x;
    int e = i << 2;
    int z = e >> 18;
    int r = e & (WK - 1);
    const float* src = (z == 0) ? wq : (z == 1) ? wk : (z == 2) ? wv : wo;
    float4 x = *(const float4*)(src + r);
    float f[4] = {x.x, x.y, x.z, x.w};
    __nv_bfloat16 hi[4], lo[4];
    #pragma unroll
    for (int j = 0; j < 4; j++) {
        hi[j] = __float2bfloat16_rn(f[j]);
        lo[j] = __float2bfloat16_rn(f[j] - __bfloat162float(hi[j]));
    }
    *(uint2*)(g_Wh + e) = *(uint2*)hi;
    *(uint2*)(g_Wl + e) = *(uint2*)lo;
}

// ================= HMMA split-bf16 GEMM =================
// Y = X @ W^T (+bias). Tile M=128,N=64. 8 warps, each 32x32 via m16n8k16.
// 24 chunks: pass0 Ah*Wh, pass1 Al*Wh, pass2 Ah*Wl (fp32 accum throughout).
__device__ __forceinline__ void ldsm4(unsigned addr, unsigned& r0, unsigned& r1,
                                      unsigned& r2, unsigned& r3) {
    asm volatile("ldmatrix.sync.aligned.m8n8.x4.shared.b16 {%0,%1,%2,%3}, [%4];"
                 : "=r"(r0), "=r"(r1), "=r"(r2), "=r"(r3) : "r"(addr));
}
__device__ __forceinline__ void mma16816(float* d, const unsigned* a,
                                         const unsigned* b) {
    asm volatile(
        "mma.sync.aligned.m16n8k16.row.col.f32.bf16.bf16.f32 "
        "{%0,%1,%2,%3}, {%4,%5,%6,%7}, {%8,%9}, {%0,%1,%2,%3};"
        : "+f"(d[0]), "+f"(d[1]), "+f"(d[2]), "+f"(d[3])
        : "r"(a[0]), "r"(a[1]), "r"(a[2]), "r"(a[3]), "r"(b[0]), "r"(b[1]));
}

__global__ __launch_bounds__(256) void mma_gemm(
    const float* __restrict__ bq, const float* __restrict__ bk,
    const float* __restrict__ bv, const float* __restrict__ bo,
    float* __restrict__ outp, int zbase)
{
    __shared__ __align__(1024) char sa[16384];   // A: 128 rows x 128B (SW128)
    __shared__ __align__(1024) char sb[8192];    // B: 64 rows x 128B

    int z = blockIdx.z + zbase;
    const __nv_bfloat16* Ah = g_Ah + (size_t)z * MK;
    const __nv_bfloat16* Al = g_Al + (size_t)z * MK;
    const __nv_bfloat16* Bh = g_Wh + (size_t)z * WK;
    const __nv_bfloat16* Bl = g_Wl + (size_t)z * WK;
    const float* bias = (z == 0) ? bq : (z == 1) ? bk : (z == 2) ? bv : bo;

    int tid = threadIdx.x, wid = tid >> 5, lane = tid & 31;
    int m0 = blockIdx.y * 128;
    int n0 = blockIdx.x * 64;
    int wm = wid >> 1, wn = wid & 1;      // warp tile (32m x 32n)

    unsigned sa_u = smem_u32(sa), sb_u = smem_u32(sb);

    // ldmatrix lane address components
    int sub = lane >> 3, r8 = lane & 7;
    int a_row = wm * 32 + ((sub & 1) << 3) + r8;    // + i*16
    int b_row = wn * 32 + ((sub & 1) << 3) + r8;    // + jj*16
    int colb  = (sub >> 1) << 4;                     // + ks*32

    // global-load indices (same as smem store pattern)
    int grow = tid >> 3, gcu = tid & 7;

    float acc[2][4][4] = {};
    uint4 pa[4], pb[2];

    // prefetch chunk 0
    {
        const __nv_bfloat16* As = Ah;
        const __nv_bfloat16* Bs = Bh;
        #pragma unroll
        for (int t = 0; t < 4; t++)
            pa[t] = *(const uint4*)(As + (size_t)(m0 + grow + t*32) * 512 + (gcu << 3));
        #pragma unroll
        for (int t = 0; t < 2; t++)
            pb[t] = *(const uint4*)(Bs + (size_t)(n0 + grow + t*32) * 512 + (gcu << 3));
    }

    for (int c = 0; c < 24; c++) {
        // store prefetched chunk to smem (swizzled)
        #pragma unroll
        for (int t = 0; t < 4; t++) {
            unsigned off = ((grow + t*32) << 7) + (gcu << 4);
            off ^= (off >> 3) & 0x70;
            *(uint4*)(sa + off) = pa[t];
        }
        #pragma unroll
        for (int t = 0; t < 2; t++) {
            unsigned off = ((grow + t*32) << 7) + (gcu << 4);
            off ^= (off >> 3) & 0x70;
            *(uint4*)(sb + off) = pb[t];
        }
        __syncthreads();

        // prefetch next chunk
        if (c < 23) {
            int cn = c + 1;
            int p  = cn >> 3;
            int k0 = (cn & 7) << 6;
            const __nv_bfloat16* As = (p == 1) ? Al : Ah;
            const __nv_bfloat16* Bs = (p == 2) ? Bl : Bh;
            #pragma unroll
            for (int t = 0; t < 4; t++)
                pa[t] = *(const uint4*)(As + (size_t)(m0 + grow + t*32) * 512 + k0 + (gcu << 3));
            #pragma unroll
            for (int t = 0; t < 2; t++)
                pb[t] = *(const uint4*)(Bs + (size_t)(n0 + grow + t*32) * 512 + k0 + (gcu << 3));
        }

        // HMMA over the 64-K chunk
        #pragma unroll
        for (int ks = 0; ks < 4; ks++) {
            unsigned a[2][4], bf[4][2];
            #pragma unroll
            for (int i = 0; i < 2; i++) {
                unsigned off = ((a_row + i*16) << 7) + colb + (ks << 5);
                off ^= (off >> 3) & 0x70;
                ldsm4(sa_u + off, a[i][0], a[i][1], a[i][2], a[i][3]);
            }
            #pragma unroll
            for (int jj = 0; jj < 2; jj++) {
                unsigned off = ((b_row + jj*16) << 7) + colb + (ks << 5);
                off ^= (off >> 3) & 0x70;
                unsigned r0, r1, r2, r3;
                ldsm4(sb_u + off, r0, r1, r2, r3);
                bf[jj*2+0][0] = r0; bf[jj*2+0][1] = r2;
                bf[jj*2+1][0] = r1; bf[jj*2+1][1] = r3;
            }
            #pragma unroll
            for (int i = 0; i < 2; i++)
                #pragma unroll
                for (int j = 0; j < 4; j++)
                    mma16816(acc[i][j], a[i], bf[j]);
        }
        __syncthreads();
    }

    // epilogue
    int rbase = m0 + wm * 32 + (lane >> 2);
    int cbase = n0 + wn * 32 + ((lane & 3) << 1);
    #pragma unroll
    for (int i = 0; i < 2; i++) {
        #pragma unroll
        for (int j = 0; j < 4; j++) {
            int c = cbase + j * 8;
            float bx = bias[c], by = bias[c+1];
            #pragma unroll
            for (int half = 0; half < 2; half++) {
                int r = rbase + i * 16 + half * 8;
                float vx = acc[i][j][half*2+0] + bx;
                float vy = acc[i][j][half*2+1] + by;
                if (z == 3) {
                    *(float2*)(outp + (size_t)r * 512 + c) = make_float2(vx, vy);
                } else {
                    float* dst = (z == 0) ? g_Q : (z == 1) ? g_K : g_V;
                    int bb = r >> 10, g = r & 1023;
                    int h = c >> 6, dd = c & 63;
                    *(float2*)(dst + (((bb << 3) + h) << 16) + (g << 6) + dd) =
                        make_float2(vx, vy);
                }
            }
        }
    }
}

// ================= flash attention (register-tiled FA2) =================
#define KT 64
#define PITCH 68
#define ATTN_SMEM ((4*64*PITCH + 128) * 4)

__global__ __launch_bounds__(256, 3) void attn_kernel(
    const float* __restrict__ rpe_x, const float* __restrict__ rpe_y)
{
    extern __shared__ float sm[];
    float (*Qt)[PITCH] = (float(*)[PITCH])sm;
    float (*Kt)[PITCH] = (float(*)[PITCH])(sm + 64*PITCH);
    float (*Vs)[PITCH] = (float(*)[PITCH])(sm + 2*64*PITCH);
    float (*Ps)[PITCH] = (float(*)[PITCH])(sm + 3*64*PITCH);
    float* rxs = sm + 4*64*PITCH;
    float* rys = rxs + 64;

    int bh = blockIdx.y;
    int b  = bh >> 3, h = bh & 7;
    int q0 = blockIdx.x * 64;
    int tid = threadIdx.x;
    int tx = tid & 15, ty = tid >> 4;

    if (tid < 63) { rxs[tid] = rpe_x[tid * H_ + h]; rys[tid] = rpe_y[tid * H_ + h]; }

    const float* qbase = &g_Q[((size_t)(bh << 10) + q0) * DH];
    #pragma unroll
    for (int p = 0; p < 4; p++) {
        int s = tid + (p << 8);
        int row = s >> 4, c4 = (s & 15) << 2;
        float4 v = *(const float4*)&qbase[row * DH + c4];
        Qt[c4+0][row] = v.x; Qt[c4+1][row] = v.y;
        Qt[c4+2][row] = v.z; Qt[c4+3][row] = v.w;
    }

    float o[4][4] = {};
    float m[4] = {-1e30f, -1e30f, -1e30f, -1e30f};
    float l[4] = {};

    const float* kbase = &g_K[(size_t)(bh << 10) * DH];
    const float* vbase = &g_V[(size_t)(bh << 10) * DH];
    int brow0 = ((b << 10) + q0 + (ty << 2)) << 10;

    for (int kt = 0; kt < G_; kt += KT) {
        __syncthreads();
        #pragma unroll
        for (int p = 0; p < 4; p++) {
            int s = tid + (p << 8);
            int row = s >> 4, c4 = (s & 15) << 2;
            float4 kv = *(const float4*)&kbase[(kt + row) * DH + c4];
            Kt[c4+0][row] = kv.x; Kt[c4+1][row] = kv.y;
            Kt[c4+2][row] = kv.z; Kt[c4+3][row] = kv.w;
            *(float4*)&Vs[row][c4] = *(const float4*)&vbase[(kt + row) * DH + c4];
        }
        __syncthreads();

        float S[4][4] = {};
        #pragma unroll 8
        for (int d = 0; d < DH; d++) {
            float4 a  = *(const float4*)&Qt[d][ty << 2];
            float4 bb2 = *(const float4*)&Kt[d][tx << 2];
            float av[4] = {a.x, a.y, a.z, a.w};
            float bv2[4] = {bb2.x, bb2.y, bb2.z, bb2.w};
            #pragma unroll
            for (int i = 0; i < 4; i++)
                #pragma unroll
                for (int j = 0; j < 4; j++)
                    S[i][j] = fmaf(av[i], bv2[j], S[i][j]);
        }

        #pragma unroll
        for (int i = 0; i < 4; i++) {
            int4 pk4 = *(const int4*)&g_bkt[brow0 + (i << 10) + kt + (tx << 2)];
            int pka[4] = {pk4.x, pk4.y, pk4.z, pk4.w};
            float sv[4];
            #pragma unroll
            for (int j = 0; j < 4; j++) {
                int pk = pka[j];
                sv[j] = (pk >= 0)
                    ? fmaf(S[i][j], 0.125f, rxs[pk & 63] + rys[(pk >> 8) & 63])
                    : -1e30f;
            }
            float rm = fmaxf(fmaxf(sv[0], sv[1]), fmaxf(sv[2], sv[3]));
            rm = fmaxf(rm, __shfl_xor_sync(0xffffffffu, rm, 1));
            rm = fmaxf(rm, __shfl_xor_sync(0xffffffffu, rm, 2));
            rm = fmaxf(rm, __shfl_xor_sync(0xffffffffu, rm, 4));
            rm = fmaxf(rm, __shfl_xor_sync(0xffffffffu, rm, 8));
            float mn = fmaxf(m[i], rm);
            float scale = __expf(m[i] - mn);
            m[i] = mn;
            float rs = 0.0f;
            #pragma unroll
            for (int j = 0; j < 4; j++) {
                float pv = __expf(sv[j] - mn);
                S[i][j] = pv;
                rs += pv;
            }
            l[i] = l[i] * scale + rs;
            #pragma unroll
            for (int j = 0; j < 4; j++) o[i][j] *= scale;
            *(float4*)&Ps[(ty << 2) + i][tx << 2] =
                make_float4(S[i][0], S[i][1], S[i][2], S[i][3]);
        }
        __syncwarp();

        #pragma unroll 8
        for (int k = 0; k < KT; k++) {
            float4 v4 = *(const float4*)&Vs[k][tx << 2];
            float vv[4] = {v4.x, v4.y, v4.z, v4.w};
            float p0 = Ps[(ty << 2) + 0][k];
            float p1 = Ps[(ty << 2) + 1][k];
            float p2 = Ps[(ty << 2) + 2][k];
            float p3 = Ps[(ty << 2) + 3][k];
            #pragma unroll
            for (int j = 0; j < 4; j++) {
                o[0][j] = fmaf(p0, vv[j], o[0][j]);
                o[1][j] = fmaf(p1, vv[j], o[1][j]);
                o[2][j] = fmaf(p2, vv[j], o[2][j]);
                o[3][j] = fmaf(p3, vv[j], o[3][j]);
            }
        }
    }

    // finalize: normalize + write bf16 hi/lo into A-slab 3 (out-proj input)
    #pragma unroll
    for (int i = 0; i < 4; i++) {
        float li = l[i];
        li += __shfl_xor_sync(0xffffffffu, li, 1);
        li += __shfl_xor_sync(0xffffffffu, li, 2);
        li += __shfl_xor_sync(0xffffffffu, li, 4);
        li += __shfl_xor_sync(0xffffffffu, li, 8);
        float inv = 1.0f / li;
        float f[4] = {o[i][0]*inv, o[i][1]*inv, o[i][2]*inv, o[i][3]*inv};
        __nv_bfloat16 hi[4], lo[4];
        #pragma unroll
        for (int j = 0; j < 4; j++) {
            hi[j] = __float2bfloat16_rn(f[j]);
            lo[j] = __float2bfloat16_rn(f[j] - __bfloat162float(hi[j]));
        }
        int q = q0 + (ty << 2) + i;
        size_t off = 3*(size_t)MK + ((size_t)((b << 10) + q)) * 512 + h * DH + (tx << 2);
        *(uint2*)(g_Ah + off) = *(uint2*)hi;
        *(uint2*)(g_Al + off) = *(uint2*)lo;
    }
}

// ================= launch =================
extern "C" void kernel_launch(void* const* d_in, const int* in_sizes, int n_in,
                              void* d_out, int out_size) {
    const float* query  = (const float*)d_in[0];
    const float* key    = (const float*)d_in[1];
    const float* value  = (const float*)d_in[2];
    const float* coords = (const float*)d_in[3];
    const int*   mask   = (const int*)  d_in[4];
    const float* Wq = (const float*)d_in[5];
    const float* bq = (const float*)d_in[6];
    const float* Wk = (const float*)d_in[7];
    const float* bk = (const float*)d_in[8];
    const float* Wv = (const float*)d_in[9];
    const float* bv = (const float*)d_in[10];
    const float* Wo = (const float*)d_in[11];
    const float* bo = (const float*)d_in[12];
    const float* rpe_x = (const float*)d_in[13];
    const float* rpe_y = (const float*)d_in[14];
    float* out = (float*)d_out;

    cudaFuncSetAttribute(attn_kernel,
                         cudaFuncAttributeMaxDynamicSharedMemorySize, ATTN_SMEM);

    convert_x<<<(3*MK/4)/256, 256>>>(query, key, value);
    convert_w<<<(4*WK/4)/256, 256>>>(Wq, Wk, Wv, Wo);
    bucket_kernel<<<(B_*G_*G_) / 256, 256>>>(coords, mask);

    mma_gemm<<<dim3(8, 32, 3), 256>>>(bq, bk, bv, bo, out, 0);

    attn_kernel<<<dim3(G_ / 64, B_ * H_), 256, ATTN_SMEM>>>(rpe_x, rpe_y);

    mma_gemm<<<dim3(8, 32, 1), 256>>>(bq, bk, bv, bo, out, 3);
}

// round 5
// speedup vs baseline: 3.1699x; 1.6617x over previous
#include <cuda_runtime.h>
#include <cuda_bf16.h>
#include <math.h>

#define B_  4
#define G_  1024
#define D_  512
#define H_  8
#define DH  64
#define MK  (4096*512)
#define WK  (512*512)

// ---- scratch (device globals: allocation-free rule) ----
__device__ unsigned g_bku[B_*G_*G_/2];                 // packed u16 buckets (2 per u32)
__device__ __align__(16) __nv_bfloat16 g_Qh[B_*H_*G_*DH], g_Ql[B_*H_*G_*DH];
__device__ __align__(16) __nv_bfloat16 g_Kh[B_*H_*G_*DH], g_Kl[B_*H_*G_*DH];
__device__ __align__(16) __nv_bfloat16 g_Vh[B_*H_*G_*DH], g_Vl[B_*H_*G_*DH];
// bf16 hi/lo split operands for projections: A slabs 0..2 = q/k/v input, 3 = attn out
__device__ __align__(16) __nv_bfloat16 g_Ah[4*MK];
__device__ __align__(16) __nv_bfloat16 g_Al[4*MK];
__device__ __align__(16) __nv_bfloat16 g_Wh[4*WK];
__device__ __align__(16) __nv_bfloat16 g_Wl[4*WK];

__device__ __forceinline__ unsigned smem_u32(const void* p) {
    unsigned r;
    asm("{ .reg .u64 t; cvta.to.shared.u64 t, %1; cvt.u32.u64 %0, t; }"
        : "=r"(r) : "l"(p));
    return r;
}
__device__ __forceinline__ void split2(float a, float b, unsigned& hp, unsigned& lp) {
    __nv_bfloat162 h = __floats2bfloat162_rn(a, b);
    float ra = a - __bfloat162float(h.x);
    float rb = b - __bfloat162float(h.y);
    __nv_bfloat162 l = __floats2bfloat162_rn(ra, rb);
    hp = *(unsigned*)&h;
    lp = *(unsigned*)&l;
}

// ================= bucket precompute (packed u16) =================
__device__ __forceinline__ int rpb(float d) {
    float ad = fabsf(d);
    int li;
    if (ad >= 128.0f) {
        li = 7;
    } else {
        float n = fmaxf(ad, 1e-6f);
        li = (int)floorf(__fdiv_rn(logf(n), 0.69314718055994530942f));
        li = max(0, min(li, 31));
    }
    return d > 0.0f ? 31 + li : (d < 0.0f ? 31 - li : 31);
}

__global__ void bucket_kernel(const float* __restrict__ coords,
                              const int*   __restrict__ mask) {
    int i = blockIdx.x * blockDim.x + threadIdx.x;     // < 2M
    int idx = i << 1;
    int k = idx & (G_-1);
    int q = (idx >> 10) & (G_-1);
    int b = idx >> 20;
    float2 cq  = ((const float2*)coords)[b*G_ + q];
    float2 ck0 = ((const float2*)coords)[b*G_ + k];
    float2 ck1 = ((const float2*)coords)[b*G_ + k + 1];
    unsigned v0 = ((unsigned)rpb(cq.x - ck0.x) << 6) | (unsigned)rpb(cq.y - ck0.y);
    unsigned v1 = ((unsigned)rpb(cq.x - ck1.x) << 6) | (unsigned)rpb(cq.y - ck1.y);
    if (mask[b*G_ + k]     == 0) v0 |= 0x8000u;
    if (mask[b*G_ + k + 1] == 0) v1 |= 0x8000u;
    g_bku[i] = v0 | (v1 << 16);
}

// ================= fp32 -> bf16 hi/lo converts =================
__global__ void convert_x(const float* __restrict__ q,
                          const float* __restrict__ k,
                          const float* __restrict__ v) {
    int i = blockIdx.x * blockDim.x + threadIdx.x;
    int e = i << 2;
    int z = e / MK;
    int r = e - z * MK;
    const float* src = (z == 0) ? q : (z == 1) ? k : v;
    float4 x = *(const float4*)(src + r);
    unsigned hp0, lp0, hp1, lp1;
    split2(x.x, x.y, hp0, lp0);
    split2(x.z, x.w, hp1, lp1);
    *(uint2*)(g_Ah + e) = make_uint2(hp0, hp1);
    *(uint2*)(g_Al + e) = make_uint2(lp0, lp1);
}

__global__ void convert_w(const float* __restrict__ wq, const float* __restrict__ wk,
                          const float* __restrict__ wv, const float* __restrict__ wo) {
    int i = blockIdx.x * blockDim.x + threadIdx.x;
    int e = i << 2;
    int z = e >> 18;
    int r = e & (WK - 1);
    const float* src = (z == 0) ? wq : (z == 1) ? wk : (z == 2) ? wv : wo;
    float4 x = *(const float4*)(src + r);
    unsigned hp0, lp0, hp1, lp1;
    split2(x.x, x.y, hp0, lp0);
    split2(x.z, x.w, hp1, lp1);
    *(uint2*)(g_Wh + e) = make_uint2(hp0, hp1);
    *(uint2*)(g_Wl + e) = make_uint2(lp0, lp1);
}

// ================= HMMA primitives =================
__device__ __forceinline__ void ldsm4(unsigned addr, unsigned& r0, unsigned& r1,
                                      unsigned& r2, unsigned& r3) {
    asm volatile("ldmatrix.sync.aligned.m8n8.x4.shared.b16 {%0,%1,%2,%3}, [%4];"
                 : "=r"(r0), "=r"(r1), "=r"(r2), "=r"(r3) : "r"(addr));
}
__device__ __forceinline__ void ldsm4t(unsigned addr, unsigned& r0, unsigned& r1,
                                       unsigned& r2, unsigned& r3) {
    asm volatile("ldmatrix.sync.aligned.m8n8.x4.trans.shared.b16 {%0,%1,%2,%3}, [%4];"
                 : "=r"(r0), "=r"(r1), "=r"(r2), "=r"(r3) : "r"(addr));
}
__device__ __forceinline__ void mma16816(float* d, const unsigned* a,
                                         const unsigned* b) {
    asm volatile(
        "mma.sync.aligned.m16n8k16.row.col.f32.bf16.bf16.f32 "
        "{%0,%1,%2,%3}, {%4,%5,%6,%7}, {%8,%9}, {%0,%1,%2,%3};"
        : "+f"(d[0]), "+f"(d[1]), "+f"(d[2]), "+f"(d[3])
        : "r"(a[0]), "r"(a[1]), "r"(a[2]), "r"(a[3]), "r"(b[0]), "r"(b[1]));
}

// ================= HMMA split-bf16 projection GEMM =================
__global__ __launch_bounds__(256) void mma_gemm(
    const float* __restrict__ bq, const float* __restrict__ bk,
    const float* __restrict__ bv, const float* __restrict__ bo,
    float* __restrict__ outp, int zbase)
{
    __shared__ __align__(1024) char sa[16384];
    __shared__ __align__(1024) char sb[8192];

    int z = blockIdx.z + zbase;
    const __nv_bfloat16* Ah = g_Ah + (size_t)z * MK;
    const __nv_bfloat16* Al = g_Al + (size_t)z * MK;
    const __nv_bfloat16* Bh = g_Wh + (size_t)z * WK;
    const __nv_bfloat16* Bl = g_Wl + (size_t)z * WK;
    const float* bias = (z == 0) ? bq : (z == 1) ? bk : (z == 2) ? bv : bo;

    int tid = threadIdx.x, wid = tid >> 5, lane = tid & 31;
    int m0 = blockIdx.y * 128;
    int n0 = blockIdx.x * 64;
    int wm = wid >> 1, wn = wid & 1;

    unsigned sa_u = smem_u32(sa), sb_u = smem_u32(sb);

    int sub = lane >> 3, r8 = lane & 7;
    int a_row = wm * 32 + ((sub & 1) << 3) + r8;
    int b_row = wn * 32 + ((sub & 1) << 3) + r8;
    int colb  = (sub >> 1) << 4;
    int grow = tid >> 3, gcu = tid & 7;

    float acc[2][4][4] = {};
    uint4 pa[4], pb[2];

    {
        #pragma unroll
        for (int t = 0; t < 4; t++)
            pa[t] = *(const uint4*)(Ah + (size_t)(m0 + grow + t*32) * 512 + (gcu << 3));
        #pragma unroll
        for (int t = 0; t < 2; t++)
            pb[t] = *(const uint4*)(Bh + (size_t)(n0 + grow + t*32) * 512 + (gcu << 3));
    }

    for (int c = 0; c < 24; c++) {
        #pragma unroll
        for (int t = 0; t < 4; t++) {
            unsigned off = ((grow + t*32) << 7) + (gcu << 4);
            off ^= (off >> 3) & 0x70;
            *(uint4*)(sa + off) = pa[t];
        }
        #pragma unroll
        for (int t = 0; t < 2; t++) {
            unsigned off = ((grow + t*32) << 7) + (gcu << 4);
            off ^= (off >> 3) & 0x70;
            *(uint4*)(sb + off) = pb[t];
        }
        __syncthreads();

        if (c < 23) {
            int cn = c + 1;
            int p  = cn >> 3;
            int k0 = (cn & 7) << 6;
            const __nv_bfloat16* As = (p == 1) ? Al : Ah;
            const __nv_bfloat16* Bs = (p == 2) ? Bl : Bh;
            #pragma unroll
            for (int t = 0; t < 4; t++)
                pa[t] = *(const uint4*)(As + (size_t)(m0 + grow + t*32) * 512 + k0 + (gcu << 3));
            #pragma unroll
            for (int t = 0; t < 2; t++)
                pb[t] = *(const uint4*)(Bs + (size_t)(n0 + grow + t*32) * 512 + k0 + (gcu << 3));
        }

        #pragma unroll
        for (int ks = 0; ks < 4; ks++) {
            unsigned a[2][4], bf[4][2];
            #pragma unroll
            for (int i = 0; i < 2; i++) {
                unsigned off = ((a_row + i*16) << 7) + colb + (ks << 5);
                off ^= (off >> 3) & 0x70;
                ldsm4(sa_u + off, a[i][0], a[i][1], a[i][2], a[i][3]);
            }
            #pragma unroll
            for (int jj = 0; jj < 2; jj++) {
                unsigned off = ((b_row + jj*16) << 7) + colb + (ks << 5);
                off ^= (off >> 3) & 0x70;
                unsigned r0, r1, r2, r3;
                ldsm4(sb_u + off, r0, r1, r2, r3);
                bf[jj*2+0][0] = r0; bf[jj*2+0][1] = r2;
                bf[jj*2+1][0] = r1; bf[jj*2+1][1] = r3;
            }
            #pragma unroll
            for (int i = 0; i < 2; i++)
                #pragma unroll
                for (int j = 0; j < 4; j++)
                    mma16816(acc[i][j], a[i], bf[j]);
        }
        __syncthreads();
    }

    int rbase = m0 + wm * 32 + (lane >> 2);
    int cbase = n0 + wn * 32 + ((lane & 3) << 1);
    #pragma unroll
    for (int i = 0; i < 2; i++) {
        #pragma unroll
        for (int j = 0; j < 4; j++) {
            int c = cbase + j * 8;
            float bx = bias[c], by = bias[c+1];
            #pragma unroll
            for (int half = 0; half < 2; half++) {
                int r = rbase + i * 16 + half * 8;
                float vx = acc[i][j][half*2+0] + bx;
                float vy = acc[i][j][half*2+1] + by;
                if (z == 3) {
                    *(float2*)(outp + (size_t)r * 512 + c) = make_float2(vx, vy);
                } else {
                    __nv_bfloat16* dh = (z == 0) ? g_Qh : (z == 1) ? g_Kh : g_Vh;
                    __nv_bfloat16* dl = (z == 0) ? g_Ql : (z == 1) ? g_Kl : g_Vl;
                    int bb = r >> 10, g = r & 1023;
                    int h = c >> 6, dd = c & 63;
                    size_t idx = (((size_t)(bb << 3) + h) << 16) + (g << 6) + dd;
                    unsigned hp, lp;
                    split2(vx, vy, hp, lp);
                    *(unsigned*)(dh + idx) = hp;
                    *(unsigned*)(dl + idx) = lp;
                }
            }
        }
    }
}

// ================= HMMA flash attention =================
// block = 128q x 64k tiles, 8 warps (16q each spanning all 64 k / 64 d)
#define SM_KH  0
#define SM_KL  8192
#define SM_VH  16384
#define SM_VL  24576
#define SM_RXY 32768
#define SM_BKT 49152
#define ATTN_SMEM (49152 + 128*33*4)

__global__ __launch_bounds__(256, 2) void attn_mma(
    const float* __restrict__ rpe_x, const float* __restrict__ rpe_y)
{
    extern __shared__ char smc[];
    float* rxy = (float*)(smc + SM_RXY);
    unsigned* sBkt = (unsigned*)(smc + SM_BKT);

    int tid = threadIdx.x, wid = tid >> 5, lane = tid & 31;
    int bh = blockIdx.y;
    int b = bh >> 3, hh = bh & 7;
    int q0 = blockIdx.x * 128;
    unsigned smu = smem_u32(smc);

    for (int i = tid; i < 4096; i += 256) {
        int bx = i >> 6, by = i & 63;
        if (bx < 63 && by < 63)
            rxy[i] = rpe_x[bx*8 + hh] + rpe_y[by*8 + hh];
    }

    int sub = lane >> 3, r8v = lane & 7;
    int r = lane >> 2, c = lane & 3;

    // stage Q (hi then lo) into K/V area, extract A-frags to regs
    unsigned qh[4][4], ql[4][4];
    #pragma unroll
    for (int s = 0; s < 2; s++) {
        const __nv_bfloat16* src = s ? g_Ql : g_Qh;
        __syncthreads();
        for (int i = tid; i < 1024; i += 256) {
            int row = i >> 3, cu = i & 7;
            unsigned off = (row << 7) + (cu << 4);
            off ^= (off >> 3) & 0x70;
            *(uint4*)(smc + off) =
                *(const uint4*)(src + ((size_t)(bh << 10) + q0 + row) * 64 + (cu << 3));
        }
        __syncthreads();
        unsigned qrow = (unsigned)(wid << 4) + ((sub & 1) << 3) + r8v;
        unsigned qcb = (sub >> 1) << 4;
        #pragma unroll
        for (int ks = 0; ks < 4; ks++) {
            unsigned off = (qrow << 7) + qcb + (ks << 5);
            off ^= (off >> 3) & 0x70;
            if (s) ldsm4(smu + off, ql[ks][0], ql[ks][1], ql[ks][2], ql[ks][3]);
            else   ldsm4(smu + off, qh[ks][0], qh[ks][1], qh[ks][2], qh[ks][3]);
        }
    }

    float o[8][4] = {};
    float m2[2] = {-1e30f, -1e30f};
    float l2[2] = {0.0f, 0.0f};

    const __nv_bfloat16* kh = g_Kh + ((size_t)bh << 10) * 64;
    const __nv_bfloat16* kl = g_Kl + ((size_t)bh << 10) * 64;
    const __nv_bfloat16* vh = g_Vh + ((size_t)bh << 10) * 64;
    const __nv_bfloat16* vl = g_Vl + ((size_t)bh << 10) * 64;
    const unsigned short* bksrc =
        (const unsigned short*)g_bku + (((size_t)(b << 10) + q0) << 10);

    for (int kt = 0; kt < G_; kt += 64) {
        __syncthreads();
        for (int i = tid; i < 512; i += 256) {
            int row = i >> 3, cu = i & 7;
            unsigned off = (row << 7) + (cu << 4);
            off ^= (off >> 3) & 0x70;
            size_t gs = (size_t)(kt + row) * 64 + (cu << 3);
            *(uint4*)(smc + SM_KH + off) = *(const uint4*)(kh + gs);
            *(uint4*)(smc + SM_KL + off) = *(const uint4*)(kl + gs);
            *(uint4*)(smc + SM_VH + off) = *(const uint4*)(vh + gs);
            *(uint4*)(smc + SM_VL + off) = *(const uint4*)(vl + gs);
        }
        for (int i = tid; i < 1024; i += 256) {
            int row = i >> 3, cu = i & 7;
            uint4 w = *(const uint4*)(bksrc + ((size_t)row << 10) + kt + (cu << 3));
            unsigned* d = sBkt + row * 33 + (cu << 2);
            d[0] = w.x; d[1] = w.y; d[2] = w.z; d[3] = w.w;
        }
        __syncthreads();

        // ---- S = Q K^T (3 split passes) ----
        float S[8][4] = {};
        #pragma unroll
        for (int ks = 0; ks < 4; ks++) {
            unsigned bf[8][2];
            #pragma unroll
            for (int t = 0; t < 4; t++) {
                unsigned krow = (t << 4) + ((sub & 1) << 3) + r8v;
                unsigned off = (krow << 7) + ((sub >> 1) << 4) + (ks << 5);
                off ^= (off >> 3) & 0x70;
                unsigned r0, r1, r2, r3;
                ldsm4(smu + SM_KH + off, r0, r1, r2, r3);
                bf[t*2+0][0] = r0; bf[t*2+0][1] = r2;
                bf[t*2+1][0] = r1; bf[t*2+1][1] = r3;
            }
            #pragma unroll
            for (int n = 0; n < 8; n++) {
                mma16816(S[n], qh[ks], bf[n]);
                mma16816(S[n], ql[ks], bf[n]);
            }
        }
        #pragma unroll
        for (int ks = 0; ks < 4; ks++) {
            unsigned bf[8][2];
            #pragma unroll
            for (int t = 0; t < 4; t++) {
                unsigned krow = (t << 4) + ((sub & 1) << 3) + r8v;
                unsigned off = (krow << 7) + ((sub >> 1) << 4) + (ks << 5);
                off ^= (off >> 3) & 0x70;
                unsigned r0, r1, r2, r3;
                ldsm4(smu + SM_KL + off, r0, r1, r2, r3);
                bf[t*2+0][0] = r0; bf[t*2+0][1] = r2;
                bf[t*2+1][0] = r1; bf[t*2+1][1] = r3;
            }
            #pragma unroll
            for (int n = 0; n < 8; n++)
                mma16816(S[n], qh[ks], bf[n]);
        }

        // ---- bias + online softmax, pack P hi/lo as A-frags ----
        unsigned pAh[4][4], pAl[4][4];
        #pragma unroll
        for (int h = 0; h < 2; h++) {
            int rowq = (wid << 4) + r + (h << 3);
            const unsigned* brow = sBkt + rowq * 33 + c;
            float rm = -1e30f;
            #pragma unroll
            for (int j = 0; j < 8; j++) {
                unsigned w = brow[j << 2];
                unsigned k0 = w & 0xffffu, k1 = w >> 16;
                float s0 = (k0 & 0x8000u) ? -1e30f
                         : fmaf(S[j][h*2+0], 0.125f, rxy[k0 & 0xfffu]);
                float s1 = (k1 & 0x8000u) ? -1e30f
                         : fmaf(S[j][h*2+1], 0.125f, rxy[k1 & 0xfffu]);
                S[j][h*2+0] = s0; S[j][h*2+1] = s1;
                rm = fmaxf(rm, fmaxf(s0, s1));
            }
            rm = fmaxf(rm, __shfl_xor_sync(0xffffffffu, rm, 1));
            rm = fmaxf(rm, __shfl_xor_sync(0xffffffffu, rm, 2));
            float mn = fmaxf(m2[h], rm);
            float corr = __expf(m2[h] - mn);
            m2[h] = mn;
            float rs = 0.0f;
            #pragma unroll
            for (int j = 0; j < 8; j++) {
                float p0 = __expf(S[j][h*2+0] - mn);
                float p1 = __expf(S[j][h*2+1] - mn);
                rs += p0 + p1;
                unsigned hp, lp;
                split2(p0, p1, hp, lp);
                pAh[j >> 1][(j & 1) * 2 + h] = hp;
                pAl[j >> 1][(j & 1) * 2 + h] = lp;
            }
            l2[h] = l2[h] * corr + rs;
            #pragma unroll
            for (int n = 0; n < 8; n++) {
                o[n][h*2+0] *= corr;
                o[n][h*2+1] *= corr;
            }
        }

        // ---- O += P V (3 split passes, V via trans ldmatrix) ----
        int krowv = (lane & 15);
        int dby = ((lane >> 4) << 4);
        #pragma unroll
        for (int jj = 0; jj < 4; jj++) {
            unsigned bf[8][2];
            #pragma unroll
            for (int t = 0; t < 4; t++) {
                unsigned off = (((jj << 4) + krowv) << 7) + (t << 5) + dby;
                off ^= (off >> 3) & 0x70;
                unsigned r0, r1, r2, r3;
                ldsm4t(smu + SM_VH + off, r0, r1, r2, r3);
                bf[t*2+0][0] = r0; bf[t*2+0][1] = r1;
                bf[t*2+1][0] = r2; bf[t*2+1][1] = r3;
            }
            #pragma unroll
            for (int n = 0; n < 8; n++) {
                mma16816(o[n], pAh[jj], bf[n]);
                mma16816(o[n], pAl[jj], bf[n]);
            }
        }
        #pragma unroll
        for (int jj = 0; jj < 4; jj++) {
            unsigned bf[8][2];
            #pragma unroll
            for (int t = 0; t < 4; t++) {
                unsigned off = (((jj << 4) + krowv) << 7) + (t << 5) + dby;
                off ^= (off >> 3) & 0x70;
                unsigned r0, r1, r2, r3;
                ldsm4t(smu + SM_VL + off, r0, r1, r2, r3);
                bf[t*2+0][0] = r0; bf[t*2+0][1] = r1;
                bf[t*2+1][0] = r2; bf[t*2+1][1] = r3;
            }
            #pragma unroll
            for (int n = 0; n < 8; n++)
                mma16816(o[n], pAh[jj], bf[n]);
        }
    }

    // ---- finalize: normalize + write bf16 hi/lo to A-slab 3 ----
    #pragma unroll
    for (int h = 0; h < 2; h++) {
        float ls = l2[h];
        ls += __shfl_xor_sync(0xffffffffu, ls, 1);
        ls += __shfl_xor_sync(0xffffffffu, ls, 2);
        float inv = 1.0f / ls;
        int q = q0 + (wid << 4) + r + (h << 3);
        size_t base = 3*(size_t)MK + ((size_t)((b << 10) + q)) * 512 + hh * 64 + (c << 1);
        #pragma unroll
        for (int j = 0; j < 8; j++) {
            float f0 = o[j][h*2+0] * inv;
            float f1 = o[j][h*2+1] * inv;
            unsigned hp, lp;
            split2(f0, f1, hp, lp);
            *(unsigned*)(g_Ah + base + (j << 3)) = hp;
            *(unsigned*)(g_Al + base + (j << 3)) = lp;
        }
    }
}

// ================= launch =================
extern "C" void kernel_launch(void* const* d_in, const int* in_sizes, int n_in,
                              void* d_out, int out_size) {
    const float* query  = (const float*)d_in[0];
    const float* key    = (const float*)d_in[1];
    const float* value  = (const float*)d_in[2];
    const float* coords = (const float*)d_in[3];
    const int*   mask   = (const int*)  d_in[4];
    const float* Wq = (const float*)d_in[5];
    const float* bq = (const float*)d_in[6];
    const float* Wk = (const float*)d_in[7];
    const float* bk = (const float*)d_in[8];
    const float* Wv = (const float*)d_in[9];
    const float* bv = (const float*)d_in[10];
    const float* Wo = (const float*)d_in[11];
    const float* bo = (const float*)d_in[12];
    const float* rpe_x = (const float*)d_in[13];
    const float* rpe_y = (const float*)d_in[14];
    float* out = (float*)d_out;

    cudaFuncSetAttribute(attn_mma,
                         cudaFuncAttributeMaxDynamicSharedMemorySize, ATTN_SMEM);

    convert_x<<<(3*MK/4)/256, 256>>>(query, key, value);
    convert_w<<<(4*WK/4)/256, 256>>>(Wq, Wk, Wv, Wo);
    bucket_kernel<<<(B_*G_*G_/2)/256, 256>>>(coords, mask);

    mma_gemm<<<dim3(8, 32, 3), 256>>>(bq, bk, bv, bo, out, 0);

    attn_mma<<<dim3(8, 32), 256, ATTN_SMEM>>>(rpe_x, rpe_y);

    mma_gemm<<<dim3(8, 32, 1), 256>>>(bq, bk, bv, bo, out, 3);
}

// round 6
// speedup vs baseline: 3.6387x; 1.1479x over previous
#include <cuda_runtime.h>
#include <cuda_bf16.h>
#include <math.h>

#define B_  4
#define G_  1024
#define D_  512
#define H_  8
#define DH  64
#define MK  (4096*512)
#define WK  (512*512)

// ---- scratch (device globals: allocation-free rule) ----
__device__ unsigned g_bku[B_*G_*G_/2];                 // packed u16 buckets (2 per u32)
__device__ __align__(16) __nv_bfloat16 g_Qh[B_*H_*G_*DH], g_Ql[B_*H_*G_*DH];
__device__ __align__(16) __nv_bfloat16 g_Kh[B_*H_*G_*DH], g_Kl[B_*H_*G_*DH];
__device__ __align__(16) __nv_bfloat16 g_Vh[B_*H_*G_*DH], g_Vl[B_*H_*G_*DH];
__device__ __align__(16) __nv_bfloat16 g_Ah[4*MK];
__device__ __align__(16) __nv_bfloat16 g_Al[4*MK];
__device__ __align__(16) __nv_bfloat16 g_Wh[4*WK];
__device__ __align__(16) __nv_bfloat16 g_Wl[4*WK];

__device__ __forceinline__ unsigned smem_u32(const void* p) {
    unsigned r;
    asm("{ .reg .u64 t; cvta.to.shared.u64 t, %1; cvt.u32.u64 %0, t; }"
        : "=r"(r) : "l"(p));
    return r;
}
__device__ __forceinline__ void split2(float a, float b, unsigned& hp, unsigned& lp) {
    __nv_bfloat162 h = __floats2bfloat162_rn(a, b);
    float ra = a - __bfloat162float(h.x);
    float rb = b - __bfloat162float(h.y);
    __nv_bfloat162 l = __floats2bfloat162_rn(ra, rb);
    hp = *(unsigned*)&h;
    lp = *(unsigned*)&l;
}
__device__ __forceinline__ void cpa16(unsigned saddr, const void* g) {
    asm volatile("cp.async.cg.shared.global [%0], [%1], 16;"
                 :: "r"(saddr), "l"(g));
}

// ================= bucket precompute (packed u16) =================
__device__ __forceinline__ int rpb(float d) {
    float ad = fabsf(d);
    int li;
    if (ad >= 128.0f) {
        li = 7;
    } else {
        float n = fmaxf(ad, 1e-6f);
        li = (int)floorf(__log2f(n));
        li = max(0, min(li, 31));
    }
    return d > 0.0f ? 31 + li : (d < 0.0f ? 31 - li : 31);
}

__global__ void bucket_kernel(const float* __restrict__ coords,
                              const int*   __restrict__ mask) {
    int i = blockIdx.x * blockDim.x + threadIdx.x;
    int idx = i << 1;
    int k = idx & (G_-1);
    int q = (idx >> 10) & (G_-1);
    int b = idx >> 20;
    float2 cq  = ((const float2*)coords)[b*G_ + q];
    float2 ck0 = ((const float2*)coords)[b*G_ + k];
    float2 ck1 = ((const float2*)coords)[b*G_ + k + 1];
    unsigned v0 = ((unsigned)rpb(cq.x - ck0.x) << 6) | (unsigned)rpb(cq.y - ck0.y);
    unsigned v1 = ((unsigned)rpb(cq.x - ck1.x) << 6) | (unsigned)rpb(cq.y - ck1.y);
    if (mask[b*G_ + k]     == 0) v0 |= 0x8000u;
    if (mask[b*G_ + k + 1] == 0) v1 |= 0x8000u;
    g_bku[i] = v0 | (v1 << 16);
}

// ================= fp32 -> bf16 hi/lo converts =================
__global__ void convert_x(const float* __restrict__ q,
                          const float* __restrict__ k,
                          const float* __restrict__ v) {
    int i = blockIdx.x * blockDim.x + threadIdx.x;
    int e = i << 2;
    int z = e / MK;
    int r = e - z * MK;
    const float* src = (z == 0) ? q : (z == 1) ? k : v;
    float4 x = *(const float4*)(src + r);
    unsigned hp0, lp0, hp1, lp1;
    split2(x.x, x.y, hp0, lp0);
    split2(x.z, x.w, hp1, lp1);
    *(uint2*)(g_Ah + e) = make_uint2(hp0, hp1);
    *(uint2*)(g_Al + e) = make_uint2(lp0, lp1);
}

__global__ void convert_w(const float* __restrict__ wq, const float* __restrict__ wk,
                          const float* __restrict__ wv, const float* __restrict__ wo) {
    int i = blockIdx.x * blockDim.x + threadIdx.x;
    int e = i << 2;
    int z = e >> 18;
    int r = e & (WK - 1);
    const float* src = (z == 0) ? wq : (z == 1) ? wk : (z == 2) ? wv : wo;
    float4 x = *(const float4*)(src + r);
    unsigned hp0, lp0, hp1, lp1;
    split2(x.x, x.y, hp0, lp0);
    split2(x.z, x.w, hp1, lp1);
    *(uint2*)(g_Wh + e) = make_uint2(hp0, hp1);
    *(uint2*)(g_Wl + e) = make_uint2(lp0, lp1);
}

// ================= HMMA primitives =================
__device__ __forceinline__ void ldsm4(unsigned addr, unsigned& r0, unsigned& r1,
                                      unsigned& r2, unsigned& r3) {
    asm volatile("ldmatrix.sync.aligned.m8n8.x4.shared.b16 {%0,%1,%2,%3}, [%4];"
                 : "=r"(r0), "=r"(r1), "=r"(r2), "=r"(r3) : "r"(addr));
}
__device__ __forceinline__ void ldsm4t(unsigned addr, unsigned& r0, unsigned& r1,
                                       unsigned& r2, unsigned& r3) {
    asm volatile("ldmatrix.sync.aligned.m8n8.x4.trans.shared.b16 {%0,%1,%2,%3}, [%4];"
                 : "=r"(r0), "=r"(r1), "=r"(r2), "=r"(r3) : "r"(addr));
}
__device__ __forceinline__ void mma16816(float* d, const unsigned* a,
                                         const unsigned* b) {
    asm volatile(
        "mma.sync.aligned.m16n8k16.row.col.f32.bf16.bf16.f32 "
        "{%0,%1,%2,%3}, {%4,%5,%6,%7}, {%8,%9}, {%0,%1,%2,%3};"
        : "+f"(d[0]), "+f"(d[1]), "+f"(d[2]), "+f"(d[3])
        : "r"(a[0]), "r"(a[1]), "r"(a[2]), "r"(a[3]), "r"(b[0]), "r"(b[1]));
}

// ================= HMMA split-bf16 projection GEMM (cp.async 3-stage) =====
#define STAGE 24576
#define GEMM_DSMEM (3*STAGE + 1024)

__global__ __launch_bounds__(256, 2) void mma_gemm(
    const float* __restrict__ bq, const float* __restrict__ bk,
    const float* __restrict__ bv, const float* __restrict__ bo,
    float* __restrict__ outp, int zbase)
{
    extern __shared__ char smd[];

    int z = blockIdx.z + zbase;
    const __nv_bfloat16* Ah = g_Ah + (size_t)z * MK;
    const __nv_bfloat16* Al = g_Al + (size_t)z * MK;
    const __nv_bfloat16* Bh = g_Wh + (size_t)z * WK;
    const __nv_bfloat16* Bl = g_Wl + (size_t)z * WK;
    const float* bias = (z == 0) ? bq : (z == 1) ? bk : (z == 2) ? bv : bo;

    int tid = threadIdx.x, wid = tid >> 5, lane = tid & 31;
    int m0 = blockIdx.y * 128;
    int n0 = blockIdx.x * 64;
    int wm = wid >> 1, wn = wid & 1;

    unsigned raw = smem_u32(smd);
    unsigned base = (raw + 1023u) & ~1023u;

    int sub = lane >> 3, r8 = lane & 7;
    int a_row = wm * 32 + ((sub & 1) << 3) + r8;
    int b_row = wn * 32 + ((sub & 1) << 3) + r8;
    int colb  = (sub >> 1) << 4;
    int grow = tid >> 3, gcu = tid & 7;

    // per-thread swizzled stage offsets (6 cp.asyncs per chunk)
    unsigned soff[4];
    #pragma unroll
    for (int t = 0; t < 4; t++) {
        unsigned off = ((grow + t*32) << 7) + (gcu << 4);
        soff[t] = off ^ ((off >> 3) & 0x70);
    }

    float acc[2][4][4] = {};

    // ---- pipeline issue helper ----
    #define ISSUE(c) do {                                                      \
        int p_ = (c) >> 3, k0_ = ((c) & 7) << 6;                               \
        const __nv_bfloat16* As_ = (p_ == 1) ? Al : Ah;                        \
        const __nv_bfloat16* Bs_ = (p_ == 2) ? Bl : Bh;                        \
        unsigned st_ = base + ((c) % 3) * STAGE;                               \
        _Pragma("unroll")                                                      \
        for (int t = 0; t < 4; t++)                                            \
            cpa16(st_ + soff[t],                                               \
                  As_ + (size_t)(m0 + grow + t*32) * 512 + k0_ + (gcu << 3));  \
        _Pragma("unroll")                                                      \
        for (int t = 0; t < 2; t++)                                            \
            cpa16(st_ + 16384 + soff[t],                                       \
                  Bs_ + (size_t)(n0 + grow + t*32) * 512 + k0_ + (gcu << 3));  \
        asm volatile("cp.async.commit_group;");                                \
    } while (0)

    ISSUE(0);
    ISSUE(1);

    for (int c = 0; c < 24; c++) {
        if (c < 23) asm volatile("cp.async.wait_group 1;");
        else        asm volatile("cp.async.wait_group 0;");
        __syncthreads();
        if (c + 2 < 24) ISSUE(c + 2);

        unsigned sa_u = base + (c % 3) * STAGE;
        unsigned sb_u = sa_u + 16384;

        #pragma unroll
        for (int ks = 0; ks < 4; ks++) {
            unsigned a[2][4], bf[4][2];
            #pragma unroll
            for (int i = 0; i < 2; i++) {
                unsigned off = ((a_row + i*16) << 7) + colb + (ks << 5);
                off ^= (off >> 3) & 0x70;
                ldsm4(sa_u + off, a[i][0], a[i][1], a[i][2], a[i][3]);
            }
            #pragma unroll
            for (int jj = 0; jj < 2; jj++) {
                unsigned off = ((b_row + jj*16) << 7) + colb + (ks << 5);
                off ^= (off >> 3) & 0x70;
                unsigned r0, r1, r2, r3;
                ldsm4(sb_u + off, r0, r1, r2, r3);
                bf[jj*2+0][0] = r0; bf[jj*2+0][1] = r2;
                bf[jj*2+1][0] = r1; bf[jj*2+1][1] = r3;
            }
            #pragma unroll
            for (int i = 0; i < 2; i++)
                #pragma unroll
                for (int j = 0; j < 4; j++)
                    mma16816(acc[i][j], a[i], bf[j]);
        }
    }

    int rbase = m0 + wm * 32 + (lane >> 2);
    int cbase = n0 + wn * 32 + ((lane & 3) << 1);
    #pragma unroll
    for (int i = 0; i < 2; i++) {
        #pragma unroll
        for (int j = 0; j < 4; j++) {
            int c = cbase + j * 8;
            float bx = bias[c], by = bias[c+1];
            #pragma unroll
            for (int half = 0; half < 2; half++) {
                int r = rbase + i * 16 + half * 8;
                float vx = acc[i][j][half*2+0] + bx;
                float vy = acc[i][j][half*2+1] + by;
                if (z == 3) {
                    *(float2*)(outp + (size_t)r * 512 + c) = make_float2(vx, vy);
                } else {
                    __nv_bfloat16* dh = (z == 0) ? g_Qh : (z == 1) ? g_Kh : g_Vh;
                    __nv_bfloat16* dl = (z == 0) ? g_Ql : (z == 1) ? g_Kl : g_Vl;
                    int bb = r >> 10, g = r & 1023;
                    int h = c >> 6, dd = c & 63;
                    size_t idx = (((size_t)(bb << 3) + h) << 16) + (g << 6) + dd;
                    unsigned hp, lp;
                    split2(vx, vy, hp, lp);
                    *(unsigned*)(dh + idx) = hp;
                    *(unsigned*)(dl + idx) = lp;
                }
            }
        }
    }
}

// ================= HMMA flash attention =================
#define SM_KH  0
#define SM_KL  8192
#define SM_VH  16384
#define SM_VL  24576
#define SM_RXY 32768
#define SM_BKT 49152
#define ATTN_SMEM (49152 + 128*33*4)

__global__ __launch_bounds__(256, 2) void attn_mma(
    const float* __restrict__ rpe_x, const float* __restrict__ rpe_y)
{
    extern __shared__ char smc[];
    float* rxy = (float*)(smc + SM_RXY);
    unsigned* sBkt = (unsigned*)(smc + SM_BKT);

    int tid = threadIdx.x, wid = tid >> 5, lane = tid & 31;
    int bh = blockIdx.y;
    int b = bh >> 3, hh = bh & 7;
    int q0 = blockIdx.x * 128;
    unsigned smu = smem_u32(smc);

    for (int i = tid; i < 4096; i += 256) {
        int bx = i >> 6, by = i & 63;
        if (bx < 63 && by < 63)
            rxy[i] = rpe_x[bx*8 + hh] + rpe_y[by*8 + hh];
    }

    int sub = lane >> 3, r8v = lane & 7;
    int r = lane >> 2, c = lane & 3;

    unsigned qh[4][4], ql[4][4];
    #pragma unroll
    for (int s = 0; s < 2; s++) {
        const __nv_bfloat16* src = s ? g_Ql : g_Qh;
        __syncthreads();
        for (int i = tid; i < 1024; i += 256) {
            int row = i >> 3, cu = i & 7;
            unsigned off = (row << 7) + (cu << 4);
            off ^= (off >> 3) & 0x70;
            *(uint4*)(smc + off) =
                *(const uint4*)(src + ((size_t)(bh << 10) + q0 + row) * 64 + (cu << 3));
        }
        __syncthreads();
        unsigned qrow = (unsigned)(wid << 4) + ((sub & 1) << 3) + r8v;
        unsigned qcb = (sub >> 1) << 4;
        #pragma unroll
        for (int ks = 0; ks < 4; ks++) {
            unsigned off = (qrow << 7) + qcb + (ks << 5);
            off ^= (off >> 3) & 0x70;
            if (s) ldsm4(smu + off, ql[ks][0], ql[ks][1], ql[ks][2], ql[ks][3]);
            else   ldsm4(smu + off, qh[ks][0], qh[ks][1], qh[ks][2], qh[ks][3]);
        }
    }

    float o[8][4] = {};
    float m2[2] = {-1e30f, -1e30f};
    float l2[2] = {0.0f, 0.0f};

    const __nv_bfloat16* kh = g_Kh + ((size_t)bh << 10) * 64;
    const __nv_bfloat16* kl = g_Kl + ((size_t)bh << 10) * 64;
    const __nv_bfloat16* vh = g_Vh + ((size_t)bh << 10) * 64;
    const __nv_bfloat16* vl = g_Vl + ((size_t)bh << 10) * 64;
    const unsigned short* bksrc =
        (const unsigned short*)g_bku + (((size_t)(b << 10) + q0) << 10);

    for (int kt = 0; kt < G_; kt += 64) {
        __syncthreads();
        for (int i = tid; i < 512; i += 256) {
            int row = i >> 3, cu = i & 7;
            unsigned off = (row << 7) + (cu << 4);
            off ^= (off >> 3) & 0x70;
            size_t gs = (size_t)(kt + row) * 64 + (cu << 3);
            *(uint4*)(smc + SM_KH + off) = *(const uint4*)(kh + gs);
            *(uint4*)(smc + SM_KL + off) = *(const uint4*)(kl + gs);
            *(uint4*)(smc + SM_VH + off) = *(const uint4*)(vh + gs);
            *(uint4*)(smc + SM_VL + off) = *(const uint4*)(vl + gs);
        }
        for (int i = tid; i < 1024; i += 256) {
            int row = i >> 3, cu = i & 7;
            uint4 w = *(const uint4*)(bksrc + ((size_t)row << 10) + kt + (cu << 3));
            unsigned* d = sBkt + row * 33 + (cu << 2);
            d[0] = w.x; d[1] = w.y; d[2] = w.z; d[3] = w.w;
        }
        __syncthreads();

        float S[8][4] = {};
        #pragma unroll
        for (int ks = 0; ks < 4; ks++) {
            unsigned bf[8][2];
            #pragma unroll
            for (int t = 0; t < 4; t++) {
                unsigned krow = (t << 4) + ((sub & 1) << 3) + r8v;
                unsigned off = (krow << 7) + ((sub >> 1) << 4) + (ks << 5);
                off ^= (off >> 3) & 0x70;
                unsigned r0, r1, r2, r3;
                ldsm4(smu + SM_KH + off, r0, r1, r2, r3);
                bf[t*2+0][0] = r0; bf[t*2+0][1] = r2;
                bf[t*2+1][0] = r1; bf[t*2+1][1] = r3;
            }
            #pragma unroll
            for (int n = 0; n < 8; n++) {
                mma16816(S[n], qh[ks], bf[n]);
                mma16816(S[n], ql[ks], bf[n]);
            }
        }
        #pragma unroll
        for (int ks = 0; ks < 4; ks++) {
            unsigned bf[8][2];
            #pragma unroll
            for (int t = 0; t < 4; t++) {
                unsigned krow = (t << 4) + ((sub & 1) << 3) + r8v;
                unsigned off = (krow << 7) + ((sub >> 1) << 4) + (ks << 5);
                off ^= (off >> 3) & 0x70;
                unsigned r0, r1, r2, r3;
                ldsm4(smu + SM_KL + off, r0, r1, r2, r3);
                bf[t*2+0][0] = r0; bf[t*2+0][1] = r2;
                bf[t*2+1][0] = r1; bf[t*2+1][1] = r3;
            }
            #pragma unroll
            for (int n = 0; n < 8; n++)
                mma16816(S[n], qh[ks], bf[n]);
        }

        unsigned pAh[4][4], pAl[4][4];
        #pragma unroll
        for (int h = 0; h < 2; h++) {
            int rowq = (wid << 4) + r + (h << 3);
            const unsigned* brow = sBkt + rowq * 33 + c;
            float rm = -1e30f;
            #pragma unroll
            for (int j = 0; j < 8; j++) {
                unsigned w = brow[j << 2];
                unsigned k0 = w & 0xffffu, k1 = w >> 16;
                float s0 = (k0 & 0x8000u) ? -1e30f
                         : fmaf(S[j][h*2+0], 0.125f, rxy[k0 & 0xfffu]);
                float s1 = (k1 & 0x8000u) ? -1e30f
                         : fmaf(S[j][h*2+1], 0.125f, rxy[k1 & 0xfffu]);
                S[j][h*2+0] = s0; S[j][h*2+1] = s1;
                rm = fmaxf(rm, fmaxf(s0, s1));
            }
            rm = fmaxf(rm, __shfl_xor_sync(0xffffffffu, rm, 1));
            rm = fmaxf(rm, __shfl_xor_sync(0xffffffffu, rm, 2));
            float mn = fmaxf(m2[h], rm);
            float corr = __expf(m2[h] - mn);
            m2[h] = mn;
            float rs = 0.0f;
            #pragma unroll
            for (int j = 0; j < 8; j++) {
                float p0 = __expf(S[j][h*2+0] - mn);
                float p1 = __expf(S[j][h*2+1] - mn);
                rs += p0 + p1;
                unsigned hp, lp;
                split2(p0, p1, hp, lp);
                pAh[j >> 1][(j & 1) * 2 + h] = hp;
                pAl[j >> 1][(j & 1) * 2 + h] = lp;
            }
            l2[h] = l2[h] * corr + rs;
            #pragma unroll
            for (int n = 0; n < 8; n++) {
                o[n][h*2+0] *= corr;
                o[n][h*2+1] *= corr;
            }
        }

        int krowv = (lane & 15);
        int dby = ((lane >> 4) << 4);
        #pragma unroll
        for (int jj = 0; jj < 4; jj++) {
            unsigned bf[8][2];
            #pragma unroll
            for (int t = 0; t < 4; t++) {
                unsigned off = (((jj << 4) + krowv) << 7) + (t << 5) + dby;
                off ^= (off >> 3) & 0x70;
                unsigned r0, r1, r2, r3;
                ldsm4t(smu + SM_VH + off, r0, r1, r2, r3);
                bf[t*2+0][0] = r0; bf[t*2+0][1] = r1;
                bf[t*2+1][0] = r2; bf[t*2+1][1] = r3;
            }
            #pragma unroll
            for (int n = 0; n < 8; n++) {
                mma16816(o[n], pAh[jj], bf[n]);
                mma16816(o[n], pAl[jj], bf[n]);
            }
        }
        #pragma unroll
        for (int jj = 0; jj < 4; jj++) {
            unsigned bf[8][2];
            #pragma unroll
            for (int t = 0; t < 4; t++) {
                unsigned off = (((jj << 4) + krowv) << 7) + (t << 5) + dby;
                off ^= (off >> 3) & 0x70;
                unsigned r0, r1, r2, r3;
                ldsm4t(smu + SM_VL + off, r0, r1, r2, r3);
                bf[t*2+0][0] = r0; bf[t*2+0][1] = r1;
                bf[t*2+1][0] = r2; bf[t*2+1][1] = r3;
            }
            #pragma unroll
            for (int n = 0; n < 8; n++)
                mma16816(o[n], pAh[jj], bf[n]);
        }
    }

    #pragma unroll
    for (int h = 0; h < 2; h++) {
        float ls = l2[h];
        ls += __shfl_xor_sync(0xffffffffu, ls, 1);
        ls += __shfl_xor_sync(0xffffffffu, ls, 2);
        float inv = 1.0f / ls;
        int q = q0 + (wid << 4) + r + (h << 3);
        size_t base = 3*(size_t)MK + ((size_t)((b << 10) + q)) * 512 + hh * 64 + (c << 1);
        #pragma unroll
        for (int j = 0; j < 8; j++) {
            float f0 = o[j][h*2+0] * inv;
            float f1 = o[j][h*2+1] * inv;
            unsigned hp, lp;
            split2(f0, f1, hp, lp);
            *(unsigned*)(g_Ah + base + (j << 3)) = hp;
            *(unsigned*)(g_Al + base + (j << 3)) = lp;
        }
    }
}

// ================= launch =================
extern "C" void kernel_launch(void* const* d_in, const int* in_sizes, int n_in,
                              void* d_out, int out_size) {
    const float* query  = (const float*)d_in[0];
    const float* key    = (const float*)d_in[1];
    const float* value  = (const float*)d_in[2];
    const float* coords = (const float*)d_in[3];
    const int*   mask   = (const int*)  d_in[4];
    const float* Wq = (const float*)d_in[5];
    const float* bq = (const float*)d_in[6];
    const float* Wk = (const float*)d_in[7];
    const float* bk = (const float*)d_in[8];
    const float* Wv = (const float*)d_in[9];
    const float* bv = (const float*)d_in[10];
    const float* Wo = (const float*)d_in[11];
    const float* bo = (const float*)d_in[12];
    const float* rpe_x = (const float*)d_in[13];
    const float* rpe_y = (const float*)d_in[14];
    float* out = (float*)d_out;

    cudaFuncSetAttribute(attn_mma,
                         cudaFuncAttributeMaxDynamicSharedMemorySize, ATTN_SMEM);
    cudaFuncSetAttribute(mma_gemm,
                         cudaFuncAttributeMaxDynamicSharedMemorySize, GEMM_DSMEM);

    convert_x<<<(3*MK/4)/256, 256>>>(query, key, value);
    convert_w<<<(4*WK/4)/256, 256>>>(Wq, Wk, Wv, Wo);
    bucket_kernel<<<(B_*G_*G_/2)/256, 256>>>(coords, mask);

    mma_gemm<<<dim3(8, 32, 3), 256, GEMM_DSMEM>>>(bq, bk, bv, bo, out, 0);

    attn_mma<<<dim3(8, 32), 256, ATTN_SMEM>>>(rpe_x, rpe_y);

    mma_gemm<<<dim3(8, 32, 1), 256, GEMM_DSMEM>>>(bq, bk, bv, bo, out, 3);
}

// round 7
// speedup vs baseline: 4.1057x; 1.1283x over previous
#include <cuda_runtime.h>
#include <cuda_bf16.h>
#include <math.h>

#define B_  4
#define G_  1024
#define D_  512
#define H_  8
#define DH  64
#define MK  (4096*512)
#define WK  (512*512)

// ---- scratch (device globals: allocation-free rule) ----
__device__ unsigned g_bku[B_*G_*G_/2];                 // packed u16 buckets (2 per u32)
__device__ __align__(16) __nv_bfloat16 g_Qh[B_*H_*G_*DH], g_Ql[B_*H_*G_*DH];
__device__ __align__(16) __nv_bfloat16 g_Kh[B_*H_*G_*DH], g_Kl[B_*H_*G_*DH];
__device__ __align__(16) __nv_bfloat16 g_Vh[B_*H_*G_*DH], g_Vl[B_*H_*G_*DH];
__device__ __align__(16) __nv_bfloat16 g_Ah[4*MK];
__device__ __align__(16) __nv_bfloat16 g_Al[4*MK];
__device__ __align__(16) __nv_bfloat16 g_Wh[4*WK];
__device__ __align__(16) __nv_bfloat16 g_Wl[4*WK];

__device__ __forceinline__ unsigned smem_u32(const void* p) {
    unsigned r;
    asm("{ .reg .u64 t; cvta.to.shared.u64 t, %1; cvt.u32.u64 %0, t; }"
        : "=r"(r) : "l"(p));
    return r;
}
__device__ __forceinline__ void split2(float a, float b, unsigned& hp, unsigned& lp) {
    __nv_bfloat162 h = __floats2bfloat162_rn(a, b);
    float ra = a - __bfloat162float(h.x);
    float rb = b - __bfloat162float(h.y);
    __nv_bfloat162 l = __floats2bfloat162_rn(ra, rb);
    hp = *(unsigned*)&h;
    lp = *(unsigned*)&l;
}
__device__ __forceinline__ void cpa16(unsigned saddr, const void* g) {
    asm volatile("cp.async.cg.shared.global [%0], [%1], 16;"
                 :: "r"(saddr), "l"(g));
}

// ================= bucket precompute (packed u16) =================
__device__ __forceinline__ int rpb(float d) {
    float ad = fabsf(d);
    int li;
    if (ad >= 128.0f) {
        li = 7;
    } else {
        float n = fmaxf(ad, 1e-6f);
        li = (int)floorf(__log2f(n));
        li = max(0, min(li, 31));
    }
    return d > 0.0f ? 31 + li : (d < 0.0f ? 31 - li : 31);
}

__global__ void bucket_kernel(const float* __restrict__ coords,
                              const int*   __restrict__ mask) {
    int i = blockIdx.x * blockDim.x + threadIdx.x;
    int idx = i << 1;
    int k = idx & (G_-1);
    int q = (idx >> 10) & (G_-1);
    int b = idx >> 20;
    float2 cq  = ((const float2*)coords)[b*G_ + q];
    float2 ck0 = ((const float2*)coords)[b*G_ + k];
    float2 ck1 = ((const float2*)coords)[b*G_ + k + 1];
    unsigned v0 = ((unsigned)rpb(cq.x - ck0.x) << 6) | (unsigned)rpb(cq.y - ck0.y);
    unsigned v1 = ((unsigned)rpb(cq.x - ck1.x) << 6) | (unsigned)rpb(cq.y - ck1.y);
    if (mask[b*G_ + k]     == 0) v0 |= 0x8000u;
    if (mask[b*G_ + k + 1] == 0) v1 |= 0x8000u;
    g_bku[i] = v0 | (v1 << 16);
}

// ================= fp32 -> bf16 hi/lo converts =================
__global__ void convert_x(const float* __restrict__ q,
                          const float* __restrict__ k,
                          const float* __restrict__ v) {
    int i = blockIdx.x * blockDim.x + threadIdx.x;
    int e = i << 2;
    int z = e / MK;
    int r = e - z * MK;
    const float* src = (z == 0) ? q : (z == 1) ? k : v;
    float4 x = *(const float4*)(src + r);
    unsigned hp0, lp0, hp1, lp1;
    split2(x.x, x.y, hp0, lp0);
    split2(x.z, x.w, hp1, lp1);
    *(uint2*)(g_Ah + e) = make_uint2(hp0, hp1);
    *(uint2*)(g_Al + e) = make_uint2(lp0, lp1);
}

__global__ void convert_w(const float* __restrict__ wq, const float* __restrict__ wk,
                          const float* __restrict__ wv, const float* __restrict__ wo) {
    int i = blockIdx.x * blockDim.x + threadIdx.x;
    int e = i << 2;
    int z = e >> 18;
    int r = e & (WK - 1);
    const float* src = (z == 0) ? wq : (z == 1) ? wk : (z == 2) ? wv : wo;
    float4 x = *(const float4*)(src + r);
    unsigned hp0, lp0, hp1, lp1;
    split2(x.x, x.y, hp0, lp0);
    split2(x.z, x.w, hp1, lp1);
    *(uint2*)(g_Wh + e) = make_uint2(hp0, hp1);
    *(uint2*)(g_Wl + e) = make_uint2(lp0, lp1);
}

// ================= HMMA primitives =================
__device__ __forceinline__ void ldsm4(unsigned addr, unsigned& r0, unsigned& r1,
                                      unsigned& r2, unsigned& r3) {
    asm volatile("ldmatrix.sync.aligned.m8n8.x4.shared.b16 {%0,%1,%2,%3}, [%4];"
                 : "=r"(r0), "=r"(r1), "=r"(r2), "=r"(r3) : "r"(addr));
}
__device__ __forceinline__ void ldsm4t(unsigned addr, unsigned& r0, unsigned& r1,
                                       unsigned& r2, unsigned& r3) {
    asm volatile("ldmatrix.sync.aligned.m8n8.x4.trans.shared.b16 {%0,%1,%2,%3}, [%4];"
                 : "=r"(r0), "=r"(r1), "=r"(r2), "=r"(r3) : "r"(addr));
}
__device__ __forceinline__ void mma16816(float* d, const unsigned* a,
                                         const unsigned* b) {
    asm volatile(
        "mma.sync.aligned.m16n8k16.row.col.f32.bf16.bf16.f32 "
        "{%0,%1,%2,%3}, {%4,%5,%6,%7}, {%8,%9}, {%0,%1,%2,%3};"
        : "+f"(d[0]), "+f"(d[1]), "+f"(d[2]), "+f"(d[3])
        : "r"(a[0]), "r"(a[1]), "r"(a[2]), "r"(a[3]), "r"(b[0]), "r"(b[1]));
}

// ================= HMMA split-bf16 GEMM: 128x128 tile, cp.async 3-stage ====
#define STAGE 32768
#define GEMM_DSMEM (3*STAGE + 1024)

__global__ __launch_bounds__(256, 2) void mma_gemm(
    const float* __restrict__ bq, const float* __restrict__ bk,
    const float* __restrict__ bv, const float* __restrict__ bo,
    float* __restrict__ outp, int zbase)
{
    extern __shared__ char smd[];

    int z = blockIdx.z + zbase;
    const __nv_bfloat16* Ah = g_Ah + (size_t)z * MK;
    const __nv_bfloat16* Al = g_Al + (size_t)z * MK;
    const __nv_bfloat16* Bh = g_Wh + (size_t)z * WK;
    const __nv_bfloat16* Bl = g_Wl + (size_t)z * WK;
    const float* bias = (z == 0) ? bq : (z == 1) ? bk : (z == 2) ? bv : bo;

    int tid = threadIdx.x, wid = tid >> 5, lane = tid & 31;
    int m0 = blockIdx.y * 128;
    int n0 = blockIdx.x * 128;
    int wm = wid >> 1, wn = wid & 1;         // warp tile: 32m x 64n

    unsigned raw = smem_u32(smd);
    unsigned base = (raw + 1023u) & ~1023u;

    int sub = lane >> 3, r8 = lane & 7;
    int a_row = wm * 32 + ((sub & 1) << 3) + r8;
    int b_row = wn * 64 + ((sub & 1) << 3) + r8;
    int colb  = (sub >> 1) << 4;
    int grow = tid >> 3, gcu = tid & 7;

    unsigned soff[4];
    #pragma unroll
    for (int t = 0; t < 4; t++) {
        unsigned off = ((grow + t*32) << 7) + (gcu << 4);
        soff[t] = off ^ ((off >> 3) & 0x70);
    }

    float acc[2][8][4] = {};

    #define ISSUE(c) do {                                                      \
        int p_ = (c) >> 3, k0_ = ((c) & 7) << 6;                               \
        const __nv_bfloat16* As_ = (p_ == 1) ? Al : Ah;                        \
        const __nv_bfloat16* Bs_ = (p_ == 2) ? Bl : Bh;                        \
        unsigned st_ = base + ((c) % 3) * STAGE;                               \
        _Pragma("unroll")                                                      \
        for (int t = 0; t < 4; t++)                                            \
            cpa16(st_ + soff[t],                                               \
                  As_ + (size_t)(m0 + grow + t*32) * 512 + k0_ + (gcu << 3));  \
        _Pragma("unroll")                                                      \
        for (int t = 0; t < 4; t++)                                            \
            cpa16(st_ + 16384 + soff[t],                                       \
                  Bs_ + (size_t)(n0 + grow + t*32) * 512 + k0_ + (gcu << 3));  \
        asm volatile("cp.async.commit_group;");                                \
    } while (0)

    ISSUE(0);
    ISSUE(1);

    for (int c = 0; c < 24; c++) {
        if (c < 23) asm volatile("cp.async.wait_group 1;");
        else        asm volatile("cp.async.wait_group 0;");
        __syncthreads();
        if (c + 2 < 24) ISSUE(c + 2);

        unsigned sa_u = base + (c % 3) * STAGE;
        unsigned sb_u = sa_u + 16384;

        #pragma unroll
        for (int ks = 0; ks < 4; ks++) {
            unsigned a[2][4], bf[8][2];
            #pragma unroll
            for (int i = 0; i < 2; i++) {
                unsigned off = ((a_row + i*16) << 7) + colb + (ks << 5);
                off ^= (off >> 3) & 0x70;
                ldsm4(sa_u + off, a[i][0], a[i][1], a[i][2], a[i][3]);
            }
            #pragma unroll
            for (int jj = 0; jj < 4; jj++) {
                unsigned off = ((b_row + jj*16) << 7) + colb + (ks << 5);
                off ^= (off >> 3) & 0x70;
                unsigned r0, r1, r2, r3;
                ldsm4(sb_u + off, r0, r1, r2, r3);
                bf[jj*2+0][0] = r0; bf[jj*2+0][1] = r2;
                bf[jj*2+1][0] = r1; bf[jj*2+1][1] = r3;
            }
            #pragma unroll
            for (int i = 0; i < 2; i++)
                #pragma unroll
                for (int j = 0; j < 8; j++)
                    mma16816(acc[i][j], a[i], bf[j]);
        }
    }

    int rbase = m0 + wm * 32 + (lane >> 2);
    int cbase = n0 + wn * 64 + ((lane & 3) << 1);
    #pragma unroll
    for (int i = 0; i < 2; i++) {
        #pragma unroll
        for (int j = 0; j < 8; j++) {
            int c = cbase + j * 8;
            float bx = bias[c], by = bias[c+1];
            #pragma unroll
            for (int half = 0; half < 2; half++) {
                int r = rbase + i * 16 + half * 8;
                float vx = acc[i][j][half*2+0] + bx;
                float vy = acc[i][j][half*2+1] + by;
                if (z == 3) {
                    *(float2*)(outp + (size_t)r * 512 + c) = make_float2(vx, vy);
                } else {
                    __nv_bfloat16* dh = (z == 0) ? g_Qh : (z == 1) ? g_Kh : g_Vh;
                    __nv_bfloat16* dl = (z == 0) ? g_Ql : (z == 1) ? g_Kl : g_Vl;
                    int bb = r >> 10, g = r & 1023;
                    int h = c >> 6, dd = c & 63;
                    size_t idx = (((size_t)(bb << 3) + h) << 16) + (g << 6) + dd;
                    unsigned hp, lp;
                    split2(vx, vy, hp, lp);
                    *(unsigned*)(dh + idx) = hp;
                    *(unsigned*)(dl + idx) = lp;
                }
            }
        }
    }
}

// ================= HMMA flash attention (cp.async double-buffered) ========
// stage layout (51200 B): KH+0, KL+8192, VH+16384, VL+24576, BKT+32768 (pitch 144)
#define AKV 51200
#define ASM_RXY (2*AKV)
#define ATTN_SMEM (2*AKV + 8192)

__global__ __launch_bounds__(256, 2) void attn_mma(
    const float* __restrict__ rpe_x, const float* __restrict__ rpe_y)
{
    extern __shared__ char smc[];
    __nv_bfloat16* rxy = (__nv_bfloat16*)(smc + ASM_RXY);

    int tid = threadIdx.x, wid = tid >> 5, lane = tid & 31;
    int bh = blockIdx.y;
    int b = bh >> 3, hh = bh & 7;
    int q0 = blockIdx.x * 128;
    unsigned smu = smem_u32(smc);

    for (int i = tid; i < 4096; i += 256) {
        int bx = i >> 6, by = i & 63;
        if (bx < 63 && by < 63)
            rxy[i] = __float2bfloat16_rn(rpe_x[bx*8 + hh] + rpe_y[by*8 + hh]);
    }

    int sub = lane >> 3, r8v = lane & 7;
    int r = lane >> 2, c = lane & 3;

    // stage Q (hi then lo) through stage-0 area, extract A-frags
    unsigned qh[4][4], ql[4][4];
    #pragma unroll
    for (int s = 0; s < 2; s++) {
        const __nv_bfloat16* src = s ? g_Ql : g_Qh;
        __syncthreads();
        for (int i = tid; i < 1024; i += 256) {
            int row = i >> 3, cu = i & 7;
            unsigned off = (row << 7) + (cu << 4);
            off ^= (off >> 3) & 0x70;
            *(uint4*)(smc + off) =
                *(const uint4*)(src + ((size_t)(bh << 10) + q0 + row) * 64 + (cu << 3));
        }
        __syncthreads();
        unsigned qrow = (unsigned)(wid << 4) + ((sub & 1) << 3) + r8v;
        unsigned qcb = (sub >> 1) << 4;
        #pragma unroll
        for (int ks = 0; ks < 4; ks++) {
            unsigned off = (qrow << 7) + qcb + (ks << 5);
            off ^= (off >> 3) & 0x70;
            if (s) ldsm4(smu + off, ql[ks][0], ql[ks][1], ql[ks][2], ql[ks][3]);
            else   ldsm4(smu + off, qh[ks][0], qh[ks][1], qh[ks][2], qh[ks][3]);
        }
    }
    __syncthreads();   // Q frags extracted before stage 0 is overwritten

    float o[8][4] = {};
    float m2[2] = {-1e30f, -1e30f};
    float l2[2] = {0.0f, 0.0f};

    const __nv_bfloat16* kh = g_Kh + ((size_t)bh << 10) * 64;
    const __nv_bfloat16* kl = g_Kl + ((size_t)bh << 10) * 64;
    const __nv_bfloat16* vh = g_Vh + ((size_t)bh << 10) * 64;
    const __nv_bfloat16* vl = g_Vl + ((size_t)bh << 10) * 64;
    const unsigned short* bksrc =
        (const unsigned short*)g_bku + (((size_t)(b << 10) + q0) << 10);

    #define ISSUE_A(ti) do {                                                   \
        unsigned st_ = smu + ((ti) & 1) * AKV;                                 \
        int kt_ = (ti) << 6;                                                   \
        _Pragma("unroll")                                                      \
        for (int p = 0; p < 2; p++) {                                          \
            int i_ = tid + (p << 8);                                           \
            int row_ = i_ >> 3, cu_ = i_ & 7;                                  \
            unsigned off_ = (row_ << 7) + (cu_ << 4);                          \
            off_ ^= (off_ >> 3) & 0x70;                                        \
            size_t gs_ = (size_t)(kt_ + row_) * 64 + (cu_ << 3);               \
            cpa16(st_ + off_,         kh + gs_);                               \
            cpa16(st_ + 8192 + off_,  kl + gs_);                               \
            cpa16(st_ + 16384 + off_, vh + gs_);                               \
            cpa16(st_ + 24576 + off_, vl + gs_);                               \
        }                                                                      \
        _Pragma("unroll")                                                      \
        for (int p = 0; p < 4; p++) {                                          \
            int i_ = tid + (p << 8);                                           \
            int row_ = i_ >> 3, cu_ = i_ & 7;                                  \
            cpa16(st_ + 32768 + row_ * 144 + (cu_ << 4),                       \
                  bksrc + ((size_t)row_ << 10) + kt_ + (cu_ << 3));            \
        }                                                                      \
        asm volatile("cp.async.commit_group;");                                \
    } while (0)

    ISSUE_A(0);

    for (int ti = 0; ti < 16; ti++) {
        if (ti < 15) {
            ISSUE_A(ti + 1);
            asm volatile("cp.async.wait_group 1;");
        } else {
            asm volatile("cp.async.wait_group 0;");
        }
        __syncthreads();

        unsigned stb = smu + (ti & 1) * AKV;
        char*    stc = smc + (ti & 1) * AKV;

        // ---- S = Q K^T (3 split passes) ----
        float S[8][4] = {};
        #pragma unroll
        for (int ks = 0; ks < 4; ks++) {
            unsigned bf[8][2];
            #pragma unroll
            for (int t = 0; t < 4; t++) {
                unsigned krow = (t << 4) + ((sub & 1) << 3) + r8v;
                unsigned off = (krow << 7) + ((sub >> 1) << 4) + (ks << 5);
                off ^= (off >> 3) & 0x70;
                unsigned r0, r1, r2, r3;
                ldsm4(stb + off, r0, r1, r2, r3);
                bf[t*2+0][0] = r0; bf[t*2+0][1] = r2;
                bf[t*2+1][0] = r1; bf[t*2+1][1] = r3;
            }
            #pragma unroll
            for (int n = 0; n < 8; n++) {
                mma16816(S[n], qh[ks], bf[n]);
                mma16816(S[n], ql[ks], bf[n]);
            }
        }
        #pragma unroll
        for (int ks = 0; ks < 4; ks++) {
            unsigned bf[8][2];
            #pragma unroll
            for (int t = 0; t < 4; t++) {
                unsigned krow = (t << 4) + ((sub & 1) << 3) + r8v;
                unsigned off = (krow << 7) + ((sub >> 1) << 4) + (ks << 5);
                off ^= (off >> 3) & 0x70;
                unsigned r0, r1, r2, r3;
                ldsm4(stb + 8192 + off, r0, r1, r2, r3);
                bf[t*2+0][0] = r0; bf[t*2+0][1] = r2;
                bf[t*2+1][0] = r1; bf[t*2+1][1] = r3;
            }
            #pragma unroll
            for (int n = 0; n < 8; n++)
                mma16816(S[n], qh[ks], bf[n]);
        }

        // ---- bias + online softmax, pack P hi/lo as A-frags ----
        unsigned pAh[4][4], pAl[4][4];
        #pragma unroll
        for (int h = 0; h < 2; h++) {
            int rowq = (wid << 4) + r + (h << 3);
            const unsigned* brow = (const unsigned*)(stc + 32768 + rowq * 144) + c;
            float rm = -1e30f;
            #pragma unroll
            for (int j = 0; j < 8; j++) {
                unsigned w = brow[j << 2];
                unsigned k0 = w & 0xffffu, k1 = w >> 16;
                float s0 = (k0 & 0x8000u) ? -1e30f
                         : fmaf(S[j][h*2+0], 0.125f,
                                __bfloat162float(rxy[k0 & 0xfffu]));
                float s1 = (k1 & 0x8000u) ? -1e30f
                         : fmaf(S[j][h*2+1], 0.125f,
                                __bfloat162float(rxy[k1 & 0xfffu]));
                S[j][h*2+0] = s0; S[j][h*2+1] = s1;
                rm = fmaxf(rm, fmaxf(s0, s1));
            }
            rm = fmaxf(rm, __shfl_xor_sync(0xffffffffu, rm, 1));
            rm = fmaxf(rm, __shfl_xor_sync(0xffffffffu, rm, 2));
            float mn = fmaxf(m2[h], rm);
            float corr = __expf(m2[h] - mn);
            m2[h] = mn;
            float rs = 0.0f;
            #pragma unroll
            for (int j = 0; j < 8; j++) {
                float p0 = __expf(S[j][h*2+0] - mn);
                float p1 = __expf(S[j][h*2+1] - mn);
                rs += p0 + p1;
                unsigned hp, lp;
                split2(p0, p1, hp, lp);
                pAh[j >> 1][(j & 1) * 2 + h] = hp;
                pAl[j >> 1][(j & 1) * 2 + h] = lp;
            }
            l2[h] = l2[h] * corr + rs;
            #pragma unroll
            for (int n = 0; n < 8; n++) {
                o[n][h*2+0] *= corr;
                o[n][h*2+1] *= corr;
            }
        }

        // ---- O += P V (3 split passes, V via trans ldmatrix) ----
        int krowv = (lane & 15);
        int dby = ((lane >> 4) << 4);
        #pragma unroll
        for (int jj = 0; jj < 4; jj++) {
            unsigned bf[8][2];
            #pragma unroll
            for (int t = 0; t < 4; t++) {
                unsigned off = (((jj << 4) + krowv) << 7) + (t << 5) + dby;
                off ^= (off >> 3) & 0x70;
                unsigned r0, r1, r2, r3;
                ldsm4t(stb + 16384 + off, r0, r1, r2, r3);
                bf[t*2+0][0] = r0; bf[t*2+0][1] = r1;
                bf[t*2+1][0] = r2; bf[t*2+1][1] = r3;
            }
            #pragma unroll
            for (int n = 0; n < 8; n++) {
                mma16816(o[n], pAh[jj], bf[n]);
                mma16816(o[n], pAl[jj], bf[n]);
            }
        }
        #pragma unroll
        for (int jj = 0; jj < 4; jj++) {
            unsigned bf[8][2];
            #pragma unroll
            for (int t = 0; t < 4; t++) {
                unsigned off = (((jj << 4) + krowv) << 7) + (t << 5) + dby;
                off ^= (off >> 3) & 0x70;
                unsigned r0, r1, r2, r3;
                ldsm4t(stb + 24576 + off, r0, r1, r2, r3);
                bf[t*2+0][0] = r0; bf[t*2+0][1] = r1;
                bf[t*2+1][0] = r2; bf[t*2+1][1] = r3;
            }
            #pragma unroll
            for (int n = 0; n < 8; n++)
                mma16816(o[n], pAh[jj], bf[n]);
        }
        __syncthreads();   // stage consumed; safe to overwrite next iteration
    }

    #pragma unroll
    for (int h = 0; h < 2; h++) {
        float ls = l2[h];
        ls += __shfl_xor_sync(0xffffffffu, ls, 1);
        ls += __shfl_xor_sync(0xffffffffu, ls, 2);
        float inv = 1.0f / ls;
        int q = q0 + (wid << 4) + r + (h << 3);
        size_t base = 3*(size_t)MK + ((size_t)((b << 10) + q)) * 512 + hh * 64 + (c << 1);
        #pragma unroll
        for (int j = 0; j < 8; j++) {
            float f0 = o[j][h*2+0] * inv;
            float f1 = o[j][h*2+1] * inv;
            unsigned hp, lp;
            split2(f0, f1, hp, lp);
            *(unsigned*)(g_Ah + base + (j << 3)) = hp;
            *(unsigned*)(g_Al + base + (j << 3)) = lp;
        }
    }
}

// ================= launch =================
extern "C" void kernel_launch(void* const* d_in, const int* in_sizes, int n_in,
                              void* d_out, int out_size) {
    const float* query  = (const float*)d_in[0];
    const float* key    = (const float*)d_in[1];
    const float* value  = (const float*)d_in[2];
    const float* coords = (const float*)d_in[3];
    const int*   mask   = (const int*)  d_in[4];
    const float* Wq = (const float*)d_in[5];
    const float* bq = (const float*)d_in[6];
    const float* Wk = (const float*)d_in[7];
    const float* bk = (const float*)d_in[8];
    const float* Wv = (const float*)d_in[9];
    const float* bv = (const float*)d_in[10];
    const float* Wo = (const float*)d_in[11];
    const float* bo = (const float*)d_in[12];
    const float* rpe_x = (const float*)d_in[13];
    const float* rpe_y = (const float*)d_in[14];
    float* out = (float*)d_out;

    cudaFuncSetAttribute(attn_mma,
                         cudaFuncAttributeMaxDynamicSharedMemorySize, ATTN_SMEM);
    cudaFuncSetAttribute(mma_gemm,
                         cudaFuncAttributeMaxDynamicSharedMemorySize, GEMM_DSMEM);

    convert_x<<<(3*MK/4)/256, 256>>>(query, key, value);
    convert_w<<<(4*WK/4)/256, 256>>>(Wq, Wk, Wv, Wo);
    bucket_kernel<<<(B_*G_*G_/2)/256, 256>>>(coords, mask);

    mma_gemm<<<dim3(4, 32, 3), 256, GEMM_DSMEM>>>(bq, bk, bv, bo, out, 0);

    attn_mma<<<dim3(8, 32), 256, ATTN_SMEM>>>(rpe_x, rpe_y);

    mma_gemm<<<dim3(4, 32, 1), 256, GEMM_DSMEM>>>(bq, bk, bv, bo, out, 3);
}

// round 8
// speedup vs baseline: 4.2588x; 1.0373x over previous
#include <cuda_runtime.h>
#include <cuda_bf16.h>
#include <math.h>

#define B_  4
#define G_  1024
#define D_  512
#define H_  8
#define DH  64
#define MK  (4096*512)
#define WK  (512*512)

// ---- scratch (device globals: allocation-free rule) ----
__device__ unsigned g_bku[B_*G_*G_/2];                 // packed u16 buckets (2 per u32)
__device__ __align__(16) __nv_bfloat16 g_Qh[B_*H_*G_*DH], g_Ql[B_*H_*G_*DH];
__device__ __align__(16) __nv_bfloat16 g_Kh[B_*H_*G_*DH], g_Kl[B_*H_*G_*DH];
__device__ __align__(16) __nv_bfloat16 g_Vh[B_*H_*G_*DH], g_Vl[B_*H_*G_*DH];
__device__ __align__(16) __nv_bfloat16 g_Ah[4*MK];
__device__ __align__(16) __nv_bfloat16 g_Al[4*MK];
__device__ __align__(16) __nv_bfloat16 g_Wh[4*WK];
__device__ __align__(16) __nv_bfloat16 g_Wl[4*WK];

__device__ __forceinline__ unsigned smem_u32(const void* p) {
    unsigned r;
    asm("{ .reg .u64 t; cvta.to.shared.u64 t, %1; cvt.u32.u64 %0, t; }"
        : "=r"(r) : "l"(p));
    return r;
}
__device__ __forceinline__ void split2(float a, float b, unsigned& hp, unsigned& lp) {
    __nv_bfloat162 h = __floats2bfloat162_rn(a, b);
    float ra = a - __bfloat162float(h.x);
    float rb = b - __bfloat162float(h.y);
    __nv_bfloat162 l = __floats2bfloat162_rn(ra, rb);
    hp = *(unsigned*)&h;
    lp = *(unsigned*)&l;
}
__device__ __forceinline__ void cpa16(unsigned saddr, const void* g) {
    asm volatile("cp.async.cg.shared.global [%0], [%1], 16;"
                 :: "r"(saddr), "l"(g));
}

// ================= fused prep: converts + bucket =================
__device__ __forceinline__ int rpb(float d) {
    float ad = fabsf(d);
    int li;
    if (ad >= 128.0f) {
        li = 7;
    } else {
        float n = fmaxf(ad, 1e-6f);
        li = (int)floorf(__log2f(n));
        li = max(0, min(li, 31));
    }
    return d > 0.0f ? 31 + li : (d < 0.0f ? 31 - li : 31);
}

// blocks [0,6144): convert_x   [6144,7168): convert_w   [7168,15360): bucket
__global__ void prep_kernel(
    const float* __restrict__ q, const float* __restrict__ k,
    const float* __restrict__ v,
    const float* __restrict__ wq, const float* __restrict__ wk,
    const float* __restrict__ wv, const float* __restrict__ wo,
    const float* __restrict__ coords, const int* __restrict__ mask)
{
    int bid = blockIdx.x;
    if (bid < 6144) {
        int i = bid * 256 + threadIdx.x;
        int e = i << 2;
        int z = e / MK;
        int r = e - z * MK;
        const float* src = (z == 0) ? q : (z == 1) ? k : v;
        float4 x = *(const float4*)(src + r);
        unsigned hp0, lp0, hp1, lp1;
        split2(x.x, x.y, hp0, lp0);
        split2(x.z, x.w, hp1, lp1);
        *(uint2*)(g_Ah + e) = make_uint2(hp0, hp1);
        *(uint2*)(g_Al + e) = make_uint2(lp0, lp1);
    } else if (bid < 7168) {
        int i = (bid - 6144) * 256 + threadIdx.x;
        int e = i << 2;
        int z = e >> 18;
        int r = e & (WK - 1);
        const float* src = (z == 0) ? wq : (z == 1) ? wk : (z == 2) ? wv : wo;
        float4 x = *(const float4*)(src + r);
        unsigned hp0, lp0, hp1, lp1;
        split2(x.x, x.y, hp0, lp0);
        split2(x.z, x.w, hp1, lp1);
        *(uint2*)(g_Wh + e) = make_uint2(hp0, hp1);
        *(uint2*)(g_Wl + e) = make_uint2(lp0, lp1);
    } else {
        int i = (bid - 7168) * 256 + threadIdx.x;
        int idx = i << 1;
        int kk = idx & (G_-1);
        int qq = (idx >> 10) & (G_-1);
        int b = idx >> 20;
        float2 cq  = ((const float2*)coords)[b*G_ + qq];
        float2 ck0 = ((const float2*)coords)[b*G_ + kk];
        float2 ck1 = ((const float2*)coords)[b*G_ + kk + 1];
        unsigned v0 = ((unsigned)rpb(cq.x - ck0.x) << 6) | (unsigned)rpb(cq.y - ck0.y);
        unsigned v1 = ((unsigned)rpb(cq.x - ck1.x) << 6) | (unsigned)rpb(cq.y - ck1.y);
        if (mask[b*G_ + kk]     == 0) v0 |= 0x8000u;
        if (mask[b*G_ + kk + 1] == 0) v1 |= 0x8000u;
        g_bku[i] = v0 | (v1 << 16);
    }
}

// ================= HMMA primitives =================
__device__ __forceinline__ void ldsm4(unsigned addr, unsigned& r0, unsigned& r1,
                                      unsigned& r2, unsigned& r3) {
    asm volatile("ldmatrix.sync.aligned.m8n8.x4.shared.b16 {%0,%1,%2,%3}, [%4];"
                 : "=r"(r0), "=r"(r1), "=r"(r2), "=r"(r3) : "r"(addr));
}
__device__ __forceinline__ void ldsm4t(unsigned addr, unsigned& r0, unsigned& r1,
                                       unsigned& r2, unsigned& r3) {
    asm volatile("ldmatrix.sync.aligned.m8n8.x4.trans.shared.b16 {%0,%1,%2,%3}, [%4];"
                 : "=r"(r0), "=r"(r1), "=r"(r2), "=r"(r3) : "r"(addr));
}
__device__ __forceinline__ void mma16816(float* d, const unsigned* a,
                                         const unsigned* b) {
    asm volatile(
        "mma.sync.aligned.m16n8k16.row.col.f32.bf16.bf16.f32 "
        "{%0,%1,%2,%3}, {%4,%5,%6,%7}, {%8,%9}, {%0,%1,%2,%3};"
        : "+f"(d[0]), "+f"(d[1]), "+f"(d[2]), "+f"(d[3])
        : "r"(a[0]), "r"(a[1]), "r"(a[2]), "r"(a[3]), "r"(b[0]), "r"(b[1]));
}

// ================= QKV GEMM: 128x128 tile, cp.async 3-stage ====
#define STAGE 32768
#define GEMM_DSMEM (3*STAGE + 1024)

__global__ __launch_bounds__(256, 2) void mma_gemm(
    const float* __restrict__ bq, const float* __restrict__ bk,
    const float* __restrict__ bv)
{
    extern __shared__ char smd[];

    int z = blockIdx.z;
    const __nv_bfloat16* Ah = g_Ah + (size_t)z * MK;
    const __nv_bfloat16* Al = g_Al + (size_t)z * MK;
    const __nv_bfloat16* Bh = g_Wh + (size_t)z * WK;
    const __nv_bfloat16* Bl = g_Wl + (size_t)z * WK;
    const float* bias = (z == 0) ? bq : (z == 1) ? bk : bv;

    int tid = threadIdx.x, wid = tid >> 5, lane = tid & 31;
    int m0 = blockIdx.y * 128;
    int n0 = blockIdx.x * 128;
    int wm = wid >> 1, wn = wid & 1;         // warp tile: 32m x 64n

    unsigned raw = smem_u32(smd);
    unsigned base = (raw + 1023u) & ~1023u;

    int sub = lane >> 3, r8 = lane & 7;
    int a_row = wm * 32 + ((sub & 1) << 3) + r8;
    int b_row = wn * 64 + ((sub & 1) << 3) + r8;
    int colb  = (sub >> 1) << 4;
    int grow = tid >> 3, gcu = tid & 7;

    unsigned soff[4];
    #pragma unroll
    for (int t = 0; t < 4; t++) {
        unsigned off = ((grow + t*32) << 7) + (gcu << 4);
        soff[t] = off ^ ((off >> 3) & 0x70);
    }

    float acc[2][8][4] = {};

    #define ISSUE(c) do {                                                      \
        int p_ = (c) >> 3, k0_ = ((c) & 7) << 6;                               \
        const __nv_bfloat16* As_ = (p_ == 1) ? Al : Ah;                        \
        const __nv_bfloat16* Bs_ = (p_ == 2) ? Bl : Bh;                        \
        unsigned st_ = base + ((c) % 3) * STAGE;                               \
        _Pragma("unroll")                                                      \
        for (int t = 0; t < 4; t++)                                            \
            cpa16(st_ + soff[t],                                               \
                  As_ + (size_t)(m0 + grow + t*32) * 512 + k0_ + (gcu << 3));  \
        _Pragma("unroll")                                                      \
        for (int t = 0; t < 4; t++)                                            \
            cpa16(st_ + 16384 + soff[t],                                       \
                  Bs_ + (size_t)(n0 + grow + t*32) * 512 + k0_ + (gcu << 3));  \
        asm volatile("cp.async.commit_group;");                                \
    } while (0)

    ISSUE(0);
    ISSUE(1);

    for (int c = 0; c < 24; c++) {
        if (c < 23) asm volatile("cp.async.wait_group 1;");
        else        asm volatile("cp.async.wait_group 0;");
        __syncthreads();
        if (c + 2 < 24) ISSUE(c + 2);

        unsigned sa_u = base + (c % 3) * STAGE;
        unsigned sb_u = sa_u + 16384;

        #pragma unroll
        for (int ks = 0; ks < 4; ks++) {
            unsigned a[2][4], bf[8][2];
            #pragma unroll
            for (int i = 0; i < 2; i++) {
                unsigned off = ((a_row + i*16) << 7) + colb + (ks << 5);
                off ^= (off >> 3) & 0x70;
                ldsm4(sa_u + off, a[i][0], a[i][1], a[i][2], a[i][3]);
            }
            #pragma unroll
            for (int jj = 0; jj < 4; jj++) {
                unsigned off = ((b_row + jj*16) << 7) + colb + (ks << 5);
                off ^= (off >> 3) & 0x70;
                unsigned r0, r1, r2, r3;
                ldsm4(sb_u + off, r0, r1, r2, r3);
                bf[jj*2+0][0] = r0; bf[jj*2+0][1] = r2;
                bf[jj*2+1][0] = r1; bf[jj*2+1][1] = r3;
            }
            #pragma unroll
            for (int i = 0; i < 2; i++)
                #pragma unroll
                for (int j = 0; j < 8; j++)
                    mma16816(acc[i][j], a[i], bf[j]);
        }
    }

    int rbase = m0 + wm * 32 + (lane >> 2);
    int cbase = n0 + wn * 64 + ((lane & 3) << 1);
    #pragma unroll
    for (int i = 0; i < 2; i++) {
        #pragma unroll
        for (int j = 0; j < 8; j++) {
            int c = cbase + j * 8;
            float bx = bias[c], by = bias[c+1];
            #pragma unroll
            for (int half = 0; half < 2; half++) {
                int r = rbase + i * 16 + half * 8;
                float vx = acc[i][j][half*2+0] + bx;
                float vy = acc[i][j][half*2+1] + by;
                __nv_bfloat16* dh = (z == 0) ? g_Qh : (z == 1) ? g_Kh : g_Vh;
                __nv_bfloat16* dl = (z == 0) ? g_Ql : (z == 1) ? g_Kl : g_Vl;
                int bb = r >> 10, g = r & 1023;
                int h = c >> 6, dd = c & 63;
                size_t idx = (((size_t)(bb << 3) + h) << 16) + (g << 6) + dd;
                unsigned hp, lp;
                split2(vx, vy, hp, lp);
                *(unsigned*)(dh + idx) = hp;
                *(unsigned*)(dl + idx) = lp;
            }
        }
    }
}

// ================= out-proj GEMM: 128x64 tile, cp.async 3-stage ====
#define OSTAGE 24576
#define OGEMM_DSMEM (3*OSTAGE + 1024)

__global__ __launch_bounds__(256, 2) void out_gemm(
    const float* __restrict__ bo, float* __restrict__ outp)
{
    extern __shared__ char smd[];

    const __nv_bfloat16* Ah = g_Ah + 3*(size_t)MK;
    const __nv_bfloat16* Al = g_Al + 3*(size_t)MK;
    const __nv_bfloat16* Bh = g_Wh + 3*(size_t)WK;
    const __nv_bfloat16* Bl = g_Wl + 3*(size_t)WK;

    int tid = threadIdx.x, wid = tid >> 5, lane = tid & 31;
    int m0 = blockIdx.y * 128;
    int n0 = blockIdx.x * 64;
    int wm = wid >> 1, wn = wid & 1;       // warp tile 32m x 32n

    unsigned raw = smem_u32(smd);
    unsigned base = (raw + 1023u) & ~1023u;

    int sub = lane >> 3, r8 = lane & 7;
    int a_row = wm * 32 + ((sub & 1) << 3) + r8;
    int b_row = wn * 32 + ((sub & 1) << 3) + r8;
    int colb  = (sub >> 1) << 4;
    int grow = tid >> 3, gcu = tid & 7;

    unsigned soff[4];
    #pragma unroll
    for (int t = 0; t < 4; t++) {
        unsigned off = ((grow + t*32) << 7) + (gcu << 4);
        soff[t] = off ^ ((off >> 3) & 0x70);
    }

    float acc[2][4][4] = {};

    #define OISSUE(c) do {                                                     \
        int p_ = (c) >> 3, k0_ = ((c) & 7) << 6;                               \
        const __nv_bfloat16* As_ = (p_ == 1) ? Al : Ah;                        \
        const __nv_bfloat16* Bs_ = (p_ == 2) ? Bl : Bh;                        \
        unsigned st_ = base + ((c) % 3) * OSTAGE;                              \
        _Pragma("unroll")                                                      \
        for (int t = 0; t < 4; t++)                                            \
            cpa16(st_ + soff[t],                                               \
                  As_ + (size_t)(m0 + grow + t*32) * 512 + k0_ + (gcu << 3));  \
        _Pragma("unroll")                                                      \
        for (int t = 0; t < 2; t++)                                            \
            cpa16(st_ + 16384 + soff[t],                                       \
                  Bs_ + (size_t)(n0 + grow + t*32) * 512 + k0_ + (gcu << 3));  \
        asm volatile("cp.async.commit_group;");                                \
    } while (0)

    OISSUE(0);
    OISSUE(1);

    for (int c = 0; c < 24; c++) {
        if (c < 23) asm volatile("cp.async.wait_group 1;");
        else        asm volatile("cp.async.wait_group 0;");
        __syncthreads();
        if (c + 2 < 24) OISSUE(c + 2);

        unsigned sa_u = base + (c % 3) * OSTAGE;
        unsigned sb_u = sa_u + 16384;

        #pragma unroll
        for (int ks = 0; ks < 4; ks++) {
            unsigned a[2][4], bf[4][2];
            #pragma unroll
            for (int i = 0; i < 2; i++) {
                unsigned off = ((a_row + i*16) << 7) + colb + (ks << 5);
                off ^= (off >> 3) & 0x70;
                ldsm4(sa_u + off, a[i][0], a[i][1], a[i][2], a[i][3]);
            }
            #pragma unroll
            for (int jj = 0; jj < 2; jj++) {
                unsigned off = ((b_row + jj*16) << 7) + colb + (ks << 5);
                off ^= (off >> 3) & 0x70;
                unsigned r0, r1, r2, r3;
                ldsm4(sb_u + off, r0, r1, r2, r3);
                bf[jj*2+0][0] = r0; bf[jj*2+0][1] = r2;
                bf[jj*2+1][0] = r1; bf[jj*2+1][1] = r3;
            }
            #pragma unroll
            for (int i = 0; i < 2; i++)
                #pragma unroll
                for (int j = 0; j < 4; j++)
                    mma16816(acc[i][j], a[i], bf[j]);
        }
    }

    int rbase = m0 + wm * 32 + (lane >> 2);
    int cbase = n0 + wn * 32 + ((lane & 3) << 1);
    #pragma unroll
    for (int i = 0; i < 2; i++) {
        #pragma unroll
        for (int j = 0; j < 4; j++) {
            int c = cbase + j * 8;
            float bx = bo[c], by = bo[c+1];
            #pragma unroll
            for (int half = 0; half < 2; half++) {
                int r = rbase + i * 16 + half * 8;
                *(float2*)(outp + (size_t)r * 512 + c) =
                    make_float2(acc[i][j][half*2+0] + bx,
                                acc[i][j][half*2+1] + by);
            }
        }
    }
}

// ================= HMMA flash attention (cp.async double-buffered) ========
#define AKV 51200
#define ASM_RXY (2*AKV)
#define ATTN_SMEM (2*AKV + 8192)

__global__ __launch_bounds__(256, 2) void attn_mma(
    const float* __restrict__ rpe_x, const float* __restrict__ rpe_y)
{
    extern __shared__ char smc[];
    __nv_bfloat16* rxy = (__nv_bfloat16*)(smc + ASM_RXY);

    int tid = threadIdx.x, wid = tid >> 5, lane = tid & 31;
    int bh = blockIdx.y;
    int b = bh >> 3, hh = bh & 7;
    int q0 = blockIdx.x * 128;
    unsigned smu = smem_u32(smc);

    for (int i = tid; i < 4096; i += 256) {
        int bx = i >> 6, by = i & 63;
        if (bx < 63 && by < 63)
            rxy[i] = __float2bfloat16_rn(rpe_x[bx*8 + hh] + rpe_y[by*8 + hh]);
    }

    int sub = lane >> 3, r8v = lane & 7;
    int r = lane >> 2, c = lane & 3;

    unsigned qh[4][4], ql[4][4];
    #pragma unroll
    for (int s = 0; s < 2; s++) {
        const __nv_bfloat16* src = s ? g_Ql : g_Qh;
        __syncthreads();
        for (int i = tid; i < 1024; i += 256) {
            int row = i >> 3, cu = i & 7;
            unsigned off = (row << 7) + (cu << 4);
            off ^= (off >> 3) & 0x70;
            *(uint4*)(smc + off) =
                *(const uint4*)(src + ((size_t)(bh << 10) + q0 + row) * 64 + (cu << 3));
        }
        __syncthreads();
        unsigned qrow = (unsigned)(wid << 4) + ((sub & 1) << 3) + r8v;
        unsigned qcb = (sub >> 1) << 4;
        #pragma unroll
        for (int ks = 0; ks < 4; ks++) {
            unsigned off = (qrow << 7) + qcb + (ks << 5);
            off ^= (off >> 3) & 0x70;
            if (s) ldsm4(smu + off, ql[ks][0], ql[ks][1], ql[ks][2], ql[ks][3]);
            else   ldsm4(smu + off, qh[ks][0], qh[ks][1], qh[ks][2], qh[ks][3]);
        }
    }
    __syncthreads();

    float o[8][4] = {};
    float m2[2] = {-1e30f, -1e30f};
    float l2[2] = {0.0f, 0.0f};

    const __nv_bfloat16* kh = g_Kh + ((size_t)bh << 10) * 64;
    const __nv_bfloat16* kl = g_Kl + ((size_t)bh << 10) * 64;
    const __nv_bfloat16* vh = g_Vh + ((size_t)bh << 10) * 64;
    const __nv_bfloat16* vl = g_Vl + ((size_t)bh << 10) * 64;
    const unsigned short* bksrc =
        (const unsigned short*)g_bku + (((size_t)(b << 10) + q0) << 10);

    #define ISSUE_A(ti) do {                                                   \
        unsigned st_ = smu + ((ti) & 1) * AKV;                                 \
        int kt_ = (ti) << 6;                                                   \
        _Pragma("unroll")                                                      \
        for (int p = 0; p < 2; p++) {                                          \
            int i_ = tid + (p << 8);                                           \
            int row_ = i_ >> 3, cu_ = i_ & 7;                                  \
            unsigned off_ = (row_ << 7) + (cu_ << 4);                          \
            off_ ^= (off_ >> 3) & 0x70;                                        \
            size_t gs_ = (size_t)(kt_ + row_) * 64 + (cu_ << 3);               \
            cpa16(st_ + off_,         kh + gs_);                               \
            cpa16(st_ + 8192 + off_,  kl + gs_);                               \
            cpa16(st_ + 16384 + off_, vh + gs_);                               \
            cpa16(st_ + 24576 + off_, vl + gs_);                               \
        }                                                                      \
        _Pragma("unroll")                                                      \
        for (int p = 0; p < 4; p++) {                                          \
            int i_ = tid + (p << 8);                                           \
            int row_ = i_ >> 3, cu_ = i_ & 7;                                  \
            cpa16(st_ + 32768 + row_ * 144 + (cu_ << 4),                       \
                  bksrc + ((size_t)row_ << 10) + kt_ + (cu_ << 3));            \
        }                                                                      \
        asm volatile("cp.async.commit_group;");                                \
    } while (0)

    ISSUE_A(0);

    for (int ti = 0; ti < 16; ti++) {
        if (ti < 15) {
            ISSUE_A(ti + 1);
            asm volatile("cp.async.wait_group 1;");
        } else {
            asm volatile("cp.async.wait_group 0;");
        }
        __syncthreads();

        unsigned stb = smu + (ti & 1) * AKV;
        char*    stc = smc + (ti & 1) * AKV;

        float S[8][4] = {};
        #pragma unroll
        for (int ks = 0; ks < 4; ks++) {
            unsigned bf[8][2];
            #pragma unroll
            for (int t = 0; t < 4; t++) {
                unsigned krow = (t << 4) + ((sub & 1) << 3) + r8v;
                unsigned off = (krow << 7) + ((sub >> 1) << 4) + (ks << 5);
                off ^= (off >> 3) & 0x70;
                unsigned r0, r1, r2, r3;
                ldsm4(stb + off, r0, r1, r2, r3);
                bf[t*2+0][0] = r0; bf[t*2+0][1] = r2;
                bf[t*2+1][0] = r1; bf[t*2+1][1] = r3;
            }
            #pragma unroll
            for (int n = 0; n < 8; n++) {
                mma16816(S[n], qh[ks], bf[n]);
                mma16816(S[n], ql[ks], bf[n]);
            }
        }
        #pragma unroll
        for (int ks = 0; ks < 4; ks++) {
            unsigned bf[8][2];
            #pragma unroll
            for (int t = 0; t < 4; t++) {
                unsigned krow = (t << 4) + ((sub & 1) << 3) + r8v;
                unsigned off = (krow << 7) + ((sub >> 1) << 4) + (ks << 5);
                off ^= (off >> 3) & 0x70;
                unsigned r0, r1, r2, r3;
                ldsm4(stb + 8192 + off, r0, r1, r2, r3);
                bf[t*2+0][0] = r0; bf[t*2+0][1] = r2;
                bf[t*2+1][0] = r1; bf[t*2+1][1] = r3;
            }
            #pragma unroll
            for (int n = 0; n < 8; n++)
                mma16816(S[n], qh[ks], bf[n]);
        }

        unsigned pAh[4][4], pAl[4][4];
        #pragma unroll
        for (int h = 0; h < 2; h++) {
            int rowq = (wid << 4) + r + (h << 3);
            const unsigned* brow = (const unsigned*)(stc + 32768 + rowq * 144) + c;
            float rm = -1e30f;
            #pragma unroll
            for (int j = 0; j < 8; j++) {
                unsigned w = brow[j << 2];
                unsigned k0 = w & 0xffffu, k1 = w >> 16;
                float s0 = (k0 & 0x8000u) ? -1e30f
                         : fmaf(S[j][h*2+0], 0.125f,
                                __bfloat162float(rxy[k0 & 0xfffu]));
                float s1 = (k1 & 0x8000u) ? -1e30f
                         : fmaf(S[j][h*2+1], 0.125f,
                                __bfloat162float(rxy[k1 & 0xfffu]));
                S[j][h*2+0] = s0; S[j][h*2+1] = s1;
                rm = fmaxf(rm, fmaxf(s0, s1));
            }
            rm = fmaxf(rm, __shfl_xor_sync(0xffffffffu, rm, 1));
            rm = fmaxf(rm, __shfl_xor_sync(0xffffffffu, rm, 2));
            float mn = fmaxf(m2[h], rm);
            float corr = __expf(m2[h] - mn);
            m2[h] = mn;
            float rs = 0.0f;
            #pragma unroll
            for (int j = 0; j < 8; j++) {
                float p0 = __expf(S[j][h*2+0] - mn);
                float p1 = __expf(S[j][h*2+1] - mn);
                rs += p0 + p1;
                unsigned hp, lp;
                split2(p0, p1, hp, lp);
                pAh[j >> 1][(j & 1) * 2 + h] = hp;
                pAl[j >> 1][(j & 1) * 2 + h] = lp;
            }
            l2[h] = l2[h] * corr + rs;
            #pragma unroll
            for (int n = 0; n < 8; n++) {
                o[n][h*2+0] *= corr;
                o[n][h*2+1] *= corr;
            }
        }

        int krowv = (lane & 15);
        int dby = ((lane >> 4) << 4);
        #pragma unroll
        for (int jj = 0; jj < 4; jj++) {
            unsigned bf[8][2];
            #pragma unroll
            for (int t = 0; t < 4; t++) {
                unsigned off = (((jj << 4) + krowv) << 7) + (t << 5) + dby;
                off ^= (off >> 3) & 0x70;
                unsigned r0, r1, r2, r3;
                ldsm4t(stb + 16384 + off, r0, r1, r2, r3);
                bf[t*2+0][0] = r0; bf[t*2+0][1] = r1;
                bf[t*2+1][0] = r2; bf[t*2+1][1] = r3;
            }
            #pragma unroll
            for (int n = 0; n < 8; n++) {
                mma16816(o[n], pAh[jj], bf[n]);
                mma16816(o[n], pAl[jj], bf[n]);
            }
        }
        #pragma unroll
        for (int jj = 0; jj < 4; jj++) {
            unsigned bf[8][2];
            #pragma unroll
            for (int t = 0; t < 4; t++) {
                unsigned off = (((jj << 4) + krowv) << 7) + (t << 5) + dby;
                off ^= (off >> 3) & 0x70;
                unsigned r0, r1, r2, r3;
                ldsm4t(stb + 24576 + off, r0, r1, r2, r3);
                bf[t*2+0][0] = r0; bf[t*2+0][1] = r1;
                bf[t*2+1][0] = r2; bf[t*2+1][1] = r3;
            }
            #pragma unroll
            for (int n = 0; n < 8; n++)
                mma16816(o[n], pAh[jj], bf[n]);
        }
        __syncthreads();
    }

    #pragma unroll
    for (int h = 0; h < 2; h++) {
        float ls = l2[h];
        ls += __shfl_xor_sync(0xffffffffu, ls, 1);
        ls += __shfl_xor_sync(0xffffffffu, ls, 2);
        float inv = 1.0f / ls;
        int q = q0 + (wid << 4) + r + (h << 3);
        size_t base = 3*(size_t)MK + ((size_t)((b << 10) + q)) * 512 + hh * 64 + (c << 1);
        #pragma unroll
        for (int j = 0; j < 8; j++) {
            float f0 = o[j][h*2+0] * inv;
            float f1 = o[j][h*2+1] * inv;
            unsigned hp, lp;
            split2(f0, f1, hp, lp);
            *(unsigned*)(g_Ah + base + (j << 3)) = hp;
            *(unsigned*)(g_Al + base + (j << 3)) = lp;
        }
    }
}

// ================= launch =================
extern "C" void kernel_launch(void* const* d_in, const int* in_sizes, int n_in,
                              void* d_out, int out_size) {
    const float* query  = (const float*)d_in[0];
    const float* key    = (const float*)d_in[1];
    const float* value  = (const float*)d_in[2];
    const float* coords = (const float*)d_in[3];
    const int*   mask   = (const int*)  d_in[4];
    const float* Wq = (const float*)d_in[5];
    const float* bq = (const float*)d_in[6];
    const float* Wk = (const float*)d_in[7];
    const float* bk = (const float*)d_in[8];
    const float* Wv = (const float*)d_in[9];
    const float* bv = (const float*)d_in[10];
    const float* Wo = (const float*)d_in[11];
    const float* bo = (const float*)d_in[12];
    const float* rpe_x = (const float*)d_in[13];
    const float* rpe_y = (const float*)d_in[14];
    float* out = (float*)d_out;

    cudaFuncSetAttribute(attn_mma,
                         cudaFuncAttributeMaxDynamicSharedMemorySize, ATTN_SMEM);
    cudaFuncSetAttribute(mma_gemm,
                         cudaFuncAttributeMaxDynamicSharedMemorySize, GEMM_DSMEM);
    cudaFuncSetAttribute(out_gemm,
                         cudaFuncAttributeMaxDynamicSharedMemorySize, OGEMM_DSMEM);

    prep_kernel<<<15360, 256>>>(query, key, value, Wq, Wk, Wv, Wo, coords, mask);

    mma_gemm<<<dim3(4, 32, 3), 256, GEMM_DSMEM>>>(bq, bk, bv);

    attn_mma<<<dim3(8, 32), 256, ATTN_SMEM>>>(rpe_x, rpe_y);

    out_gemm<<<dim3(8, 32), 256, OGEMM_DSMEM>>>(bo, out);
}

// round 9
// speedup vs baseline: 4.8285x; 1.1338x over previous
#include <cuda_runtime.h>
#include <cuda_bf16.h>
#include <cuda_fp16.h>
#include <math.h>

#define B_  4
#define G_  1024
#define D_  512
#define H_  8
#define DH  64
#define MK  (4096*512)
#define WK  (512*512)

// ---- scratch (device globals: allocation-free rule) ----
__device__ unsigned g_bku[B_*G_*G_/2];                 // packed u16 buckets (2 per u32)
__device__ __align__(16) __nv_bfloat16 g_Qh[B_*H_*G_*DH], g_Ql[B_*H_*G_*DH];
__device__ __align__(16) __nv_bfloat16 g_Kh[B_*H_*G_*DH], g_Kl[B_*H_*G_*DH];
__device__ __align__(16) __half        g_Vf[B_*H_*G_*DH];   // fp16 V (single)
__device__ __align__(16) __nv_bfloat16 g_Ah[4*MK];
__device__ __align__(16) __nv_bfloat16 g_Al[4*MK];
__device__ __align__(16) __nv_bfloat16 g_Wh[4*WK];
__device__ __align__(16) __nv_bfloat16 g_Wl[4*WK];

#define LOG2E 1.4426950408889634f
#define SCL   (0.125f * LOG2E)

__device__ __forceinline__ unsigned smem_u32(const void* p) {
    unsigned r;
    asm("{ .reg .u64 t; cvta.to.shared.u64 t, %1; cvt.u32.u64 %0, t; }"
        : "=r"(r) : "l"(p));
    return r;
}
__device__ __forceinline__ void split2(float a, float b, unsigned& hp, unsigned& lp) {
    __nv_bfloat162 h = __floats2bfloat162_rn(a, b);
    float ra = a - __bfloat162float(h.x);
    float rb = b - __bfloat162float(h.y);
    __nv_bfloat162 l = __floats2bfloat162_rn(ra, rb);
    hp = *(unsigned*)&h;
    lp = *(unsigned*)&l;
}
__device__ __forceinline__ void cpa16(unsigned saddr, const void* g) {
    asm volatile("cp.async.cg.shared.global [%0], [%1], 16;"
                 :: "r"(saddr), "l"(g));
}
__device__ __forceinline__ float ex2(float x) {
    float y;
    asm("ex2.approx.ftz.f32 %0, %1;" : "=f"(y) : "f"(x));
    return y;
}

// ================= fused prep: converts + bucket =================
__device__ __forceinline__ int rpb(float d) {
    float ad = fabsf(d);
    int li;
    if (ad >= 128.0f) {
        li = 7;
    } else {
        float n = fmaxf(ad, 1e-6f);
        li = (int)floorf(__log2f(n));
        li = max(0, min(li, 31));
    }
    return d > 0.0f ? 31 + li : (d < 0.0f ? 31 - li : 31);
}

// blocks [0,6144): convert_x   [6144,7168): convert_w   [7168,15360): bucket
__global__ void prep_kernel(
    const float* __restrict__ q, const float* __restrict__ k,
    const float* __restrict__ v,
    const float* __restrict__ wq, const float* __restrict__ wk,
    const float* __restrict__ wv, const float* __restrict__ wo,
    const float* __restrict__ coords, const int* __restrict__ mask)
{
    int bid = blockIdx.x;
    if (bid < 6144) {
        int i = bid * 256 + threadIdx.x;
        int e = i << 2;
        int z = e / MK;
        int r = e - z * MK;
        const float* src = (z == 0) ? q : (z == 1) ? k : v;
        float4 x = *(const float4*)(src + r);
        unsigned hp0, lp0, hp1, lp1;
        split2(x.x, x.y, hp0, lp0);
        split2(x.z, x.w, hp1, lp1);
        *(uint2*)(g_Ah + e) = make_uint2(hp0, hp1);
        *(uint2*)(g_Al + e) = make_uint2(lp0, lp1);
    } else if (bid < 7168) {
        int i = (bid - 6144) * 256 + threadIdx.x;
        int e = i << 2;
        int z = e >> 18;
        int r = e & (WK - 1);
        const float* src = (z == 0) ? wq : (z == 1) ? wk : (z == 2) ? wv : wo;
        float4 x = *(const float4*)(src + r);
        unsigned hp0, lp0, hp1, lp1;
        split2(x.x, x.y, hp0, lp0);
        split2(x.z, x.w, hp1, lp1);
        *(uint2*)(g_Wh + e) = make_uint2(hp0, hp1);
        *(uint2*)(g_Wl + e) = make_uint2(lp0, lp1);
    } else {
        int i = (bid - 7168) * 256 + threadIdx.x;
        int idx = i << 1;
        int kk = idx & (G_-1);
        int qq = (idx >> 10) & (G_-1);
        int b = idx >> 20;
        float2 cq  = ((const float2*)coords)[b*G_ + qq];
        float2 ck0 = ((const float2*)coords)[b*G_ + kk];
        float2 ck1 = ((const float2*)coords)[b*G_ + kk + 1];
        unsigned v0 = ((unsigned)rpb(cq.x - ck0.x) << 6) | (unsigned)rpb(cq.y - ck0.y);
        unsigned v1 = ((unsigned)rpb(cq.x - ck1.x) << 6) | (unsigned)rpb(cq.y - ck1.y);
        if (mask[b*G_ + kk]     == 0) v0 |= 0x8000u;
        if (mask[b*G_ + kk + 1] == 0) v1 |= 0x8000u;
        g_bku[i] = v0 | (v1 << 16);
    }
}

// ================= HMMA primitives =================
__device__ __forceinline__ void ldsm4(unsigned addr, unsigned& r0, unsigned& r1,
                                      unsigned& r2, unsigned& r3) {
    asm volatile("ldmatrix.sync.aligned.m8n8.x4.shared.b16 {%0,%1,%2,%3}, [%4];"
                 : "=r"(r0), "=r"(r1), "=r"(r2), "=r"(r3) : "r"(addr));
}
__device__ __forceinline__ void ldsm4t(unsigned addr, unsigned& r0, unsigned& r1,
                                       unsigned& r2, unsigned& r3) {
    asm volatile("ldmatrix.sync.aligned.m8n8.x4.trans.shared.b16 {%0,%1,%2,%3}, [%4];"
                 : "=r"(r0), "=r"(r1), "=r"(r2), "=r"(r3) : "r"(addr));
}
__device__ __forceinline__ void mma16816(float* d, const unsigned* a,
                                         const unsigned* b) {
    asm volatile(
        "mma.sync.aligned.m16n8k16.row.col.f32.bf16.bf16.f32 "
        "{%0,%1,%2,%3}, {%4,%5,%6,%7}, {%8,%9}, {%0,%1,%2,%3};"
        : "+f"(d[0]), "+f"(d[1]), "+f"(d[2]), "+f"(d[3])
        : "r"(a[0]), "r"(a[1]), "r"(a[2]), "r"(a[3]), "r"(b[0]), "r"(b[1]));
}
__device__ __forceinline__ void mma16816h(float* d, const unsigned* a,
                                          const unsigned* b) {
    asm volatile(
        "mma.sync.aligned.m16n8k16.row.col.f32.f16.f16.f32 "
        "{%0,%1,%2,%3}, {%4,%5,%6,%7}, {%8,%9}, {%0,%1,%2,%3};"
        : "+f"(d[0]), "+f"(d[1]), "+f"(d[2]), "+f"(d[3])
        : "r"(a[0]), "r"(a[1]), "r"(a[2]), "r"(a[3]), "r"(b[0]), "r"(b[1]));
}

// ================= QKV GEMM: 128x128 tile, cp.async 3-stage ====
#define STAGE 32768
#define GEMM_DSMEM (3*STAGE + 1024)

__global__ __launch_bounds__(256, 2) void mma_gemm(
    const float* __restrict__ bq, const float* __restrict__ bk,
    const float* __restrict__ bv)
{
    extern __shared__ char smd[];

    int z = blockIdx.z;
    const __nv_bfloat16* Ah = g_Ah + (size_t)z * MK;
    const __nv_bfloat16* Al = g_Al + (size_t)z * MK;
    const __nv_bfloat16* Bh = g_Wh + (size_t)z * WK;
    const __nv_bfloat16* Bl = g_Wl + (size_t)z * WK;
    const float* bias = (z == 0) ? bq : (z == 1) ? bk : bv;

    int tid = threadIdx.x, wid = tid >> 5, lane = tid & 31;
    int m0 = blockIdx.y * 128;
    int n0 = blockIdx.x * 128;
    int wm = wid >> 1, wn = wid & 1;

    unsigned raw = smem_u32(smd);
    unsigned base = (raw + 1023u) & ~1023u;

    int sub = lane >> 3, r8 = lane & 7;
    int a_row = wm * 32 + ((sub & 1) << 3) + r8;
    int b_row = wn * 64 + ((sub & 1) << 3) + r8;
    int colb  = (sub >> 1) << 4;
    int grow = tid >> 3, gcu = tid & 7;

    unsigned soff[4];
    #pragma unroll
    for (int t = 0; t < 4; t++) {
        unsigned off = ((grow + t*32) << 7) + (gcu << 4);
        soff[t] = off ^ ((off >> 3) & 0x70);
    }

    float acc[2][8][4] = {};

    #define ISSUE(c) do {                                                      \
        int p_ = (c) >> 3, k0_ = ((c) & 7) << 6;                               \
        const __nv_bfloat16* As_ = (p_ == 1) ? Al : Ah;                        \
        const __nv_bfloat16* Bs_ = (p_ == 2) ? Bl : Bh;                        \
        unsigned st_ = base + ((c) % 3) * STAGE;                               \
        _Pragma("unroll")                                                      \
        for (int t = 0; t < 4; t++)                                            \
            cpa16(st_ + soff[t],                                               \
                  As_ + (size_t)(m0 + grow + t*32) * 512 + k0_ + (gcu << 3));  \
        _Pragma("unroll")                                                      \
        for (int t = 0; t < 4; t++)                                            \
            cpa16(st_ + 16384 + soff[t],                                       \
                  Bs_ + (size_t)(n0 + grow + t*32) * 512 + k0_ + (gcu << 3));  \
        asm volatile("cp.async.commit_group;");                                \
    } while (0)

    ISSUE(0);
    ISSUE(1);

    for (int c = 0; c < 24; c++) {
        if (c < 23) asm volatile("cp.async.wait_group 1;");
        else        asm volatile("cp.async.wait_group 0;");
        __syncthreads();
        if (c + 2 < 24) ISSUE(c + 2);

        unsigned sa_u = base + (c % 3) * STAGE;
        unsigned sb_u = sa_u + 16384;

        #pragma unroll
        for (int ks = 0; ks < 4; ks++) {
            unsigned a[2][4], bf[8][2];
            #pragma unroll
            for (int i = 0; i < 2; i++) {
                unsigned off = ((a_row + i*16) << 7) + colb + (ks << 5);
                off ^= (off >> 3) & 0x70;
                ldsm4(sa_u + off, a[i][0], a[i][1], a[i][2], a[i][3]);
            }
            #pragma unroll
            for (int jj = 0; jj < 4; jj++) {
                unsigned off = ((b_row + jj*16) << 7) + colb + (ks << 5);
                off ^= (off >> 3) & 0x70;
                unsigned r0, r1, r2, r3;
                ldsm4(sb_u + off, r0, r1, r2, r3);
                bf[jj*2+0][0] = r0; bf[jj*2+0][1] = r2;
                bf[jj*2+1][0] = r1; bf[jj*2+1][1] = r3;
            }
            #pragma unroll
            for (int i = 0; i < 2; i++)
                #pragma unroll
                for (int j = 0; j < 8; j++)
                    mma16816(acc[i][j], a[i], bf[j]);
        }
    }

    int rbase = m0 + wm * 32 + (lane >> 2);
    int cbase = n0 + wn * 64 + ((lane & 3) << 1);
    #pragma unroll
    for (int i = 0; i < 2; i++) {
        #pragma unroll
        for (int j = 0; j < 8; j++) {
            int c = cbase + j * 8;
            float bx = bias[c], by = bias[c+1];
            #pragma unroll
            for (int half = 0; half < 2; half++) {
                int r = rbase + i * 16 + half * 8;
                float vx = acc[i][j][half*2+0] + bx;
                float vy = acc[i][j][half*2+1] + by;
                int bb = r >> 10, g = r & 1023;
                int h = c >> 6, dd = c & 63;
                size_t idx = (((size_t)(bb << 3) + h) << 16) + (g << 6) + dd;
                if (z == 2) {
                    __half2 v2 = __floats2half2_rn(vx, vy);
                    *(unsigned*)(g_Vf + idx) = *(unsigned*)&v2;
                } else {
                    __nv_bfloat16* dh = (z == 0) ? g_Qh : g_Kh;
                    __nv_bfloat16* dl = (z == 0) ? g_Ql : g_Kl;
                    unsigned hp, lp;
                    split2(vx, vy, hp, lp);
                    *(unsigned*)(dh + idx) = hp;
                    *(unsigned*)(dl + idx) = lp;
                }
            }
        }
    }
}

// ================= out-proj GEMM: 128x64 tile, cp.async 3-stage ====
#define OSTAGE 24576
#define OGEMM_DSMEM (3*OSTAGE + 1024)

__global__ __launch_bounds__(256, 2) void out_gemm(
    const float* __restrict__ bo, float* __restrict__ outp)
{
    extern __shared__ char smd[];

    const __nv_bfloat16* Ah = g_Ah + 3*(size_t)MK;
    const __nv_bfloat16* Al = g_Al + 3*(size_t)MK;
    const __nv_bfloat16* Bh = g_Wh + 3*(size_t)WK;
    const __nv_bfloat16* Bl = g_Wl + 3*(size_t)WK;

    int tid = threadIdx.x, wid = tid >> 5, lane = tid & 31;
    int m0 = blockIdx.y * 128;
    int n0 = blockIdx.x * 64;
    int wm = wid >> 1, wn = wid & 1;

    unsigned raw = smem_u32(smd);
    unsigned base = (raw + 1023u) & ~1023u;

    int sub = lane >> 3, r8 = lane & 7;
    int a_row = wm * 32 + ((sub & 1) << 3) + r8;
    int b_row = wn * 32 + ((sub & 1) << 3) + r8;
    int colb  = (sub >> 1) << 4;
    int grow = tid >> 3, gcu = tid & 7;

    unsigned soff[4];
    #pragma unroll
    for (int t = 0; t < 4; t++) {
        unsigned off = ((grow + t*32) << 7) + (gcu << 4);
        soff[t] = off ^ ((off >> 3) & 0x70);
    }

    float acc[2][4][4] = {};

    #define OISSUE(c) do {                                                     \
        int p_ = (c) >> 3, k0_ = ((c) & 7) << 6;                               \
        const __nv_bfloat16* As_ = (p_ == 1) ? Al : Ah;                        \
        const __nv_bfloat16* Bs_ = (p_ == 2) ? Bl : Bh;                        \
        unsigned st_ = base + ((c) % 3) * OSTAGE;                              \
        _Pragma("unroll")                                                      \
        for (int t = 0; t < 4; t++)                                            \
            cpa16(st_ + soff[t],                                               \
                  As_ + (size_t)(m0 + grow + t*32) * 512 + k0_ + (gcu << 3));  \
        _Pragma("unroll")                                                      \
        for (int t = 0; t < 2; t++)                                            \
            cpa16(st_ + 16384 + soff[t],                                       \
                  Bs_ + (size_t)(n0 + grow + t*32) * 512 + k0_ + (gcu << 3));  \
        asm volatile("cp.async.commit_group;");                                \
    } while (0)

    OISSUE(0);
    OISSUE(1);

    for (int c = 0; c < 24; c++) {
        if (c < 23) asm volatile("cp.async.wait_group 1;");
        else        asm volatile("cp.async.wait_group 0;");
        __syncthreads();
        if (c + 2 < 24) OISSUE(c + 2);

        unsigned sa_u = base + (c % 3) * OSTAGE;
        unsigned sb_u = sa_u + 16384;

        #pragma unroll
        for (int ks = 0; ks < 4; ks++) {
            unsigned a[2][4], bf[4][2];
            #pragma unroll
            for (int i = 0; i < 2; i++) {
                unsigned off = ((a_row + i*16) << 7) + colb + (ks << 5);
                off ^= (off >> 3) & 0x70;
                ldsm4(sa_u + off, a[i][0], a[i][1], a[i][2], a[i][3]);
            }
            #pragma unroll
            for (int jj = 0; jj < 2; jj++) {
                unsigned off = ((b_row + jj*16) << 7) + colb + (ks << 5);
                off ^= (off >> 3) & 0x70;
                unsigned r0, r1, r2, r3;
                ldsm4(sb_u + off, r0, r1, r2, r3);
                bf[jj*2+0][0] = r0; bf[jj*2+0][1] = r2;
                bf[jj*2+1][0] = r1; bf[jj*2+1][1] = r3;
            }
            #pragma unroll
            for (int i = 0; i < 2; i++)
                #pragma unroll
                for (int j = 0; j < 4; j++)
                    mma16816(acc[i][j], a[i], bf[j]);
        }
    }

    int rbase = m0 + wm * 32 + (lane >> 2);
    int cbase = n0 + wn * 32 + ((lane & 3) << 1);
    #pragma unroll
    for (int i = 0; i < 2; i++) {
        #pragma unroll
        for (int j = 0; j < 4; j++) {
            int c = cbase + j * 8;
            float bx = bo[c], by = bo[c+1];
            #pragma unroll
            for (int half = 0; half < 2; half++) {
                int r = rbase + i * 16 + half * 8;
                *(float2*)(outp + (size_t)r * 512 + c) =
                    make_float2(acc[i][j][half*2+0] + bx,
                                acc[i][j][half*2+1] + by);
            }
        }
    }
}

// ================= HMMA flash attention (fp16 PV, single barrier/tile) ====
// stage (43008 B): KH+0, KL+8192, VF+16384, BKT+24576 (pitch 144, 18432 B)
#define AKV 43008
#define ASM_RXY (2*AKV)
#define ATTN_SMEM (2*AKV + 8192)

__global__ __launch_bounds__(256, 2) void attn_mma(
    const float* __restrict__ rpe_x, const float* __restrict__ rpe_y)
{
    extern __shared__ char smc[];
    __nv_bfloat16* rxy = (__nv_bfloat16*)(smc + ASM_RXY);

    int tid = threadIdx.x, wid = tid >> 5, lane = tid & 31;
    int bh = blockIdx.y;
    int b = bh >> 3, hh = bh & 7;
    int q0 = blockIdx.x * 128;
    unsigned smu = smem_u32(smc);

    for (int i = tid; i < 4096; i += 256) {
        int bx = i >> 6, by = i & 63;
        if (bx < 63 && by < 63)
            rxy[i] = __float2bfloat16_rn((rpe_x[bx*8 + hh] + rpe_y[by*8 + hh]) * LOG2E);
    }

    int sub = lane >> 3, r8v = lane & 7;
    int r = lane >> 2, c = lane & 3;

    // stage Q (hi then lo) through stage-0 area, extract A-frags
    unsigned qh[4][4], ql[4][4];
    #pragma unroll
    for (int s = 0; s < 2; s++) {
        const __nv_bfloat16* src = s ? g_Ql : g_Qh;
        __syncthreads();
        for (int i = tid; i < 1024; i += 256) {
            int row = i >> 3, cu = i & 7;
            unsigned off = (row << 7) + (cu << 4);
            off ^= (off >> 3) & 0x70;
            *(uint4*)(smc + off) =
                *(const uint4*)(src + ((size_t)(bh << 10) + q0 + row) * 64 + (cu << 3));
        }
        __syncthreads();
        unsigned qrow = (unsigned)(wid << 4) + ((sub & 1) << 3) + r8v;
        unsigned qcb = (sub >> 1) << 4;
        #pragma unroll
        for (int ks = 0; ks < 4; ks++) {
            unsigned off = (qrow << 7) + qcb + (ks << 5);
            off ^= (off >> 3) & 0x70;
            if (s) ldsm4(smu + off, ql[ks][0], ql[ks][1], ql[ks][2], ql[ks][3]);
            else   ldsm4(smu + off, qh[ks][0], qh[ks][1], qh[ks][2], qh[ks][3]);
        }
    }
    __syncthreads();   // Q frags extracted before stage 0 is overwritten

    float o[8][4] = {};
    float m2[2] = {-1e30f, -1e30f};
    float l2[2] = {0.0f, 0.0f};

    const __nv_bfloat16* kh = g_Kh + ((size_t)bh << 10) * 64;
    const __nv_bfloat16* kl = g_Kl + ((size_t)bh << 10) * 64;
    const __half*        vf = g_Vf + ((size_t)bh << 10) * 64;
    const unsigned short* bksrc =
        (const unsigned short*)g_bku + (((size_t)(b << 10) + q0) << 10);

    #define ISSUE_A(ti) do {                                                   \
        unsigned st_ = smu + ((ti) & 1) * AKV;                                 \
        int kt_ = (ti) << 6;                                                   \
        _Pragma("unroll")                                                      \
        for (int p = 0; p < 2; p++) {                                          \
            int i_ = tid + (p << 8);                                           \
            int row_ = i_ >> 3, cu_ = i_ & 7;                                  \
            unsigned off_ = (row_ << 7) + (cu_ << 4);                          \
            off_ ^= (off_ >> 3) & 0x70;                                        \
            size_t gs_ = (size_t)(kt_ + row_) * 64 + (cu_ << 3);               \
            cpa16(st_ + off_,         kh + gs_);                               \
            cpa16(st_ + 8192 + off_,  kl + gs_);                               \
            cpa16(st_ + 16384 + off_, vf + gs_);                               \
        }                                                                      \
        _Pragma("unroll")                                                      \
        for (int p = 0; p < 4; p++) {                                          \
            int i_ = tid + (p << 8);                                           \
            int row_ = i_ >> 3, cu_ = i_ & 7;                                  \
            cpa16(st_ + 24576 + row_ * 144 + (cu_ << 4),                       \
                  bksrc + ((size_t)row_ << 10) + kt_ + (cu_ << 3));            \
        }                                                                      \
        asm volatile("cp.async.commit_group;");                                \
    } while (0)

    ISSUE_A(0);

    for (int ti = 0; ti < 16; ti++) {
        asm volatile("cp.async.wait_group 0;");
        __syncthreads();
        if (ti < 15) ISSUE_A(ti + 1);

        unsigned stb = smu + (ti & 1) * AKV;
        char*    stc = smc + (ti & 1) * AKV;

        // ---- S = Q K^T (3 split passes, bf16) ----
        float S[8][4] = {};
        #pragma unroll
        for (int ks = 0; ks < 4; ks++) {
            unsigned bf[8][2];
            #pragma unroll
            for (int t = 0; t < 4; t++) {
                unsigned krow = (t << 4) + ((sub & 1) << 3) + r8v;
                unsigned off = (krow << 7) + ((sub >> 1) << 4) + (ks << 5);
                off ^= (off >> 3) & 0x70;
                unsigned r0, r1, r2, r3;
                ldsm4(stb + off, r0, r1, r2, r3);
                bf[t*2+0][0] = r0; bf[t*2+0][1] = r2;
                bf[t*2+1][0] = r1; bf[t*2+1][1] = r3;
            }
            #pragma unroll
            for (int n = 0; n < 8; n++) {
                mma16816(S[n], qh[ks], bf[n]);
                mma16816(S[n], ql[ks], bf[n]);
            }
        }
        #pragma unroll
        for (int ks = 0; ks < 4; ks++) {
            unsigned bf[8][2];
            #pragma unroll
            for (int t = 0; t < 4; t++) {
                unsigned krow = (t << 4) + ((sub & 1) << 3) + r8v;
                unsigned off = (krow << 7) + ((sub >> 1) << 4) + (ks << 5);
                off ^= (off >> 3) & 0x70;
                unsigned r0, r1, r2, r3;
                ldsm4(stb + 8192 + off, r0, r1, r2, r3);
                bf[t*2+0][0] = r0; bf[t*2+0][1] = r2;
                bf[t*2+1][0] = r1; bf[t*2+1][1] = r3;
            }
            #pragma unroll
            for (int n = 0; n < 8; n++)
                mma16816(S[n], qh[ks], bf[n]);
        }

        // ---- bias + online softmax (log2 domain), pack P fp16 A-frags ----
        unsigned pAf[4][4];
        #pragma unroll
        for (int h = 0; h < 2; h++) {
            int rowq = (wid << 4) + r + (h << 3);
            const unsigned* brow = (const unsigned*)(stc + 24576 + rowq * 144) + c;
            float rm = -1e30f;
            #pragma unroll
            for (int j = 0; j < 8; j++) {
                unsigned w = brow[j << 2];
                unsigned k0 = w & 0xffffu, k1 = w >> 16;
                float s0 = (k0 & 0x8000u) ? -1e30f
                         : fmaf(S[j][h*2+0], SCL,
                                __bfloat162float(rxy[k0 & 0xfffu]));
                float s1 = (k1 & 0x8000u) ? -1e30f
                         : fmaf(S[j][h*2+1], SCL,
                                __bfloat162float(rxy[k1 & 0xfffu]));
                S[j][h*2+0] = s0; S[j][h*2+1] = s1;
                rm = fmaxf(rm, fmaxf(s0, s1));
            }
            rm = fmaxf(rm, __shfl_xor_sync(0xffffffffu, rm, 1));
            rm = fmaxf(rm, __shfl_xor_sync(0xffffffffu, rm, 2));
            float mn = fmaxf(m2[h], rm);
            float corr = ex2(m2[h] - mn);
            m2[h] = mn;
            float rs = 0.0f;
            #pragma unroll
            for (int j = 0; j < 8; j++) {
                float p0 = ex2(S[j][h*2+0] - mn);
                float p1 = ex2(S[j][h*2+1] - mn);
                rs += p0 + p1;
                __half2 hp2 = __floats2half2_rn(p0, p1);
                pAf[j >> 1][(j & 1) * 2 + h] = *(unsigned*)&hp2;
            }
            l2[h] = l2[h] * corr + rs;
            #pragma unroll
            for (int n = 0; n < 8; n++) {
                o[n][h*2+0] *= corr;
                o[n][h*2+1] *= corr;
            }
        }

        // ---- O += P V (single fp16 pass, V via trans ldmatrix) ----
        int krowv = (lane & 15);
        int dby = ((lane >> 4) << 4);
        #pragma unroll
        for (int jj = 0; jj < 4; jj++) {
            unsigned bf[8][2];
            #pragma unroll
            for (int t = 0; t < 4; t++) {
                unsigned off = (((jj << 4) + krowv) << 7) + (t << 5) + dby;
                off ^= (off >> 3) & 0x70;
                unsigned r0, r1, r2, r3;
                ldsm4t(stb + 16384 + off, r0, r1, r2, r3);
                bf[t*2+0][0] = r0; bf[t*2+0][1] = r1;
                bf[t*2+1][0] = r2; bf[t*2+1][1] = r3;
            }
            #pragma unroll
            for (int n = 0; n < 8; n++)
                mma16816h(o[n], pAf[jj], bf[n]);
        }
    }

    // ---- finalize: normalize + write bf16 hi/lo to A-slab 3 ----
    #pragma unroll
    for (int h = 0; h < 2; h++) {
        float ls = l2[h];
        ls += __shfl_xor_sync(0xffffffffu, ls, 1);
        ls += __shfl_xor_sync(0xffffffffu, ls, 2);
        float inv = 1.0f / ls;
        int q = q0 + (wid << 4) + r + (h << 3);
        size_t base = 3*(size_t)MK + ((size_t)((b << 10) + q)) * 512 + hh * 64 + (c << 1);
        #pragma unroll
        for (int j = 0; j < 8; j++) {
            float f0 = o[j][h*2+0] * inv;
            float f1 = o[j][h*2+1] * inv;
            unsigned hp, lp;
            split2(f0, f1, hp, lp);
            *(unsigned*)(g_Ah + base + (j << 3)) = hp;
            *(unsigned*)(g_Al + base + (j << 3)) = lp;
        }
    }
}

// ================= launch =================
extern "C" void kernel_launch(void* const* d_in, const int* in_sizes, int n_in,
                              void* d_out, int out_size) {
    const float* query  = (const float*)d_in[0];
    const float* key    = (const float*)d_in[1];
    const float* value  = (const float*)d_in[2];
    const float* coords = (const float*)d_in[3];
    const int*   mask   = (const int*)  d_in[4];
    const float* Wq = (const float*)d_in[5];
    const float* bq = (const float*)d_in[6];
    const float* Wk = (const float*)d_in[7];
    const float* bk = (const float*)d_in[8];
    const float* Wv = (const float*)d_in[9];
    const float* bv = (const float*)d_in[10];
    const float* Wo = (const float*)d_in[11];
    const float* bo = (const float*)d_in[12];
    const float* rpe_x = (const float*)d_in[13];
    const float* rpe_y = (const float*)d_in[14];
    float* out = (float*)d_out;

    cudaFuncSetAttribute(attn_mma,
                         cudaFuncAttributeMaxDynamicSharedMemorySize, ATTN_SMEM);
    cudaFuncSetAttribute(mma_gemm,
                         cudaFuncAttributeMaxDynamicSharedMemorySize, GEMM_DSMEM);
    cudaFuncSetAttribute(out_gemm,
                         cudaFuncAttributeMaxDynamicSharedMemorySize, OGEMM_DSMEM);

    prep_kernel<<<15360, 256>>>(query, key, value, Wq, Wk, Wv, Wo, coords, mask);

    mma_gemm<<<dim3(4, 32, 3), 256, GEMM_DSMEM>>>(bq, bk, bv);

    attn_mma<<<dim3(8, 32), 256, ATTN_SMEM>>>(rpe_x, rpe_y);

    out_gemm<<<dim3(8, 32), 256, OGEMM_DSMEM>>>(bo, out);
}

// round 10
// speedup vs baseline: 4.9790x; 1.0312x over previous
#include <cuda_runtime.h>
#include <cuda_bf16.h>
#include <cuda_fp16.h>
#include <math.h>

#define B_  4
#define G_  1024
#define D_  512
#define H_  8
#define DH  64
#define MK  (4096*512)
#define WK  (512*512)

// ---- scratch (device globals: allocation-free rule) ----
__device__ unsigned g_bku[B_*G_*G_/2];                 // packed u16 buckets (2 per u32)
__device__ __align__(16) __nv_bfloat16 g_Qh[B_*H_*G_*DH], g_Ql[B_*H_*G_*DH];
__device__ __align__(16) __nv_bfloat16 g_Kh[B_*H_*G_*DH], g_Kl[B_*H_*G_*DH];
__device__ __align__(16) __half        g_Vf[B_*H_*G_*DH];   // fp16 V (single)
__device__ __align__(16) __nv_bfloat16 g_Ah[4*MK];
__device__ __align__(16) __nv_bfloat16 g_Al[4*MK];
__device__ __align__(16) __nv_bfloat16 g_Wh[4*WK];
__device__ __align__(16) __nv_bfloat16 g_Wl[4*WK];

#define LOG2E 1.4426950408889634f
#define SCL   (0.125f * LOG2E)
#define MFIX  8.0f                     // fixed log2-domain softmax shift

__device__ __forceinline__ unsigned smem_u32(const void* p) {
    unsigned r;
    asm("{ .reg .u64 t; cvta.to.shared.u64 t, %1; cvt.u32.u64 %0, t; }"
        : "=r"(r) : "l"(p));
    return r;
}
__device__ __forceinline__ void split2(float a, float b, unsigned& hp, unsigned& lp) {
    __nv_bfloat162 h = __floats2bfloat162_rn(a, b);
    float ra = a - __bfloat162float(h.x);
    float rb = b - __bfloat162float(h.y);
    __nv_bfloat162 l = __floats2bfloat162_rn(ra, rb);
    hp = *(unsigned*)&h;
    lp = *(unsigned*)&l;
}
__device__ __forceinline__ void cpa16(unsigned saddr, const void* g) {
    asm volatile("cp.async.cg.shared.global [%0], [%1], 16;"
                 :: "r"(saddr), "l"(g));
}
__device__ __forceinline__ float ex2(float x) {
    float y;
    asm("ex2.approx.ftz.f32 %0, %1;" : "=f"(y) : "f"(x));
    return y;
}

// ================= fused prep: converts + bucket =================
__device__ __forceinline__ int rpb(float d) {
    float ad = fabsf(d);
    int li;
    if (ad >= 128.0f) {
        li = 7;
    } else {
        float n = fmaxf(ad, 1e-6f);
        li = (int)floorf(__log2f(n));
        li = max(0, min(li, 31));
    }
    return d > 0.0f ? 31 + li : (d < 0.0f ? 31 - li : 31);
}

// blocks [0,6144): convert_x   [6144,7168): convert_w   [7168,15360): bucket
__global__ void prep_kernel(
    const float* __restrict__ q, const float* __restrict__ k,
    const float* __restrict__ v,
    const float* __restrict__ wq, const float* __restrict__ wk,
    const float* __restrict__ wv, const float* __restrict__ wo,
    const float* __restrict__ coords, const int* __restrict__ mask)
{
    int bid = blockIdx.x;
    if (bid < 6144) {
        int i = bid * 256 + threadIdx.x;
        int e = i << 2;
        int z = e / MK;
        int r = e - z * MK;
        const float* src = (z == 0) ? q : (z == 1) ? k : v;
        float4 x = *(const float4*)(src + r);
        unsigned hp0, lp0, hp1, lp1;
        split2(x.x, x.y, hp0, lp0);
        split2(x.z, x.w, hp1, lp1);
        *(uint2*)(g_Ah + e) = make_uint2(hp0, hp1);
        *(uint2*)(g_Al + e) = make_uint2(lp0, lp1);
    } else if (bid < 7168) {
        int i = (bid - 6144) * 256 + threadIdx.x;
        int e = i << 2;
        int z = e >> 18;
        int r = e & (WK - 1);
        const float* src = (z == 0) ? wq : (z == 1) ? wk : (z == 2) ? wv : wo;
        float4 x = *(const float4*)(src + r);
        unsigned hp0, lp0, hp1, lp1;
        split2(x.x, x.y, hp0, lp0);
        split2(x.z, x.w, hp1, lp1);
        *(uint2*)(g_Wh + e) = make_uint2(hp0, hp1);
        *(uint2*)(g_Wl + e) = make_uint2(lp0, lp1);
    } else {
        int i = (bid - 7168) * 256 + threadIdx.x;
        int idx = i << 1;
        int kk = idx & (G_-1);
        int qq = (idx >> 10) & (G_-1);
        int b = idx >> 20;
        float2 cq  = ((const float2*)coords)[b*G_ + qq];
        float2 ck0 = ((const float2*)coords)[b*G_ + kk];
        float2 ck1 = ((const float2*)coords)[b*G_ + kk + 1];
        unsigned v0 = ((unsigned)rpb(cq.x - ck0.x) << 6) | (unsigned)rpb(cq.y - ck0.y);
        unsigned v1 = ((unsigned)rpb(cq.x - ck1.x) << 6) | (unsigned)rpb(cq.y - ck1.y);
        if (mask[b*G_ + kk]     == 0) v0 = 0x0FFFu;   // sentinel -> -inf bias
        if (mask[b*G_ + kk + 1] == 0) v1 = 0x0FFFu;
        g_bku[i] = v0 | (v1 << 16);
    }
}

// ================= HMMA primitives =================
__device__ __forceinline__ void ldsm4(unsigned addr, unsigned& r0, unsigned& r1,
                                      unsigned& r2, unsigned& r3) {
    asm volatile("ldmatrix.sync.aligned.m8n8.x4.shared.b16 {%0,%1,%2,%3}, [%4];"
                 : "=r"(r0), "=r"(r1), "=r"(r2), "=r"(r3) : "r"(addr));
}
__device__ __forceinline__ void ldsm4t(unsigned addr, unsigned& r0, unsigned& r1,
                                       unsigned& r2, unsigned& r3) {
    asm volatile("ldmatrix.sync.aligned.m8n8.x4.trans.shared.b16 {%0,%1,%2,%3}, [%4];"
                 : "=r"(r0), "=r"(r1), "=r"(r2), "=r"(r3) : "r"(addr));
}
__device__ __forceinline__ void mma16816(float* d, const unsigned* a,
                                         const unsigned* b) {
    asm volatile(
        "mma.sync.aligned.m16n8k16.row.col.f32.bf16.bf16.f32 "
        "{%0,%1,%2,%3}, {%4,%5,%6,%7}, {%8,%9}, {%0,%1,%2,%3};"
        : "+f"(d[0]), "+f"(d[1]), "+f"(d[2]), "+f"(d[3])
        : "r"(a[0]), "r"(a[1]), "r"(a[2]), "r"(a[3]), "r"(b[0]), "r"(b[1]));
}
__device__ __forceinline__ void mma16816h(float* d, const unsigned* a,
                                          const unsigned* b) {
    asm volatile(
        "mma.sync.aligned.m16n8k16.row.col.f32.f16.f16.f32 "
        "{%0,%1,%2,%3}, {%4,%5,%6,%7}, {%8,%9}, {%0,%1,%2,%3};"
        : "+f"(d[0]), "+f"(d[1]), "+f"(d[2]), "+f"(d[3])
        : "r"(a[0]), "r"(a[1]), "r"(a[2]), "r"(a[3]), "r"(b[0]), "r"(b[1]));
}

// ================= QKV GEMM: 128x128 tile, cp.async 3-stage ====
#define STAGE 32768
#define GEMM_DSMEM (3*STAGE + 1024)

__global__ __launch_bounds__(256, 2) void mma_gemm(
    const float* __restrict__ bq, const float* __restrict__ bk,
    const float* __restrict__ bv)
{
    extern __shared__ char smd[];

    int z = blockIdx.z;
    const __nv_bfloat16* Ah = g_Ah + (size_t)z * MK;
    const __nv_bfloat16* Al = g_Al + (size_t)z * MK;
    const __nv_bfloat16* Bh = g_Wh + (size_t)z * WK;
    const __nv_bfloat16* Bl = g_Wl + (size_t)z * WK;
    const float* bias = (z == 0) ? bq : (z == 1) ? bk : bv;

    int tid = threadIdx.x, wid = tid >> 5, lane = tid & 31;
    int m0 = blockIdx.y * 128;
    int n0 = blockIdx.x * 128;
    int wm = wid >> 1, wn = wid & 1;

    unsigned raw = smem_u32(smd);
    unsigned base = (raw + 1023u) & ~1023u;

    int sub = lane >> 3, r8 = lane & 7;
    int a_row = wm * 32 + ((sub & 1) << 3) + r8;
    int b_row = wn * 64 + ((sub & 1) << 3) + r8;
    int colb  = (sub >> 1) << 4;
    int grow = tid >> 3, gcu = tid & 7;

    unsigned soff[4];
    #pragma unroll
    for (int t = 0; t < 4; t++) {
        unsigned off = ((grow + t*32) << 7) + (gcu << 4);
        soff[t] = off ^ ((off >> 3) & 0x70);
    }

    float acc[2][8][4] = {};

    #define ISSUE(c) do {                                                      \
        int p_ = (c) >> 3, k0_ = ((c) & 7) << 6;                               \
        const __nv_bfloat16* As_ = (p_ == 1) ? Al : Ah;                        \
        const __nv_bfloat16* Bs_ = (p_ == 2) ? Bl : Bh;                        \
        unsigned st_ = base + ((c) % 3) * STAGE;                               \
        _Pragma("unroll")                                                      \
        for (int t = 0; t < 4; t++)                                            \
            cpa16(st_ + soff[t],                                               \
                  As_ + (size_t)(m0 + grow + t*32) * 512 + k0_ + (gcu << 3));  \
        _Pragma("unroll")                                                      \
        for (int t = 0; t < 4; t++)                                            \
            cpa16(st_ + 16384 + soff[t],                                       \
                  Bs_ + (size_t)(n0 + grow + t*32) * 512 + k0_ + (gcu << 3));  \
        asm volatile("cp.async.commit_group;");                                \
    } while (0)

    ISSUE(0);
    ISSUE(1);

    for (int c = 0; c < 24; c++) {
        if (c < 23) asm volatile("cp.async.wait_group 1;");
        else        asm volatile("cp.async.wait_group 0;");
        __syncthreads();
        if (c + 2 < 24) ISSUE(c + 2);

        unsigned sa_u = base + (c % 3) * STAGE;
        unsigned sb_u = sa_u + 16384;

        #pragma unroll
        for (int ks = 0; ks < 4; ks++) {
            unsigned a[2][4], bf[8][2];
            #pragma unroll
            for (int i = 0; i < 2; i++) {
                unsigned off = ((a_row + i*16) << 7) + colb + (ks << 5);
                off ^= (off >> 3) & 0x70;
                ldsm4(sa_u + off, a[i][0], a[i][1], a[i][2], a[i][3]);
            }
            #pragma unroll
            for (int jj = 0; jj < 4; jj++) {
                unsigned off = ((b_row + jj*16) << 7) + colb + (ks << 5);
                off ^= (off >> 3) & 0x70;
                unsigned r0, r1, r2, r3;
                ldsm4(sb_u + off, r0, r1, r2, r3);
                bf[jj*2+0][0] = r0; bf[jj*2+0][1] = r2;
                bf[jj*2+1][0] = r1; bf[jj*2+1][1] = r3;
            }
            #pragma unroll
            for (int i = 0; i < 2; i++)
                #pragma unroll
                for (int j = 0; j < 8; j++)
                    mma16816(acc[i][j], a[i], bf[j]);
        }
    }

    int rbase = m0 + wm * 32 + (lane >> 2);
    int cbase = n0 + wn * 64 + ((lane & 3) << 1);
    #pragma unroll
    for (int i = 0; i < 2; i++) {
        #pragma unroll
        for (int j = 0; j < 8; j++) {
            int c = cbase + j * 8;
            float bx = bias[c], by = bias[c+1];
            #pragma unroll
            for (int half = 0; half < 2; half++) {
                int r = rbase + i * 16 + half * 8;
                float vx = acc[i][j][half*2+0] + bx;
                float vy = acc[i][j][half*2+1] + by;
                int bb = r >> 10, g = r & 1023;
                int h = c >> 6, dd = c & 63;
                size_t idx = (((size_t)(bb << 3) + h) << 16) + (g << 6) + dd;
                if (z == 2) {
                    __half2 v2 = __floats2half2_rn(vx, vy);
                    *(unsigned*)(g_Vf + idx) = *(unsigned*)&v2;
                } else {
                    __nv_bfloat16* dh = (z == 0) ? g_Qh : g_Kh;
                    __nv_bfloat16* dl = (z == 0) ? g_Ql : g_Kl;
                    unsigned hp, lp;
                    split2(vx, vy, hp, lp);
                    *(unsigned*)(dh + idx) = hp;
                    *(unsigned*)(dl + idx) = lp;
                }
            }
        }
    }
}

// ================= out-proj GEMM: 128x64 tile, cp.async 4-stage ====
#define OSTAGE 24576
#define OGEMM_DSMEM (4*OSTAGE + 1024)

__global__ __launch_bounds__(256, 2) void out_gemm(
    const float* __restrict__ bo, float* __restrict__ outp)
{
    extern __shared__ char smd[];

    const __nv_bfloat16* Ah = g_Ah + 3*(size_t)MK;
    const __nv_bfloat16* Al = g_Al + 3*(size_t)MK;
    const __nv_bfloat16* Bh = g_Wh + 3*(size_t)WK;
    const __nv_bfloat16* Bl = g_Wl + 3*(size_t)WK;

    int tid = threadIdx.x, wid = tid >> 5, lane = tid & 31;
    int m0 = blockIdx.y * 128;
    int n0 = blockIdx.x * 64;
    int wm = wid >> 1, wn = wid & 1;

    unsigned raw = smem_u32(smd);
    unsigned base = (raw + 1023u) & ~1023u;

    int sub = lane >> 3, r8 = lane & 7;
    int a_row = wm * 32 + ((sub & 1) << 3) + r8;
    int b_row = wn * 32 + ((sub & 1) << 3) + r8;
    int colb  = (sub >> 1) << 4;
    int grow = tid >> 3, gcu = tid & 7;

    unsigned soff[4];
    #pragma unroll
    for (int t = 0; t < 4; t++) {
        unsigned off = ((grow + t*32) << 7) + (gcu << 4);
        soff[t] = off ^ ((off >> 3) & 0x70);
    }

    float acc[2][4][4] = {};

    #define OISSUE(c) do {                                                     \
        int p_ = (c) >> 3, k0_ = ((c) & 7) << 6;                               \
        const __nv_bfloat16* As_ = (p_ == 1) ? Al : Ah;                        \
        const __nv_bfloat16* Bs_ = (p_ == 2) ? Bl : Bh;                        \
        unsigned st_ = base + ((c) & 3) * OSTAGE;                              \
        _Pragma("unroll")                                                      \
        for (int t = 0; t < 4; t++)                                            \
            cpa16(st_ + soff[t],                                               \
                  As_ + (size_t)(m0 + grow + t*32) * 512 + k0_ + (gcu << 3));  \
        _Pragma("unroll")                                                      \
        for (int t = 0; t < 2; t++)                                            \
            cpa16(st_ + 16384 + soff[t],                                       \
                  Bs_ + (size_t)(n0 + grow + t*32) * 512 + k0_ + (gcu << 3));  \
        asm volatile("cp.async.commit_group;");                                \
    } while (0)

    OISSUE(0);
    OISSUE(1);
    OISSUE(2);

    for (int c = 0; c < 24; c++) {
        if      (c <= 21) asm volatile("cp.async.wait_group 2;");
        else if (c == 22) asm volatile("cp.async.wait_group 1;");
        else              asm volatile("cp.async.wait_group 0;");
        __syncthreads();
        if (c + 3 < 24) OISSUE(c + 3);

        unsigned sa_u = base + (c & 3) * OSTAGE;
        unsigned sb_u = sa_u + 16384;

        #pragma unroll
        for (int ks = 0; ks < 4; ks++) {
            unsigned a[2][4], bf[4][2];
            #pragma unroll
            for (int i = 0; i < 2; i++) {
                unsigned off = ((a_row + i*16) << 7) + colb + (ks << 5);
                off ^= (off >> 3) & 0x70;
                ldsm4(sa_u + off, a[i][0], a[i][1], a[i][2], a[i][3]);
            }
            #pragma unroll
            for (int jj = 0; jj < 2; jj++) {
                unsigned off = ((b_row + jj*16) << 7) + colb + (ks << 5);
                off ^= (off >> 3) & 0x70;
                unsigned r0, r1, r2, r3;
                ldsm4(sb_u + off, r0, r1, r2, r3);
                bf[jj*2+0][0] = r0; bf[jj*2+0][1] = r2;
                bf[jj*2+1][0] = r1; bf[jj*2+1][1] = r3;
            }
            #pragma unroll
            for (int i = 0; i < 2; i++)
                #pragma unroll
                for (int j = 0; j < 4; j++)
                    mma16816(acc[i][j], a[i], bf[j]);
        }
    }

    int rbase = m0 + wm * 32 + (lane >> 2);
    int cbase = n0 + wn * 32 + ((lane & 3) << 1);
    #pragma unroll
    for (int i = 0; i < 2; i++) {
        #pragma unroll
        for (int j = 0; j < 4; j++) {
            int c = cbase + j * 8;
            float bx = bo[c], by = bo[c+1];
            #pragma unroll
            for (int half = 0; half < 2; half++) {
                int r = rbase + i * 16 + half * 8;
                *(float2*)(outp + (size_t)r * 512 + c) =
                    make_float2(acc[i][j][half*2+0] + bx,
                                acc[i][j][half*2+1] + by);
            }
        }
    }
}

// ================= HMMA flash attention (fixed-shift softmax) ====
// stage (43008 B): KH+0, KL+8192, VF+16384, BKT+24576 (pitch 144, 18432 B)
// rxy table: f32, 4096 entries at 2*AKV (16 KB); total 102400 B
#define AKV 43008
#define ASM_RXY (2*AKV)
#define ATTN_SMEM (2*AKV + 16384)

__global__ __launch_bounds__(256, 2) void attn_mma(
    const float* __restrict__ rpe_x, const float* __restrict__ rpe_y)
{
    extern __shared__ char smc[];
    float* rxyf = (float*)(smc + ASM_RXY);

    int tid = threadIdx.x, wid = tid >> 5, lane = tid & 31;
    int bh = blockIdx.y;
    int b = bh >> 3, hh = bh & 7;
    int q0 = blockIdx.x * 128;
    unsigned smu = smem_u32(smc);

    for (int i = tid; i < 4096; i += 256) {
        int bx = i >> 6, by = i & 63;
        rxyf[i] = (bx < 63 && by < 63)
            ? fmaf(rpe_x[bx*8 + hh] + rpe_y[by*8 + hh], LOG2E, -MFIX)
            : -__int_as_float(0x7f800000);               // -inf sentinel
    }

    int sub = lane >> 3, r8v = lane & 7;
    int r = lane >> 2, c = lane & 3;

    // stage Q (hi then lo) through stage-0 area, extract A-frags
    unsigned qh[4][4], ql[4][4];
    #pragma unroll
    for (int s = 0; s < 2; s++) {
        const __nv_bfloat16* src = s ? g_Ql : g_Qh;
        __syncthreads();
        for (int i = tid; i < 1024; i += 256) {
            int row = i >> 3, cu = i & 7;
            unsigned off = (row << 7) + (cu << 4);
            off ^= (off >> 3) & 0x70;
            *(uint4*)(smc + off) =
                *(const uint4*)(src + ((size_t)(bh << 10) + q0 + row) * 64 + (cu << 3));
        }
        __syncthreads();
        unsigned qrow = (unsigned)(wid << 4) + ((sub & 1) << 3) + r8v;
        unsigned qcb = (sub >> 1) << 4;
        #pragma unroll
        for (int ks = 0; ks < 4; ks++) {
            unsigned off = (qrow << 7) + qcb + (ks << 5);
            off ^= (off >> 3) & 0x70;
            if (s) ldsm4(smu + off, ql[ks][0], ql[ks][1], ql[ks][2], ql[ks][3]);
            else   ldsm4(smu + off, qh[ks][0], qh[ks][1], qh[ks][2], qh[ks][3]);
        }
    }
    __syncthreads();   // Q frags extracted before stage 0 is overwritten

    float o[8][4] = {};
    float l2[2] = {0.0f, 0.0f};

    const __nv_bfloat16* kh = g_Kh + ((size_t)bh << 10) * 64;
    const __nv_bfloat16* kl = g_Kl + ((size_t)bh << 10) * 64;
    const __half*        vf = g_Vf + ((size_t)bh << 10) * 64;
    const unsigned short* bksrc =
        (const unsigned short*)g_bku + (((size_t)(b << 10) + q0) << 10);

    #define ISSUE_A(ti) do {                                                   \
        unsigned st_ = smu + ((ti) & 1) * AKV;                                 \
        int kt_ = (ti) << 6;                                                   \
        _Pragma("unroll")                                                      \
        for (int p = 0; p < 2; p++) {                                          \
            int i_ = tid + (p << 8);                                           \
            int row_ = i_ >> 3, cu_ = i_ & 7;                                  \
            unsigned off_ = (row_ << 7) + (cu_ << 4);                          \
            off_ ^= (off_ >> 3) & 0x70;                                        \
            size_t gs_ = (size_t)(kt_ + row_) * 64 + (cu_ << 3);               \
            cpa16(st_ + off_,         kh + gs_);                               \
            cpa16(st_ + 8192 + off_,  kl + gs_);                               \
            cpa16(st_ + 16384 + off_, vf + gs_);                               \
        }                                                                      \
        _Pragma("unroll")                                                      \
        for (int p = 0; p < 4; p++) {                                          \
            int i_ = tid + (p << 8);                                           \
            int row_ = i_ >> 3, cu_ = i_ & 7;                                  \
            cpa16(st_ + 24576 + row_ * 144 + (cu_ << 4),                       \
                  bksrc + ((size_t)row_ << 10) + kt_ + (cu_ << 3));            \
        }                                                                      \
        asm volatile("cp.async.commit_group;");                                \
    } while (0)

    ISSUE_A(0);

    for (int ti = 0; ti < 16; ti++) {
        asm volatile("cp.async.wait_group 0;");
        __syncthreads();
        if (ti < 15) ISSUE_A(ti + 1);

        unsigned stb = smu + (ti & 1) * AKV;
        char*    stc = smc + (ti & 1) * AKV;

        // ---- S = Q K^T (3 split passes, bf16) ----
        float S[8][4] = {};
        #pragma unroll
        for (int ks = 0; ks < 4; ks++) {
            unsigned bf[8][2];
            #pragma unroll
            for (int t = 0; t < 4; t++) {
                unsigned krow = (t << 4) + ((sub & 1) << 3) + r8v;
                unsigned off = (krow << 7) + ((sub >> 1) << 4) + (ks << 5);
                off ^= (off >> 3) & 0x70;
                unsigned r0, r1, r2, r3;
                ldsm4(stb + off, r0, r1, r2, r3);
                bf[t*2+0][0] = r0; bf[t*2+0][1] = r2;
                bf[t*2+1][0] = r1; bf[t*2+1][1] = r3;
            }
            #pragma unroll
            for (int n = 0; n < 8; n++) {
                mma16816(S[n], qh[ks], bf[n]);
                mma16816(S[n], ql[ks], bf[n]);
            }
        }
        #pragma unroll
        for (int ks = 0; ks < 4; ks++) {
            unsigned bf[8][2];
            #pragma unroll
            for (int t = 0; t < 4; t++) {
                unsigned krow = (t << 4) + ((sub & 1) << 3) + r8v;
                unsigned off = (krow << 7) + ((sub >> 1) << 4) + (ks << 5);
                off ^= (off >> 3) & 0x70;
                unsigned r0, r1, r2, r3;
                ldsm4(stb + 8192 + off, r0, r1, r2, r3);
                bf[t*2+0][0] = r0; bf[t*2+0][1] = r2;
                bf[t*2+1][0] = r1; bf[t*2+1][1] = r3;
            }
            #pragma unroll
            for (int n = 0; n < 8; n++)
                mma16816(S[n], qh[ks], bf[n]);
        }

        // ---- fixed-shift softmax: p = ex2(S*SCL + (bias*log2e - 8)) ----
        unsigned pAf[4][4];
        #pragma unroll
        for (int h = 0; h < 2; h++) {
            int rowq = (wid << 4) + r + (h << 3);
            const unsigned* brow = (const unsigned*)(stc + 24576 + rowq * 144) + c;
            float rs = 0.0f;
            #pragma unroll
            for (int j = 0; j < 8; j++) {
                unsigned w = brow[j << 2];
                float p0 = ex2(fmaf(S[j][h*2+0], SCL, rxyf[w & 0xffffu]));
                float p1 = ex2(fmaf(S[j][h*2+1], SCL, rxyf[w >> 16]));
                rs += p0 + p1;
                __half2 hp2 = __floats2half2_rn(p0, p1);
                pAf[j >> 1][(j & 1) * 2 + h] = *(unsigned*)&hp2;
            }
            l2[h] += rs;
        }

        // ---- O += P V (single fp16 pass, V via trans ldmatrix) ----
        int krowv = (lane & 15);
        int dby = ((lane >> 4) << 4);
        #pragma unroll
        for (int jj = 0; jj < 4; jj++) {
            unsigned bf[8][2];
            #pragma unroll
            for (int t = 0; t < 4; t++) {
                unsigned off = (((jj << 4) + krowv) << 7) + (t << 5) + dby;
                off ^= (off >> 3) & 0x70;
                unsigned r0, r1, r2, r3;
                ldsm4t(stb + 16384 + off, r0, r1, r2, r3);
                bf[t*2+0][0] = r0; bf[t*2+0][1] = r1;
                bf[t*2+1][0] = r2; bf[t*2+1][1] = r3;
            }
            #pragma unroll
            for (int n = 0; n < 8; n++)
                mma16816h(o[n], pAf[jj], bf[n]);
        }
    }

    // ---- finalize: normalize + write bf16 hi/lo to A-slab 3 ----
    #pragma unroll
    for (int h = 0; h < 2; h++) {
        float ls = l2[h];
        ls += __shfl_xor_sync(0xffffffffu, ls, 1);
        ls += __shfl_xor_sync(0xffffffffu, ls, 2);
        float inv = 1.0f / ls;
        int q = q0 + (wid << 4) + r + (h << 3);
        size_t base = 3*(size_t)MK + ((size_t)((b << 10) + q)) * 512 + hh * 64 + (c << 1);
        #pragma unroll
        for (int j = 0; j < 8; j++) {
            float f0 = o[j][h*2+0] * inv;
            float f1 = o[j][h*2+1] * inv;
            unsigned hp, lp;
            split2(f0, f1, hp, lp);
            *(unsigned*)(g_Ah + base + (j << 3)) = hp;
            *(unsigned*)(g_Al + base + (j << 3)) = lp;
        }
    }
}

// ================= launch =================
extern "C" void kernel_launch(void* const* d_in, const int* in_sizes, int n_in,
                              void* d_out, int out_size) {
    const float* query  = (const float*)d_in[0];
    const float* key    = (const float*)d_in[1];
    const float* value  = (const float*)d_in[2];
    const float* coords = (const float*)d_in[3];
    const int*   mask   = (const int*)  d_in[4];
    const float* Wq = (const float*)d_in[5];
    const float* bq = (const float*)d_in[6];
    const float* Wk = (const float*)d_in[7];
    const float* bk = (const float*)d_in[8];
    const float* Wv = (const float*)d_in[9];
    const float* bv = (const float*)d_in[10];
    const float* Wo = (const float*)d_in[11];
    const float* bo = (const float*)d_in[12];
    const float* rpe_x = (const float*)d_in[13];
    const float* rpe_y = (const float*)d_in[14];
    float* out = (float*)d_out;

    cudaFuncSetAttribute(attn_mma,
                         cudaFuncAttributeMaxDynamicSharedMemorySize, ATTN_SMEM);
    cudaFuncSetAttribute(mma_gemm,
                         cudaFuncAttributeMaxDynamicSharedMemorySize, GEMM_DSMEM);
    cudaFuncSetAttribute(out_gemm,
                         cudaFuncAttributeMaxDynamicSharedMemorySize, OGEMM_DSMEM);

    prep_kernel<<<15360, 256>>>(query, key, value, Wq, Wk, Wv, Wo, coords, mask);

    mma_gemm<<<dim3(4, 32, 3), 256, GEMM_DSMEM>>>(bq, bk, bv);

    attn_mma<<<dim3(8, 32), 256, ATTN_SMEM>>>(rpe_x, rpe_y);

    out_gemm<<<dim3(8, 32), 256, OGEMM_DSMEM>>>(bo, out);
}